// round 8
// baseline (speedup 1.0000x reference)
#include <cuda_runtime.h>
#include <cuda_bf16.h>
#include <cstdint>
#include <math.h>

// ---------------- problem constants ----------------
#define N0   4096
#define INC  128
#define HC   512
#define OC   64
#define KP1  2000
#define KP2  1000
#define KP3  500

#define ACT_NONE 0
#define ACT_RELU 1
#define ACT_SIGM 2

// ---------------- scratch (device globals; allocation-free) ----------------
__device__ float g_Augp[(size_t)2048*2048];
__device__ float g_h0 [(size_t)N0*HC];
__device__ float g_h1 [(size_t)KP1*HC];
__device__ float g_h2 [(size_t)KP2*HC];
__device__ float g_h3 [(size_t)KP3*HC];
__device__ float g_hb [(size_t)KP1*HC];
__device__ float g_xw [(size_t)N0*HC];
__device__ float g_t  [(size_t)4096*1024];
__device__ float g_u  [(size_t)N0*HC];
__device__ float g_dis[N0];
__device__ float g_sc [N0];
__device__ float g_pn [1];
__device__ int   g_perm0[KP1];
__device__ int   g_perm1[KP2];
__device__ int   g_perm2[KP3];
__device__ __nv_bfloat16 g_bA0 [(size_t)4096*4096];  // bf16(A0+I)
__device__ __nv_bfloat16 g_bA1 [(size_t)2048*2048];  // bf16(A1+I)
__device__ __nv_bfloat16 g_bX2 [(size_t)1024*2048];  // (A2+I) split [hi|lo]
__device__ __nv_bfloat16 g_bX3 [(size_t)512*1024];   // (A3+I) split [hi|lo]
__device__ __nv_bfloat16 g_G  [(size_t)2048*4096];   // row-gathered operand / P
__device__ __nv_bfloat16 g_Q  [(size_t)512*2048];    // pool2 [lo|hi] operand
__device__ __nv_bfloat16 g_zpk[(size_t)4096*1024];   // packed z operand

// ---------------- cp.async helpers ----------------
#define CPASYNC16(dst_u32, src_ptr) \
    asm volatile("cp.async.ca.shared.global [%0], [%1], 16;" :: "r"(dst_u32), "l"(src_ptr))
#define CP_COMMIT() asm volatile("cp.async.commit_group;")

// 256x128 tiles, 4-stage pipeline, dynamic smem
#define NN_AS (256*40)
#define NN_BS (32*136)
#define NT_AS (256*40)
#define NT_BS (128*40)
#define NN_SMEM (4 * (NN_AS + NN_BS) * 2)   // 116736 B
#define NT_SMEM (4 * (NT_AS + NT_BS) * 2)   // 122880 B

// acc: 0 = store, 2 = atomicAdd (C pre-zeroed; split-K)
// ---------------- NN GEMM: C(MxN) = A(MxK) @ B(KxN), 256x128 tile ----------------
__global__ void __launch_bounds__(256, 1) hgemm_nn(int M, int N, int K,
        const __nv_bfloat16* __restrict__ A, int lda,
        const __nv_bfloat16* __restrict__ B, int ldb,
        float* __restrict__ C, int ldc, int acc) {
    extern __shared__ __nv_bfloat16 dsm[];
    __nv_bfloat16* Asm = dsm;
    __nv_bfloat16* Bsm = dsm + 4 * NN_AS;
    const int tid  = threadIdx.x;
    const int lane = tid & 31;
    const int warp = tid >> 5;
    const int wm = (warp >> 1) * 64;   // 4 warp rows
    const int wn = (warp & 1) * 64;    // 2 warp cols
    const int m0 = blockIdx.y * 256;
    const int n0 = blockIdx.x * 128;
    const int Kc = K / gridDim.z;
    const int k0 = blockIdx.z * Kc;

    const int br = tid >> 3, bc = (tid & 7) * 16;

    float c[4][8][4];
#pragma unroll
    for (int mt = 0; mt < 4; mt++)
#pragma unroll
        for (int nt = 0; nt < 8; nt++)
#pragma unroll
            for (int r = 0; r < 4; r++) c[mt][nt][r] = 0.f;

    const int ntile = Kc >> 5;

#define NN_LOAD(s, kk) { \
    unsigned da = (unsigned)__cvta_generic_to_shared(Asm + (s) * NN_AS + tid * 40); \
    const __nv_bfloat16* pa = A + (size_t)(m0 + tid) * lda + (kk); \
    CPASYNC16(da, pa); CPASYNC16(da + 16, pa + 8); \
    CPASYNC16(da + 32, pa + 16); CPASYNC16(da + 48, pa + 24); \
    unsigned db = (unsigned)__cvta_generic_to_shared(Bsm + (s) * NN_BS + br * 136 + bc); \
    const __nv_bfloat16* pb = B + (size_t)((kk) + br) * ldb + n0 + bc; \
    CPASYNC16(db, pb); CPASYNC16(db + 16, pb + 8); }

    for (int p = 0; p < 3; ++p) {
        if (p < ntile) NN_LOAD(p, k0 + p * 32);
        CP_COMMIT();
    }

    for (int it = 0; it < ntile; ++it) {
        asm volatile("cp.async.wait_group 2;");
        __syncthreads();
        int pf = it + 3;
        if (pf < ntile) NN_LOAD(pf & 3, k0 + pf * 32);
        CP_COMMIT();

        const int s = it & 3;
        const __nv_bfloat16* As_s = Asm + s * NN_AS;
        const __nv_bfloat16* Bs_s = Bsm + s * NN_BS;
#pragma unroll
        for (int ks = 0; ks < 32; ks += 16) {
            uint32_t af[4][4];
#pragma unroll
            for (int mt = 0; mt < 4; mt++) {
                unsigned addr = (unsigned)__cvta_generic_to_shared(
                    As_s + (wm + mt * 16 + (lane & 15)) * 40 + ks + (lane >> 4) * 8);
                asm volatile("ldmatrix.sync.aligned.m8n8.x4.shared.b16 {%0,%1,%2,%3}, [%4];"
                    : "=r"(af[mt][0]), "=r"(af[mt][1]), "=r"(af[mt][2]), "=r"(af[mt][3])
                    : "r"(addr));
            }
            uint32_t bfr[8][2];
#pragma unroll
            for (int nt = 0; nt < 8; nt++) {
                unsigned addr = (unsigned)__cvta_generic_to_shared(
                    Bs_s + (ks + (lane & 15)) * 136 + wn + nt * 8);
                asm volatile("ldmatrix.sync.aligned.m8n8.x2.trans.shared.b16 {%0,%1}, [%2];"
                    : "=r"(bfr[nt][0]), "=r"(bfr[nt][1]) : "r"(addr));
            }
#pragma unroll
            for (int mt = 0; mt < 4; mt++)
#pragma unroll
                for (int nt = 0; nt < 8; nt++)
                    asm volatile(
                        "mma.sync.aligned.m16n8k16.row.col.f32.bf16.bf16.f32 "
                        "{%0,%1,%2,%3}, {%4,%5,%6,%7}, {%8,%9}, {%0,%1,%2,%3};"
                        : "+f"(c[mt][nt][0]), "+f"(c[mt][nt][1]),
                          "+f"(c[mt][nt][2]), "+f"(c[mt][nt][3])
                        : "r"(af[mt][0]), "r"(af[mt][1]), "r"(af[mt][2]), "r"(af[mt][3]),
                          "r"(bfr[nt][0]), "r"(bfr[nt][1]));
        }
        __syncthreads();
    }

    const int r0 = lane >> 2, c0 = (lane & 3) * 2;
#pragma unroll
    for (int mt = 0; mt < 4; mt++)
#pragma unroll
        for (int nt = 0; nt < 8; nt++) {
            int row = m0 + wm + mt * 16 + r0;
            int col = n0 + wn + nt * 8 + c0;
            float* p0 = C + (size_t)row * ldc + col;
            float* p1 = C + (size_t)(row + 8) * ldc + col;
            if (acc == 2) {
                atomicAdd(p0,     c[mt][nt][0]); atomicAdd(p0 + 1, c[mt][nt][1]);
                atomicAdd(p1,     c[mt][nt][2]); atomicAdd(p1 + 1, c[mt][nt][3]);
            } else {
                p0[0] = c[mt][nt][0]; p0[1] = c[mt][nt][1];
                p1[0] = c[mt][nt][2]; p1[1] = c[mt][nt][3];
            }
        }
}

// ---------------- NT GEMM: C(MxN) = A(MxK) @ B(NxK)^T, 256x128 tile ----------------
__global__ void __launch_bounds__(256, 1) hgemm_nt(int M, int N, int K,
        const __nv_bfloat16* __restrict__ A, int lda,
        const __nv_bfloat16* __restrict__ B, int ldb,
        float* __restrict__ C, int ldc, int acc) {
    extern __shared__ __nv_bfloat16 dsm[];
    __nv_bfloat16* Asm = dsm;
    __nv_bfloat16* Bsm = dsm + 4 * NT_AS;
    const int tid  = threadIdx.x;
    const int lane = tid & 31;
    const int warp = tid >> 5;
    const int wm = (warp >> 1) * 64;
    const int wn = (warp & 1) * 64;
    const int m0 = blockIdx.y * 256;
    const int n0 = blockIdx.x * 128;
    const int Kc = K / gridDim.z;
    const int k0 = blockIdx.z * Kc;

    float c[4][8][4];
#pragma unroll
    for (int mt = 0; mt < 4; mt++)
#pragma unroll
        for (int nt = 0; nt < 8; nt++)
#pragma unroll
            for (int r = 0; r < 4; r++) c[mt][nt][r] = 0.f;

    const int ntile = Kc >> 5;

#define NT_LOAD(s, kk) { \
    unsigned da = (unsigned)__cvta_generic_to_shared(Asm + (s) * NT_AS + tid * 40); \
    const __nv_bfloat16* pa = A + (size_t)(m0 + tid) * lda + (kk); \
    CPASYNC16(da, pa); CPASYNC16(da + 16, pa + 8); \
    CPASYNC16(da + 32, pa + 16); CPASYNC16(da + 48, pa + 24); \
    unsigned db = (unsigned)__cvta_generic_to_shared(Bsm + (s) * NT_BS + (tid >> 1) * 40 + (tid & 1) * 16); \
    const __nv_bfloat16* pb = B + (size_t)(n0 + (tid >> 1)) * ldb + (kk) + (tid & 1) * 16; \
    CPASYNC16(db, pb); CPASYNC16(db + 16, pb + 8); }

    for (int p = 0; p < 3; ++p) {
        if (p < ntile) NT_LOAD(p, k0 + p * 32);
        CP_COMMIT();
    }

    for (int it = 0; it < ntile; ++it) {
        asm volatile("cp.async.wait_group 2;");
        __syncthreads();
        int pf = it + 3;
        if (pf < ntile) NT_LOAD(pf & 3, k0 + pf * 32);
        CP_COMMIT();

        const int s = it & 3;
        const __nv_bfloat16* As_s = Asm + s * NT_AS;
        const __nv_bfloat16* Bs_s = Bsm + s * NT_BS;
#pragma unroll
        for (int ks = 0; ks < 32; ks += 16) {
            uint32_t af[4][4];
#pragma unroll
            for (int mt = 0; mt < 4; mt++) {
                unsigned addr = (unsigned)__cvta_generic_to_shared(
                    As_s + (wm + mt * 16 + (lane & 15)) * 40 + ks + (lane >> 4) * 8);
                asm volatile("ldmatrix.sync.aligned.m8n8.x4.shared.b16 {%0,%1,%2,%3}, [%4];"
                    : "=r"(af[mt][0]), "=r"(af[mt][1]), "=r"(af[mt][2]), "=r"(af[mt][3])
                    : "r"(addr));
            }
            uint32_t bfr[8][2];
#pragma unroll
            for (int nt = 0; nt < 8; nt++) {
                unsigned addr = (unsigned)__cvta_generic_to_shared(
                    Bs_s + (wn + nt * 8 + (lane & 7)) * 40 + ks + ((lane >> 3) & 1) * 8);
                asm volatile("ldmatrix.sync.aligned.m8n8.x2.shared.b16 {%0,%1}, [%2];"
                    : "=r"(bfr[nt][0]), "=r"(bfr[nt][1]) : "r"(addr));
            }
#pragma unroll
            for (int mt = 0; mt < 4; mt++)
#pragma unroll
                for (int nt = 0; nt < 8; nt++)
                    asm volatile(
                        "mma.sync.aligned.m16n8k16.row.col.f32.bf16.bf16.f32 "
                        "{%0,%1,%2,%3}, {%4,%5,%6,%7}, {%8,%9}, {%0,%1,%2,%3};"
                        : "+f"(c[mt][nt][0]), "+f"(c[mt][nt][1]),
                          "+f"(c[mt][nt][2]), "+f"(c[mt][nt][3])
                        : "r"(af[mt][0]), "r"(af[mt][1]), "r"(af[mt][2]), "r"(af[mt][3]),
                          "r"(bfr[nt][0]), "r"(bfr[nt][1]));
        }
        __syncthreads();
    }

    const int r0 = lane >> 2, c0 = (lane & 3) * 2;
#pragma unroll
    for (int mt = 0; mt < 4; mt++)
#pragma unroll
        for (int nt = 0; nt < 8; nt++) {
            int row = m0 + wm + mt * 16 + r0;
            int col = n0 + wn + nt * 8 + c0;
            float* p0 = C + (size_t)row * ldc + col;
            float* p1 = C + (size_t)(row + 8) * ldc + col;
            if (acc == 2) {
                atomicAdd(p0,     c[mt][nt][0]); atomicAdd(p0 + 1, c[mt][nt][1]);
                atomicAdd(p1,     c[mt][nt][2]); atomicAdd(p1 + 1, c[mt][nt][3]);
            } else {
                p0[0] = c[mt][nt][0]; p0[1] = c[mt][nt][1];
                p1[0] = c[mt][nt][2]; p1[1] = c[mt][nt][3];
            }
        }
}

// ---------------- SGEMM (fp32 SIMT) with optional fused bias+act ----------------
__global__ void __launch_bounds__(256) sgemm(int M, int N, int K,
                                             const float* __restrict__ A,
                                             const float* __restrict__ B,
                                             const float* __restrict__ bias,
                                             float* __restrict__ C, int act) {
    __shared__ float As[8][128];
    __shared__ float Bs[8][128];
    const int tid  = threadIdx.x;
    const int tx   = tid & 15;
    const int ty   = tid >> 4;
    const int row0 = blockIdx.y * 128;
    const int col0 = blockIdx.x * 128;
    const int a_row = tid >> 1, a_col = (tid & 1) << 2;
    const int b_row = tid >> 5, b_col = (tid & 31) << 2;

    float acc[8][8];
#pragma unroll
    for (int i = 0; i < 8; i++)
#pragma unroll
        for (int j = 0; j < 8; j++) acc[i][j] = 0.f;

    for (int kk = 0; kk < K; kk += 8) {
        float4 av = make_float4(0.f, 0.f, 0.f, 0.f);
        {
            int gm = row0 + a_row, gk = kk + a_col;
            if (gm < M && gk < K)
                av = *reinterpret_cast<const float4*>(A + (size_t)gm * K + gk);
        }
        As[a_col + 0][a_row] = av.x;
        As[a_col + 1][a_row] = av.y;
        As[a_col + 2][a_row] = av.z;
        As[a_col + 3][a_row] = av.w;

        float4 bv = make_float4(0.f, 0.f, 0.f, 0.f);
        {
            int gk = kk + b_row, gn = col0 + b_col;
            if (gk < K && gn < N)
                bv = *reinterpret_cast<const float4*>(B + (size_t)gk * N + gn);
        }
        *reinterpret_cast<float4*>(&Bs[b_row][b_col]) = bv;
        __syncthreads();

#pragma unroll
        for (int k = 0; k < 8; k++) {
            float4 a0 = *reinterpret_cast<const float4*>(&As[k][ty * 8]);
            float4 a1 = *reinterpret_cast<const float4*>(&As[k][ty * 8 + 4]);
            float4 b0 = *reinterpret_cast<const float4*>(&Bs[k][tx * 8]);
            float4 b1 = *reinterpret_cast<const float4*>(&Bs[k][tx * 8 + 4]);
            float a[8] = {a0.x, a0.y, a0.z, a0.w, a1.x, a1.y, a1.z, a1.w};
            float b[8] = {b0.x, b0.y, b0.z, b0.w, b1.x, b1.y, b1.z, b1.w};
#pragma unroll
            for (int i = 0; i < 8; i++)
#pragma unroll
                for (int j = 0; j < 8; j++) acc[i][j] += a[i] * b[j];
        }
        __syncthreads();
    }

#pragma unroll
    for (int i = 0; i < 8; i++) {
        int gm = row0 + ty * 8 + i;
        if (gm >= M) continue;
        float* Cr = C + (size_t)gm * N;
#pragma unroll
        for (int j = 0; j < 8; j++) {
            int gn = col0 + tx * 8 + j;
            if (gn >= N) continue;
            float v = acc[i][j];
            if (bias) v += bias[gn];
            if (act == ACT_RELU) v = fmaxf(v, 0.f);
            else if (act == ACT_SIGM) v = 1.f / (1.f + expf(-v));
            Cr[gn] = v;
        }
    }
}

// ---------------- elementwise / graph kernels ----------------
__global__ void k_edges_b(const int* __restrict__ ei, int E, __nv_bfloat16* __restrict__ A) {
    int e = blockIdx.x * blockDim.x + threadIdx.x;
    if (e >= E) return;
    int s = ei[e], d = ei[E + e];
    __nv_bfloat16 one = __float2bfloat16(1.f);
    A[(size_t)s * N0 + d] = one;
    A[(size_t)d * N0 + s] = one;
}

__global__ void k_diag1_b(__nv_bfloat16* __restrict__ A, int n, int ld) {
    int i = blockIdx.x * blockDim.x + threadIdx.x;
    if (i < n) {
        size_t p = (size_t)i * ld + i;
        A[p] = __float2bfloat16(__bfloat162float(A[p]) + 1.f);
    }
}

__global__ void k_dis_b(const __nv_bfloat16* __restrict__ M, int ld, int w,
                        float* __restrict__ dis) {
    __shared__ float red[256];
    int row = blockIdx.x;
    const __nv_bfloat16* Mr = M + (size_t)row * ld;
    float s = 0.f;
    for (int j = threadIdx.x; j < w; j += 256) s += __bfloat162float(Mr[j]);
    red[threadIdx.x] = s;
    __syncthreads();
    for (int o = 128; o > 0; o >>= 1) {
        if (threadIdx.x < o) red[threadIdx.x] += red[threadIdx.x + o];
        __syncthreads();
    }
    if (threadIdx.x == 0) dis[row] = rsqrtf(red[0]);
}

__global__ void k_scale_pack(const float* __restrict__ xw, const float* __restrict__ dis,
                             int n, int np, int C, int Cpad,
                             __nv_bfloat16* __restrict__ zpk) {
    int i = blockIdx.x * blockDim.x + threadIdx.x;
    int W = 2 * Cpad;
    if (i >= np * W) return;
    int r = i / W, cc = i - r * W;
    int col = (cc < Cpad) ? cc : cc - Cpad;
    float v = (r < n && col < C) ? dis[r] * xw[(size_t)r * C + col] : 0.f;
    __nv_bfloat16 hi = __float2bfloat16(v);
    if (cc < Cpad) zpk[i] = hi;
    else           zpk[i] = __float2bfloat16(v - __bfloat162float(hi));
}

__global__ void k_scale_pack_stk(const float* __restrict__ xw, const float* __restrict__ dis,
                                 int n, int np, int C,
                                 __nv_bfloat16* __restrict__ Bp) {
    int i = blockIdx.x * blockDim.x + threadIdx.x;
    int W = 2 * C;
    if (i >= 2 * np * W) return;
    int r = i / W, cc = i - r * W;
    int rr = (r < np) ? r : r - np;
    int col = (cc < C) ? cc : cc - C;
    float v = (rr < n) ? dis[rr] * xw[(size_t)rr * C + col] : 0.f;
    __nv_bfloat16 hi = __float2bfloat16(v);
    __nv_bfloat16 lo = __float2bfloat16(v - __bfloat162float(hi));
    bool wantHi = ((r < np) == (cc < C));
    Bp[i] = wantHi ? hi : lo;
}

__global__ void k_epilogue_sum2(const float* __restrict__ t, int ldt, int half,
                                const float* __restrict__ dis, const float* __restrict__ b,
                                int n, int C, float* __restrict__ out, int act) {
    int i = blockIdx.x * blockDim.x + threadIdx.x;
    if (i >= n * C) return;
    int r = i / C, cc = i - r * C;
    float v = dis[r] * (t[(size_t)r * ldt + cc] + t[(size_t)r * ldt + cc + half]) + b[cc];
    if (act == ACT_RELU) v = fmaxf(v, 0.f);
    else if (act == ACT_SIGM) v = 1.f / (1.f + expf(-v));
    out[i] = v;
}

__global__ void k_sum2_scale(const float* __restrict__ t, int ldt, int half,
                             const float* __restrict__ dis, int n, int C,
                             float* __restrict__ S) {
    int i = blockIdx.x * blockDim.x + threadIdx.x;
    if (i >= n * C) return;
    int r = i / C, cc = i - r * C;
    S[i] = dis[r] * (t[(size_t)r * ldt + cc] + t[(size_t)r * ldt + cc + half]);
}

__global__ void k_crop_tobf16(const float* __restrict__ Augp, int kpad, int k, int np,
                              __nv_bfloat16* __restrict__ bA) {
    int i = blockIdx.x * blockDim.x + threadIdx.x;
    if (i >= np * np) return;
    int r = i / np, cc = i - r * np;
    float v = 0.f;
    if (r < k && cc < k) v = (r == cc) ? 1.f : Augp[(size_t)r * kpad + cc];
    bA[i] = __float2bfloat16(v);
}

__global__ void k_crop_pack_X(const float* __restrict__ Augp, int kpad, int k, int np,
                              __nv_bfloat16* __restrict__ X) {
    int i = blockIdx.x * blockDim.x + threadIdx.x;
    if (i >= np * np) return;
    int r = i / np, cc = i - r * np;
    float v = 0.f;
    if (r < k && cc < k) v = (r == cc) ? 1.f : Augp[(size_t)r * kpad + cc];
    __nv_bfloat16 hi = __float2bfloat16(v);
    __nv_bfloat16 lo = __float2bfloat16(v - __bfloat162float(hi));
    X[(size_t)r * (2 * np) + cc]      = hi;
    X[(size_t)r * (2 * np) + np + cc] = lo;
}

__global__ void k_gather_rows(const __nv_bfloat16* __restrict__ bApI, int np,
                              const int* __restrict__ perm, int k, int kpad,
                              __nv_bfloat16* __restrict__ G) {
    int i = blockIdx.x * blockDim.x + threadIdx.x;
    if (i >= kpad * np) return;
    int r = i / np, j = i - r * np;
    G[i] = (r < k) ? bApI[(size_t)perm[r] * np + j] : __float2bfloat16(0.f);
}

__global__ void k_gather_PQ_b(const __nv_bfloat16* __restrict__ X2, int np,
                              const int* __restrict__ perm, int k, int kpad,
                              __nv_bfloat16* __restrict__ P,
                              __nv_bfloat16* __restrict__ Q) {
    int i = blockIdx.x * blockDim.x + threadIdx.x;
    int W = 2 * np;
    if (i >= kpad * W) return;
    int r = i / W, j = i - r * W;
    __nv_bfloat16 v = (r < k) ? X2[(size_t)perm[r] * W + j] : __float2bfloat16(0.f);
    P[i] = v;
    int js = (j < np) ? j + np : j - np;
    Q[(size_t)r * W + js] = v;
}

__global__ void k_pnorm(const float* __restrict__ p, int n, float* __restrict__ out) {
    __shared__ float red[256];
    float s = 0.f;
    for (int i = threadIdx.x; i < n; i += 256) s += p[i] * p[i];
    red[threadIdx.x] = s;
    __syncthreads();
    for (int o = 128; o > 0; o >>= 1) {
        if (threadIdx.x < o) red[threadIdx.x] += red[threadIdx.x + o];
        __syncthreads();
    }
    if (threadIdx.x == 0) out[0] = sqrtf(red[0]);
}

__global__ void k_scores(const float* __restrict__ h, int n, int C,
                         const float* __restrict__ p, const float* __restrict__ pn,
                         float* __restrict__ score) {
    int row = blockIdx.x * 8 + (threadIdx.x >> 5);
    int lane = threadIdx.x & 31;
    if (row >= n) return;
    const float* hr = h + (size_t)row * C;
    float s = 0.f;
    for (int cc = lane; cc < C; cc += 32) s += hr[cc] * p[cc];
    for (int o = 16; o > 0; o >>= 1) s += __shfl_xor_sync(0xffffffffu, s, o);
    if (lane == 0) score[row] = tanhf(s / pn[0]);
}

__global__ void __launch_bounds__(1024) k_sort_topk(const float* __restrict__ score,
                                                    int n, int npad, int k,
                                                    int* __restrict__ perm) {
    __shared__ float skey[4096];
    __shared__ int   sidx[4096];
    for (int i = threadIdx.x; i < npad; i += blockDim.x) {
        skey[i] = (i < n) ? score[i] : -INFINITY;
        sidx[i] = i;
    }
    __syncthreads();
    for (int kk = 2; kk <= npad; kk <<= 1) {
        for (int j = kk >> 1; j > 0; j >>= 1) {
            for (int i = threadIdx.x; i < npad; i += blockDim.x) {
                int ixj = i ^ j;
                if (ixj > i) {
                    float a = skey[i], b = skey[ixj];
                    bool sw = ((i & kk) == 0) ? (a < b) : (a > b);
                    if (sw) {
                        skey[i] = b; skey[ixj] = a;
                        int t = sidx[i]; sidx[i] = sidx[ixj]; sidx[ixj] = t;
                    }
                }
            }
            __syncthreads();
        }
    }
    for (int i = threadIdx.x; i < k; i += blockDim.x) perm[i] = sidx[i];
}

__global__ void k_gatherX(const float* __restrict__ h, int C,
                          const int* __restrict__ perm, const float* __restrict__ score,
                          int k, float* __restrict__ out) {
    int i = blockIdx.x * blockDim.x + threadIdx.x;
    if (i >= k * C) return;
    int r = i / C, cc = i - r * C;
    int pr = perm[r];
    out[i] = h[(size_t)pr * C + cc] * score[pr];
}

__global__ void k_scatter_add(float* __restrict__ u, const float* __restrict__ h,
                              const int* __restrict__ perm, int k, int C) {
    int i = blockIdx.x * blockDim.x + threadIdx.x;
    if (i >= k * C) return;
    int r = i / C, cc = i - r * C;
    u[(size_t)perm[r] * C + cc] += h[i];
}

// ---------------- host orchestration ----------------
static void run_sgemm(int M, int N, int K, const float* A, const float* B,
                      const float* bias, float* C, int act) {
    dim3 g((N + 127) / 128, (M + 127) / 128);
    sgemm<<<g, 256>>>(M, N, K, A, B, bias, C, act);
}
static void run_nn(int M, int N, int K, const __nv_bfloat16* A, int lda,
                   const __nv_bfloat16* B, int ldb, float* C, int ldc, int acc, int splitk) {
    cudaFuncSetAttribute(hgemm_nn, cudaFuncAttributeMaxDynamicSharedMemorySize, NN_SMEM);
    dim3 g(N / 128, M / 256, splitk);
    hgemm_nn<<<g, 256, NN_SMEM>>>(M, N, K, A, lda, B, ldb, C, ldc, acc);
}
static void run_nt(int M, int N, int K, const __nv_bfloat16* A, int lda,
                   const __nv_bfloat16* B, int ldb, float* C, int ldc, int acc, int splitk) {
    cudaFuncSetAttribute(hgemm_nt, cudaFuncAttributeMaxDynamicSharedMemorySize, NT_SMEM);
    dim3 g(N / 128, M / 256, splitk);
    hgemm_nt<<<g, 256, NT_SMEM>>>(M, N, K, A, lda, B, ldb, C, ldc, acc);
}

// exact-bf16 adjacency GCN (XW-first order)
static void run_gcn_exact(const __nv_bfloat16* bApI, int n, int np,
                          const float* X, int inC, const float* W, int outC, const float* b,
                          float* out, int act, int splitk,
                          float* xw, float* t, float* dis, __nv_bfloat16* zpk) {
    run_sgemm(n, outC, inC, X, W, nullptr, xw, ACT_NONE);
    k_dis_b<<<n, 256>>>(bApI, np, np, dis);
    int Cpad = (outC % 128 == 0) ? outC : 128;
    int W2 = 2 * Cpad;
    int tot = np * W2;
    k_scale_pack<<<(tot + 255) / 256, 256>>>(xw, dis, n, np, outC, Cpad, zpk);
    cudaMemsetAsync(t, 0, (size_t)np * W2 * sizeof(float), 0);
    run_nn(np, W2, np, bApI, np, zpk, W2, t, W2, 2, splitk);
    int nc = n * outC;
    k_epilogue_sum2<<<(nc + 255) / 256, 256>>>(t, W2, Cpad, dis, b, n, outC, out, act);
}

// split-adjacency GCN
static void run_gcn_split(const __nv_bfloat16* X2, int n, int np,
                          const float* X, int inC, const float* W, int outC, const float* b,
                          float* out, int act, int splitk,
                          float* xw, float* t, float* dis, __nv_bfloat16* Bp) {
    run_sgemm(n, outC, inC, X, W, nullptr, xw, ACT_NONE);
    k_dis_b<<<n, 256>>>(X2, 2 * np, 2 * np, dis);
    int W2 = 2 * outC;
    int tot = 2 * np * W2;
    k_scale_pack_stk<<<(tot + 255) / 256, 256>>>(xw, dis, n, np, outC, Bp);
    cudaMemsetAsync(t, 0, (size_t)np * W2 * sizeof(float), 0);
    run_nn(np, W2, 2 * np, X2, 2 * np, Bp, W2, t, W2, 2, splitk);
    int nc = n * outC;
    k_epilogue_sum2<<<(nc + 255) / 256, 256>>>(t, W2, outC, dis, b, n, outC, out, act);
}

static void run_scores_sort(const float* h, int n, int npad, const float* p, int k,
                            int* perm, float* score, float* pn) {
    k_pnorm<<<1, 256>>>(p, HC, pn);
    k_scores<<<(n + 7) / 8, 256>>>(h, n, HC, p, pn, score);
    k_sort_topk<<<1, 1024>>>(score, n, npad, k, perm);
}

extern "C" void kernel_launch(void* const* d_in, const int* in_sizes, int n_in,
                              void* d_out, int out_size) {
    const float* x   = (const float*)d_in[0];
    const int*   ei  = (const int*)  d_in[1];
    const float* Wd0 = (const float*)d_in[2];  const float* bd0 = (const float*)d_in[3];
    const float* Wd1 = (const float*)d_in[4];  const float* bd1 = (const float*)d_in[5];
    const float* Wd2 = (const float*)d_in[6];  const float* bd2 = (const float*)d_in[7];
    const float* Wd3 = (const float*)d_in[8];  const float* bd3 = (const float*)d_in[9];
    const float* p1  = (const float*)d_in[10];
    const float* p2  = (const float*)d_in[11];
    const float* p3  = (const float*)d_in[12];
    const float* Wu0 = (const float*)d_in[13]; const float* bu0 = (const float*)d_in[14];
    const float* Wu1 = (const float*)d_in[15]; const float* bu1 = (const float*)d_in[16];
    const float* Wu2 = (const float*)d_in[17]; const float* bu2 = (const float*)d_in[18];
    const int E = in_sizes[1] / 2;

    float *Augp, *h0, *h1, *h2, *h3, *hb, *xw, *t, *u, *dis, *sc, *pn;
    int *pm0, *pm1, *pm2;
    __nv_bfloat16 *bA0, *bA1, *bX2, *bX3, *G, *Q, *zpk;
    cudaGetSymbolAddress((void**)&Augp, g_Augp);
    cudaGetSymbolAddress((void**)&h0,  g_h0);
    cudaGetSymbolAddress((void**)&h1,  g_h1);
    cudaGetSymbolAddress((void**)&h2,  g_h2);
    cudaGetSymbolAddress((void**)&h3,  g_h3);
    cudaGetSymbolAddress((void**)&hb,  g_hb);
    cudaGetSymbolAddress((void**)&xw,  g_xw);
    cudaGetSymbolAddress((void**)&t,   g_t);
    cudaGetSymbolAddress((void**)&u,   g_u);
    cudaGetSymbolAddress((void**)&dis, g_dis);
    cudaGetSymbolAddress((void**)&sc,  g_sc);
    cudaGetSymbolAddress((void**)&pn,  g_pn);
    cudaGetSymbolAddress((void**)&pm0, g_perm0);
    cudaGetSymbolAddress((void**)&pm1, g_perm1);
    cudaGetSymbolAddress((void**)&pm2, g_perm2);
    cudaGetSymbolAddress((void**)&bA0, g_bA0);
    cudaGetSymbolAddress((void**)&bA1, g_bA1);
    cudaGetSymbolAddress((void**)&bX2, g_bX2);
    cudaGetSymbolAddress((void**)&bX3, g_bX3);
    cudaGetSymbolAddress((void**)&G,   g_G);
    cudaGetSymbolAddress((void**)&Q,   g_Q);
    cudaGetSymbolAddress((void**)&zpk, g_zpk);

    // ---- build bf16(A0+I) directly ----
    cudaMemsetAsync(bA0, 0, (size_t)N0 * N0 * sizeof(__nv_bfloat16), 0);
    k_edges_b<<<(E + 255) / 256, 256>>>(ei, E, bA0);
    k_diag1_b<<<(N0 + 255) / 256, 256>>>(bA0, N0, N0);

    // ---- down path: level 0, adjacency-first order (inC=128 << 512) ----
    k_dis_b<<<N0, 256>>>(bA0, N0, N0, dis);
    k_scale_pack<<<(N0 * 256 + 255) / 256, 256>>>(x, dis, N0, N0, INC, INC, zpk);
    cudaMemsetAsync(t, 0, (size_t)N0 * 256 * sizeof(float), 0);
    run_nn(N0, 256, N0, bA0, N0, zpk, 256, t, 256, 2, 8);
    k_sum2_scale<<<(N0 * INC + 255) / 256, 256>>>(t, 256, INC, dis, N0, INC, xw);
    run_sgemm(N0, HC, INC, xw, Wd0, bd0, h0, ACT_RELU);

    // pool0: A1 = [(A0+I)^2]_{perm0,perm0} = G@G^T, diag->0, +I -> bA1
    run_scores_sort(h0, N0, 4096, p1, KP1, pm0, sc, pn);
    k_gather_rows<<<(2048 * 4096 + 255) / 256, 256>>>(bA0, 4096, pm0, KP1, 2048, G);
    cudaMemsetAsync(Augp, 0, (size_t)2048 * 2048 * sizeof(float), 0);
    run_nt(2048, 2048, 4096, G, 4096, G, 4096, Augp, 2048, 2, 2);
    k_gatherX<<<(KP1 * HC + 255) / 256, 256>>>(h0, HC, pm0, sc, KP1, u);
    k_crop_tobf16<<<(2048 * 2048 + 255) / 256, 256>>>(Augp, 2048, KP1, 2048, bA1);
    run_gcn_exact(bA1, KP1, 2048, u, HC, Wd1, HC, bd1, h1, ACT_RELU, 4,
                  xw, t, dis, zpk);

    // pool1: A2 submatrix via G@G^T (split-K), -> bX2 split
    run_scores_sort(h1, KP1, 2048, p2, KP2, pm1, sc, pn);
    k_gather_rows<<<(1024 * 2048 + 255) / 256, 256>>>(bA1, 2048, pm1, KP2, 1024, G);
    cudaMemsetAsync(Augp, 0, (size_t)1024 * 1024 * sizeof(float), 0);
    run_nt(1024, 1024, 2048, G, 2048, G, 2048, Augp, 1024, 2, 8);
    k_gatherX<<<(KP2 * HC + 255) / 256, 256>>>(h1, HC, pm1, sc, KP2, u);
    k_crop_pack_X<<<(1024 * 1024 + 255) / 256, 256>>>(Augp, 1024, KP2, 1024, bX2);
    run_gcn_split(bX2, KP2, 1024, u, HC, Wd2, HC, bd2, h2, ACT_RELU, 8,
                  xw, t, dis, zpk);

    // pool2: A3 = P@P^T + P@Q^T (exact hi/lo split), -> bX3 split
    run_scores_sort(h2, KP2, 1024, p3, KP3, pm2, sc, pn);
    k_gather_PQ_b<<<(512 * 2048 + 255) / 256, 256>>>(bX2, 1024, pm2, KP3, 512, G, Q);
    cudaMemsetAsync(Augp, 0, (size_t)512 * 512 * sizeof(float), 0);
    run_nt(512, 512, 2048, G, 2048, G, 2048, Augp, 512, 2, 8);
    run_nt(512, 512, 2048, G, 2048, Q, 2048, Augp, 512, 2, 8);
    k_gatherX<<<(KP3 * HC + 255) / 256, 256>>>(h2, HC, pm2, sc, KP3, u);
    k_crop_pack_X<<<(512 * 512 + 255) / 256, 256>>>(Augp, 512, KP3, 512, bX3);
    run_gcn_split(bX3, KP3, 512, u, HC, Wd3, HC, bd3, h3, ACT_RELU, 4,
                  xw, t, dis, zpk);

    // ---- up path ----
    cudaMemcpyAsync(u, h2, (size_t)KP2 * HC * sizeof(float), cudaMemcpyDeviceToDevice, 0);
    k_scatter_add<<<(KP3 * HC + 255) / 256, 256>>>(u, h3, pm2, KP3, HC);
    run_gcn_split(bX2, KP2, 1024, u, HC, Wu0, HC, bu0, hb, ACT_RELU, 8,
                  xw, t, dis, zpk);

    cudaMemcpyAsync(u, h1, (size_t)KP1 * HC * sizeof(float), cudaMemcpyDeviceToDevice, 0);
    k_scatter_add<<<(KP2 * HC + 255) / 256, 256>>>(u, hb, pm1, KP2, HC);
    run_gcn_exact(bA1, KP1, 2048, u, HC, Wu1, HC, bu1, hb, ACT_RELU, 4,
                  xw, t, dis, zpk);

    cudaMemcpyAsync(u, h0, (size_t)N0 * HC * sizeof(float), cudaMemcpyDeviceToDevice, 0);
    k_scatter_add<<<(KP1 * HC + 255) / 256, 256>>>(u, hb, pm0, KP1, HC);
    run_gcn_exact(bA0, N0, 4096, u, HC, Wu2, OC, bu2, (float*)d_out, ACT_SIGM, 8,
                  xw, t, dis, zpk);
}

// round 9
// speedup vs baseline: 1.1293x; 1.1293x over previous
#include <cuda_runtime.h>
#include <cuda_bf16.h>
#include <cstdint>
#include <math.h>

// ---------------- problem constants ----------------
#define N0   4096
#define INC  128
#define HC   512
#define OC   64
#define KP1  2000
#define KP2  1000
#define KP3  500

#define ACT_NONE 0
#define ACT_RELU 1
#define ACT_SIGM 2

// ---------------- scratch (device globals; allocation-free) ----------------
__device__ float g_Augp[(size_t)2048*2048];
__device__ float g_h0 [(size_t)N0*HC];
__device__ float g_h1 [(size_t)KP1*HC];
__device__ float g_h2 [(size_t)KP2*HC];
__device__ float g_h3 [(size_t)KP3*HC];
__device__ float g_hb [(size_t)KP1*HC];
__device__ float g_xw [(size_t)N0*HC];
__device__ float g_t  [(size_t)4096*1024];
__device__ float g_u  [(size_t)N0*HC];
__device__ float g_dis[N0];
__device__ float g_sc [N0];
__device__ float g_pn [1];
__device__ int   g_perm0[KP1];
__device__ int   g_perm1[KP2];
__device__ int   g_perm2[KP3];
__device__ __nv_bfloat16 g_bA0 [(size_t)4096*4096];  // bf16(A0+I)
__device__ __nv_bfloat16 g_bA1 [(size_t)2048*2048];  // bf16(A1+I)
__device__ __nv_bfloat16 g_bX2 [(size_t)1024*2048];  // (A2+I) split [hi|lo]
__device__ __nv_bfloat16 g_bX3 [(size_t)512*1024];   // (A3+I) split [hi|lo]
__device__ __nv_bfloat16 g_G  [(size_t)2048*4096];   // row-gathered operand / P
__device__ __nv_bfloat16 g_Q  [(size_t)512*2048];    // pool2 [lo|hi] operand
__device__ __nv_bfloat16 g_zpk[(size_t)4096*1024];   // packed z operand

// ---------------- cp.async helpers ----------------
#define CPASYNC16(dst_u32, src_ptr) \
    asm volatile("cp.async.ca.shared.global [%0], [%1], 16;" :: "r"(dst_u32), "l"(src_ptr))
#define CP_COMMIT() asm volatile("cp.async.commit_group;")

// 128x128 tiles, 4-stage pipeline, dynamic smem (2 CTAs/SM)
#define NN_AS (128*40)
#define NN_BS (32*136)
#define NT_AS (128*40)
#define NT_BS (128*40)
#define NN_SMEM (4 * (NN_AS + NN_BS) * 2)   // 75776 B
#define NT_SMEM (4 * (NT_AS + NT_BS) * 2)   // 81920 B

// acc: 0 = store, 2 = atomicAdd (C pre-zeroed; split-K)
// ---------------- NN GEMM: C(MxN) = A(MxK) @ B(KxN), bf16->fp32 ----------------
__global__ void __launch_bounds__(256) hgemm_nn(int M, int N, int K,
        const __nv_bfloat16* __restrict__ A, int lda,
        const __nv_bfloat16* __restrict__ B, int ldb,
        float* __restrict__ C, int ldc, int acc) {
    extern __shared__ __nv_bfloat16 dsm[];
    __nv_bfloat16* Asm = dsm;
    __nv_bfloat16* Bsm = dsm + 4 * NN_AS;
    const int tid  = threadIdx.x;
    const int lane = tid & 31;
    const int warp = tid >> 5;
    const int wm = (warp >> 2) * 64;
    const int wn = (warp & 3) * 32;
    const int m0 = blockIdx.y * 128;
    const int n0 = blockIdx.x * 128;
    const int Kc = K / gridDim.z;
    const int k0 = blockIdx.z * Kc;

    const int ar = tid >> 1, ac = (tid & 1) * 16;
    const int br = tid >> 3, bc = (tid & 7) * 16;

    float c[4][4][4];
#pragma unroll
    for (int mt = 0; mt < 4; mt++)
#pragma unroll
        for (int nt = 0; nt < 4; nt++)
#pragma unroll
            for (int r = 0; r < 4; r++) c[mt][nt][r] = 0.f;

    const int ntile = Kc >> 5;

#define NN_LOAD(s, kk) { \
    unsigned da = (unsigned)__cvta_generic_to_shared(Asm + (s) * NN_AS + ar * 40 + ac); \
    const __nv_bfloat16* pa = A + (size_t)(m0 + ar) * lda + (kk) + ac; \
    CPASYNC16(da, pa); CPASYNC16(da + 16, pa + 8); \
    unsigned db = (unsigned)__cvta_generic_to_shared(Bsm + (s) * NN_BS + br * 136 + bc); \
    const __nv_bfloat16* pb = B + (size_t)((kk) + br) * ldb + n0 + bc; \
    CPASYNC16(db, pb); CPASYNC16(db + 16, pb + 8); }

    for (int p = 0; p < 3; ++p) {
        if (p < ntile) NN_LOAD(p, k0 + p * 32);
        CP_COMMIT();
    }

    for (int it = 0; it < ntile; ++it) {
        asm volatile("cp.async.wait_group 2;");
        __syncthreads();
        int pf = it + 3;
        if (pf < ntile) NN_LOAD(pf & 3, k0 + pf * 32);
        CP_COMMIT();

        const int s = it & 3;
        const __nv_bfloat16* As_s = Asm + s * NN_AS;
        const __nv_bfloat16* Bs_s = Bsm + s * NN_BS;
#pragma unroll
        for (int ks = 0; ks < 32; ks += 16) {
            uint32_t af[4][4];
#pragma unroll
            for (int mt = 0; mt < 4; mt++) {
                unsigned addr = (unsigned)__cvta_generic_to_shared(
                    As_s + (wm + mt * 16 + (lane & 15)) * 40 + ks + (lane >> 4) * 8);
                asm volatile("ldmatrix.sync.aligned.m8n8.x4.shared.b16 {%0,%1,%2,%3}, [%4];"
                    : "=r"(af[mt][0]), "=r"(af[mt][1]), "=r"(af[mt][2]), "=r"(af[mt][3])
                    : "r"(addr));
            }
            uint32_t bfr[4][2];
#pragma unroll
            for (int nt = 0; nt < 4; nt++) {
                unsigned addr = (unsigned)__cvta_generic_to_shared(
                    Bs_s + (ks + (lane & 15)) * 136 + wn + nt * 8);
                asm volatile("ldmatrix.sync.aligned.m8n8.x2.trans.shared.b16 {%0,%1}, [%2];"
                    : "=r"(bfr[nt][0]), "=r"(bfr[nt][1]) : "r"(addr));
            }
#pragma unroll
            for (int mt = 0; mt < 4; mt++)
#pragma unroll
                for (int nt = 0; nt < 4; nt++)
                    asm volatile(
                        "mma.sync.aligned.m16n8k16.row.col.f32.bf16.bf16.f32 "
                        "{%0,%1,%2,%3}, {%4,%5,%6,%7}, {%8,%9}, {%0,%1,%2,%3};"
                        : "+f"(c[mt][nt][0]), "+f"(c[mt][nt][1]),
                          "+f"(c[mt][nt][2]), "+f"(c[mt][nt][3])
                        : "r"(af[mt][0]), "r"(af[mt][1]), "r"(af[mt][2]), "r"(af[mt][3]),
                          "r"(bfr[nt][0]), "r"(bfr[nt][1]));
        }
        __syncthreads();
    }

    const int r0 = lane >> 2, c0 = (lane & 3) * 2;
#pragma unroll
    for (int mt = 0; mt < 4; mt++)
#pragma unroll
        for (int nt = 0; nt < 4; nt++) {
            int row = m0 + wm + mt * 16 + r0;
            int col = n0 + wn + nt * 8 + c0;
            float* p0 = C + (size_t)row * ldc + col;
            float* p1 = C + (size_t)(row + 8) * ldc + col;
            if (acc == 2) {
                atomicAdd(p0,     c[mt][nt][0]); atomicAdd(p0 + 1, c[mt][nt][1]);
                atomicAdd(p1,     c[mt][nt][2]); atomicAdd(p1 + 1, c[mt][nt][3]);
            } else {
                p0[0] = c[mt][nt][0]; p0[1] = c[mt][nt][1];
                p1[0] = c[mt][nt][2]; p1[1] = c[mt][nt][3];
            }
        }
}

// ---------------- NT GEMM: C(MxN) = A(MxK) @ B(NxK)^T ----------------
// tri != 0: C symmetric, M==N; compute only tiles with n-tile >= m-tile.
__global__ void __launch_bounds__(256) hgemm_nt(int M, int N, int K,
        const __nv_bfloat16* __restrict__ A, int lda,
        const __nv_bfloat16* __restrict__ B, int ldb,
        float* __restrict__ C, int ldc, int acc, int tri) {
    extern __shared__ __nv_bfloat16 dsm[];
    __nv_bfloat16* Asm = dsm;
    __nv_bfloat16* Bsm = dsm + 4 * NT_AS;
    const int tid  = threadIdx.x;
    const int lane = tid & 31;
    const int warp = tid >> 5;
    const int wm = (warp >> 2) * 64;
    const int wn = (warp & 3) * 32;

    int m0, n0;
    if (tri) {
        int bid = blockIdx.x;
        int by = (int)((sqrtf(8.f * bid + 1.f) - 1.f) * 0.5f);
        while ((by + 1) * (by + 2) / 2 <= bid) by++;
        while (by * (by + 1) / 2 > bid) by--;
        int bx = bid - by * (by + 1) / 2;   // bx <= by
        m0 = bx * 128;                       // row tile <= col tile
        n0 = by * 128;
    } else {
        m0 = blockIdx.y * 128;
        n0 = blockIdx.x * 128;
    }
    const int Kc = K / gridDim.z;
    const int k0 = blockIdx.z * Kc;

    const int ar = tid >> 1, ac = (tid & 1) * 16;

    float c[4][4][4];
#pragma unroll
    for (int mt = 0; mt < 4; mt++)
#pragma unroll
        for (int nt = 0; nt < 4; nt++)
#pragma unroll
            for (int r = 0; r < 4; r++) c[mt][nt][r] = 0.f;

    const int ntile = Kc >> 5;

#define NT_LOAD(s, kk) { \
    unsigned da = (unsigned)__cvta_generic_to_shared(Asm + (s) * NT_AS + ar * 40 + ac); \
    const __nv_bfloat16* pa = A + (size_t)(m0 + ar) * lda + (kk) + ac; \
    CPASYNC16(da, pa); CPASYNC16(da + 16, pa + 8); \
    unsigned db = (unsigned)__cvta_generic_to_shared(Bsm + (s) * NT_BS + ar * 40 + ac); \
    const __nv_bfloat16* pb = B + (size_t)(n0 + ar) * ldb + (kk) + ac; \
    CPASYNC16(db, pb); CPASYNC16(db + 16, pb + 8); }

    for (int p = 0; p < 3; ++p) {
        if (p < ntile) NT_LOAD(p, k0 + p * 32);
        CP_COMMIT();
    }

    for (int it = 0; it < ntile; ++it) {
        asm volatile("cp.async.wait_group 2;");
        __syncthreads();
        int pf = it + 3;
        if (pf < ntile) NT_LOAD(pf & 3, k0 + pf * 32);
        CP_COMMIT();

        const int s = it & 3;
        const __nv_bfloat16* As_s = Asm + s * NT_AS;
        const __nv_bfloat16* Bs_s = Bsm + s * NT_BS;
#pragma unroll
        for (int ks = 0; ks < 32; ks += 16) {
            uint32_t af[4][4];
#pragma unroll
            for (int mt = 0; mt < 4; mt++) {
                unsigned addr = (unsigned)__cvta_generic_to_shared(
                    As_s + (wm + mt * 16 + (lane & 15)) * 40 + ks + (lane >> 4) * 8);
                asm volatile("ldmatrix.sync.aligned.m8n8.x4.shared.b16 {%0,%1,%2,%3}, [%4];"
                    : "=r"(af[mt][0]), "=r"(af[mt][1]), "=r"(af[mt][2]), "=r"(af[mt][3])
                    : "r"(addr));
            }
            uint32_t bfr[4][2];
#pragma unroll
            for (int nt = 0; nt < 4; nt++) {
                unsigned addr = (unsigned)__cvta_generic_to_shared(
                    Bs_s + (wn + nt * 8 + (lane & 7)) * 40 + ks + ((lane >> 3) & 1) * 8);
                asm volatile("ldmatrix.sync.aligned.m8n8.x2.shared.b16 {%0,%1}, [%2];"
                    : "=r"(bfr[nt][0]), "=r"(bfr[nt][1]) : "r"(addr));
            }
#pragma unroll
            for (int mt = 0; mt < 4; mt++)
#pragma unroll
                for (int nt = 0; nt < 4; nt++)
                    asm volatile(
                        "mma.sync.aligned.m16n8k16.row.col.f32.bf16.bf16.f32 "
                        "{%0,%1,%2,%3}, {%4,%5,%6,%7}, {%8,%9}, {%0,%1,%2,%3};"
                        : "+f"(c[mt][nt][0]), "+f"(c[mt][nt][1]),
                          "+f"(c[mt][nt][2]), "+f"(c[mt][nt][3])
                        : "r"(af[mt][0]), "r"(af[mt][1]), "r"(af[mt][2]), "r"(af[mt][3]),
                          "r"(bfr[nt][0]), "r"(bfr[nt][1]));
        }
        __syncthreads();
    }

    const int r0 = lane >> 2, c0 = (lane & 3) * 2;
#pragma unroll
    for (int mt = 0; mt < 4; mt++)
#pragma unroll
        for (int nt = 0; nt < 4; nt++) {
            int row = m0 + wm + mt * 16 + r0;
            int col = n0 + wn + nt * 8 + c0;
            float* p0 = C + (size_t)row * ldc + col;
            float* p1 = C + (size_t)(row + 8) * ldc + col;
            if (acc == 2) {
                atomicAdd(p0,     c[mt][nt][0]); atomicAdd(p0 + 1, c[mt][nt][1]);
                atomicAdd(p1,     c[mt][nt][2]); atomicAdd(p1 + 1, c[mt][nt][3]);
            } else {
                p0[0] = c[mt][nt][0]; p0[1] = c[mt][nt][1];
                p1[0] = c[mt][nt][2]; p1[1] = c[mt][nt][3];
            }
        }
}

// ---------------- SGEMM (fp32 SIMT) with optional fused bias+act ----------------
__global__ void __launch_bounds__(256) sgemm(int M, int N, int K,
                                             const float* __restrict__ A,
                                             const float* __restrict__ B,
                                             const float* __restrict__ bias,
                                             float* __restrict__ C, int act) {
    __shared__ float As[8][128];
    __shared__ float Bs[8][128];
    const int tid  = threadIdx.x;
    const int tx   = tid & 15;
    const int ty   = tid >> 4;
    const int row0 = blockIdx.y * 128;
    const int col0 = blockIdx.x * 128;
    const int a_row = tid >> 1, a_col = (tid & 1) << 2;
    const int b_row = tid >> 5, b_col = (tid & 31) << 2;

    float acc[8][8];
#pragma unroll
    for (int i = 0; i < 8; i++)
#pragma unroll
        for (int j = 0; j < 8; j++) acc[i][j] = 0.f;

    for (int kk = 0; kk < K; kk += 8) {
        float4 av = make_float4(0.f, 0.f, 0.f, 0.f);
        {
            int gm = row0 + a_row, gk = kk + a_col;
            if (gm < M && gk < K)
                av = *reinterpret_cast<const float4*>(A + (size_t)gm * K + gk);
        }
        As[a_col + 0][a_row] = av.x;
        As[a_col + 1][a_row] = av.y;
        As[a_col + 2][a_row] = av.z;
        As[a_col + 3][a_row] = av.w;

        float4 bv = make_float4(0.f, 0.f, 0.f, 0.f);
        {
            int gk = kk + b_row, gn = col0 + b_col;
            if (gk < K && gn < N)
                bv = *reinterpret_cast<const float4*>(B + (size_t)gk * N + gn);
        }
        *reinterpret_cast<float4*>(&Bs[b_row][b_col]) = bv;
        __syncthreads();

#pragma unroll
        for (int k = 0; k < 8; k++) {
            float4 a0 = *reinterpret_cast<const float4*>(&As[k][ty * 8]);
            float4 a1 = *reinterpret_cast<const float4*>(&As[k][ty * 8 + 4]);
            float4 b0 = *reinterpret_cast<const float4*>(&Bs[k][tx * 8]);
            float4 b1 = *reinterpret_cast<const float4*>(&Bs[k][tx * 8 + 4]);
            float a[8] = {a0.x, a0.y, a0.z, a0.w, a1.x, a1.y, a1.z, a1.w};
            float b[8] = {b0.x, b0.y, b0.z, b0.w, b1.x, b1.y, b1.z, b1.w};
#pragma unroll
            for (int i = 0; i < 8; i++)
#pragma unroll
                for (int j = 0; j < 8; j++) acc[i][j] += a[i] * b[j];
        }
        __syncthreads();
    }

#pragma unroll
    for (int i = 0; i < 8; i++) {
        int gm = row0 + ty * 8 + i;
        if (gm >= M) continue;
        float* Cr = C + (size_t)gm * N;
#pragma unroll
        for (int j = 0; j < 8; j++) {
            int gn = col0 + tx * 8 + j;
            if (gn >= N) continue;
            float v = acc[i][j];
            if (bias) v += bias[gn];
            if (act == ACT_RELU) v = fmaxf(v, 0.f);
            else if (act == ACT_SIGM) v = 1.f / (1.f + expf(-v));
            Cr[gn] = v;
        }
    }
}

// ---------------- elementwise / graph kernels ----------------
__global__ void k_edges_b(const int* __restrict__ ei, int E, __nv_bfloat16* __restrict__ A) {
    int e = blockIdx.x * blockDim.x + threadIdx.x;
    if (e >= E) return;
    int s = ei[e], d = ei[E + e];
    __nv_bfloat16 one = __float2bfloat16(1.f);
    A[(size_t)s * N0 + d] = one;
    A[(size_t)d * N0 + s] = one;
}

__global__ void k_diag1_b(__nv_bfloat16* __restrict__ A, int n, int ld) {
    int i = blockIdx.x * blockDim.x + threadIdx.x;
    if (i < n) {
        size_t p = (size_t)i * ld + i;
        A[p] = __float2bfloat16(__bfloat162float(A[p]) + 1.f);
    }
}

__global__ void k_dis_b(const __nv_bfloat16* __restrict__ M, int ld, int w,
                        float* __restrict__ dis) {
    __shared__ float red[256];
    int row = blockIdx.x;
    const __nv_bfloat16* Mr = M + (size_t)row * ld;
    float s = 0.f;
    for (int j = threadIdx.x; j < w; j += 256) s += __bfloat162float(Mr[j]);
    red[threadIdx.x] = s;
    __syncthreads();
    for (int o = 128; o > 0; o >>= 1) {
        if (threadIdx.x < o) red[threadIdx.x] += red[threadIdx.x + o];
        __syncthreads();
    }
    if (threadIdx.x == 0) dis[row] = rsqrtf(red[0]);
}

__global__ void k_scale_pack(const float* __restrict__ xw, const float* __restrict__ dis,
                             int n, int np, int C, int Cpad,
                             __nv_bfloat16* __restrict__ zpk) {
    int i = blockIdx.x * blockDim.x + threadIdx.x;
    int W = 2 * Cpad;
    if (i >= np * W) return;
    int r = i / W, cc = i - r * W;
    int col = (cc < Cpad) ? cc : cc - Cpad;
    float v = (r < n && col < C) ? dis[r] * xw[(size_t)r * C + col] : 0.f;
    __nv_bfloat16 hi = __float2bfloat16(v);
    if (cc < Cpad) zpk[i] = hi;
    else           zpk[i] = __float2bfloat16(v - __bfloat162float(hi));
}

__global__ void k_scale_pack_stk(const float* __restrict__ xw, const float* __restrict__ dis,
                                 int n, int np, int C,
                                 __nv_bfloat16* __restrict__ Bp) {
    int i = blockIdx.x * blockDim.x + threadIdx.x;
    int W = 2 * C;
    if (i >= 2 * np * W) return;
    int r = i / W, cc = i - r * W;
    int rr = (r < np) ? r : r - np;
    int col = (cc < C) ? cc : cc - C;
    float v = (rr < n) ? dis[rr] * xw[(size_t)rr * C + col] : 0.f;
    __nv_bfloat16 hi = __float2bfloat16(v);
    __nv_bfloat16 lo = __float2bfloat16(v - __bfloat162float(hi));
    bool wantHi = ((r < np) == (cc < C));
    Bp[i] = wantHi ? hi : lo;
}

__global__ void k_epilogue_sum2(const float* __restrict__ t, int ldt, int half,
                                const float* __restrict__ dis, const float* __restrict__ b,
                                int n, int C, float* __restrict__ out, int act) {
    int i = blockIdx.x * blockDim.x + threadIdx.x;
    if (i >= n * C) return;
    int r = i / C, cc = i - r * C;
    float v = dis[r] * (t[(size_t)r * ldt + cc] + t[(size_t)r * ldt + cc + half]) + b[cc];
    if (act == ACT_RELU) v = fmaxf(v, 0.f);
    else if (act == ACT_SIGM) v = 1.f / (1.f + expf(-v));
    out[i] = v;
}

__global__ void k_sum2_scale(const float* __restrict__ t, int ldt, int half,
                             const float* __restrict__ dis, int n, int C,
                             float* __restrict__ S) {
    int i = blockIdx.x * blockDim.x + threadIdx.x;
    if (i >= n * C) return;
    int r = i / C, cc = i - r * C;
    S[i] = dis[r] * (t[(size_t)r * ldt + cc] + t[(size_t)r * ldt + cc + half]);
}

// bA (np x np) = bf16 of upper-stored symmetric Augp + I  (reads min/max index)
__global__ void k_crop_tobf16(const float* __restrict__ Augp, int kpad, int k, int np,
                              __nv_bfloat16* __restrict__ bA) {
    int i = blockIdx.x * blockDim.x + threadIdx.x;
    if (i >= np * np) return;
    int r = i / np, cc = i - r * np;
    float v = 0.f;
    if (r < k && cc < k) {
        if (r == cc) v = 1.f;
        else {
            int rr = (r < cc) ? r : cc;
            int c2 = (r < cc) ? cc : r;
            v = Augp[(size_t)rr * kpad + c2];
        }
    }
    bA[i] = __float2bfloat16(v);
}

// X (np x 2np) = [hi | lo] of upper-stored symmetric Augp + I
__global__ void k_crop_pack_X(const float* __restrict__ Augp, int kpad, int k, int np,
                              __nv_bfloat16* __restrict__ X) {
    int i = blockIdx.x * blockDim.x + threadIdx.x;
    if (i >= np * np) return;
    int r = i / np, cc = i - r * np;
    float v = 0.f;
    if (r < k && cc < k) {
        if (r == cc) v = 1.f;
        else {
            int rr = (r < cc) ? r : cc;
            int c2 = (r < cc) ? cc : r;
            v = Augp[(size_t)rr * kpad + c2];
        }
    }
    __nv_bfloat16 hi = __float2bfloat16(v);
    __nv_bfloat16 lo = __float2bfloat16(v - __bfloat162float(hi));
    X[(size_t)r * (2 * np) + cc]      = hi;
    X[(size_t)r * (2 * np) + np + cc] = lo;
}

__global__ void k_gather_rows(const __nv_bfloat16* __restrict__ bApI, int np,
                              const int* __restrict__ perm, int k, int kpad,
                              __nv_bfloat16* __restrict__ G) {
    int i = blockIdx.x * blockDim.x + threadIdx.x;
    if (i >= kpad * np) return;
    int r = i / np, j = i - r * np;
    G[i] = (r < k) ? bApI[(size_t)perm[r] * np + j] : __float2bfloat16(0.f);
}

__global__ void k_gather_PQ_b(const __nv_bfloat16* __restrict__ X2, int np,
                              const int* __restrict__ perm, int k, int kpad,
                              __nv_bfloat16* __restrict__ P,
                              __nv_bfloat16* __restrict__ Q) {
    int i = blockIdx.x * blockDim.x + threadIdx.x;
    int W = 2 * np;
    if (i >= kpad * W) return;
    int r = i / W, j = i - r * W;
    __nv_bfloat16 v = (r < k) ? X2[(size_t)perm[r] * W + j] : __float2bfloat16(0.f);
    P[i] = v;
    int js = (j < np) ? j + np : j - np;
    Q[(size_t)r * W + js] = v;
}

__global__ void k_pnorm(const float* __restrict__ p, int n, float* __restrict__ out) {
    __shared__ float red[256];
    float s = 0.f;
    for (int i = threadIdx.x; i < n; i += 256) s += p[i] * p[i];
    red[threadIdx.x] = s;
    __syncthreads();
    for (int o = 128; o > 0; o >>= 1) {
        if (threadIdx.x < o) red[threadIdx.x] += red[threadIdx.x + o];
        __syncthreads();
    }
    if (threadIdx.x == 0) out[0] = sqrtf(red[0]);
}

__global__ void k_scores(const float* __restrict__ h, int n, int C,
                         const float* __restrict__ p, const float* __restrict__ pn,
                         float* __restrict__ score) {
    int row = blockIdx.x * 8 + (threadIdx.x >> 5);
    int lane = threadIdx.x & 31;
    if (row >= n) return;
    const float* hr = h + (size_t)row * C;
    float s = 0.f;
    for (int cc = lane; cc < C; cc += 32) s += hr[cc] * p[cc];
    for (int o = 16; o > 0; o >>= 1) s += __shfl_xor_sync(0xffffffffu, s, o);
    if (lane == 0) score[row] = tanhf(s / pn[0]);
}

__global__ void __launch_bounds__(1024) k_sort_topk(const float* __restrict__ score,
                                                    int n, int npad, int k,
                                                    int* __restrict__ perm) {
    __shared__ float skey[4096];
    __shared__ int   sidx[4096];
    for (int i = threadIdx.x; i < npad; i += blockDim.x) {
        skey[i] = (i < n) ? score[i] : -INFINITY;
        sidx[i] = i;
    }
    __syncthreads();
    for (int kk = 2; kk <= npad; kk <<= 1) {
        for (int j = kk >> 1; j > 0; j >>= 1) {
            for (int i = threadIdx.x; i < npad; i += blockDim.x) {
                int ixj = i ^ j;
                if (ixj > i) {
                    float a = skey[i], b = skey[ixj];
                    bool sw = ((i & kk) == 0) ? (a < b) : (a > b);
                    if (sw) {
                        skey[i] = b; skey[ixj] = a;
                        int t = sidx[i]; sidx[i] = sidx[ixj]; sidx[ixj] = t;
                    }
                }
            }
            __syncthreads();
        }
    }
    for (int i = threadIdx.x; i < k; i += blockDim.x) perm[i] = sidx[i];
}

__global__ void k_gatherX(const float* __restrict__ h, int C,
                          const int* __restrict__ perm, const float* __restrict__ score,
                          int k, float* __restrict__ out) {
    int i = blockIdx.x * blockDim.x + threadIdx.x;
    if (i >= k * C) return;
    int r = i / C, cc = i - r * C;
    int pr = perm[r];
    out[i] = h[(size_t)pr * C + cc] * score[pr];
}

__global__ void k_scatter_add(float* __restrict__ u, const float* __restrict__ h,
                              const int* __restrict__ perm, int k, int C) {
    int i = blockIdx.x * blockDim.x + threadIdx.x;
    if (i >= k * C) return;
    int r = i / C, cc = i - r * C;
    u[(size_t)perm[r] * C + cc] += h[i];
}

// ---------------- host orchestration ----------------
static void run_sgemm(int M, int N, int K, const float* A, const float* B,
                      const float* bias, float* C, int act) {
    dim3 g((N + 127) / 128, (M + 127) / 128);
    sgemm<<<g, 256>>>(M, N, K, A, B, bias, C, act);
}
static void run_nn(int M, int N, int K, const __nv_bfloat16* A, int lda,
                   const __nv_bfloat16* B, int ldb, float* C, int ldc, int acc, int splitk) {
    cudaFuncSetAttribute(hgemm_nn, cudaFuncAttributeMaxDynamicSharedMemorySize, NN_SMEM);
    dim3 g(N / 128, M / 128, splitk);
    hgemm_nn<<<g, 256, NN_SMEM>>>(M, N, K, A, lda, B, ldb, C, ldc, acc);
}
// symmetric NT (upper-triangular tiles only)
static void run_nt_tri(int M, int K, const __nv_bfloat16* A, int lda,
                       const __nv_bfloat16* B, int ldb, float* C, int ldc, int splitk) {
    cudaFuncSetAttribute(hgemm_nt, cudaFuncAttributeMaxDynamicSharedMemorySize, NT_SMEM);
    int T = M / 128;
    dim3 g(T * (T + 1) / 2, 1, splitk);
    hgemm_nt<<<g, 256, NT_SMEM>>>(M, M, K, A, lda, B, ldb, C, ldc, 2, 1);
}

// exact-bf16 adjacency GCN (XW-first order)
static void run_gcn_exact(const __nv_bfloat16* bApI, int n, int np,
                          const float* X, int inC, const float* W, int outC, const float* b,
                          float* out, int act, int splitk,
                          float* xw, float* t, float* dis, __nv_bfloat16* zpk) {
    run_sgemm(n, outC, inC, X, W, nullptr, xw, ACT_NONE);
    k_dis_b<<<n, 256>>>(bApI, np, np, dis);
    int Cpad = (outC % 128 == 0) ? outC : 128;
    int W2 = 2 * Cpad;
    int tot = np * W2;
    k_scale_pack<<<(tot + 255) / 256, 256>>>(xw, dis, n, np, outC, Cpad, zpk);
    cudaMemsetAsync(t, 0, (size_t)np * W2 * sizeof(float), 0);
    run_nn(np, W2, np, bApI, np, zpk, W2, t, W2, 2, splitk);
    int nc = n * outC;
    k_epilogue_sum2<<<(nc + 255) / 256, 256>>>(t, W2, Cpad, dis, b, n, outC, out, act);
}

// split-adjacency GCN
static void run_gcn_split(const __nv_bfloat16* X2, int n, int np,
                          const float* X, int inC, const float* W, int outC, const float* b,
                          float* out, int act, int splitk,
                          float* xw, float* t, float* dis, __nv_bfloat16* Bp) {
    run_sgemm(n, outC, inC, X, W, nullptr, xw, ACT_NONE);
    k_dis_b<<<n, 256>>>(X2, 2 * np, 2 * np, dis);
    int W2 = 2 * outC;
    int tot = 2 * np * W2;
    k_scale_pack_stk<<<(tot + 255) / 256, 256>>>(xw, dis, n, np, outC, Bp);
    cudaMemsetAsync(t, 0, (size_t)np * W2 * sizeof(float), 0);
    run_nn(np, W2, 2 * np, X2, 2 * np, Bp, W2, t, W2, 2, splitk);
    int nc = n * outC;
    k_epilogue_sum2<<<(nc + 255) / 256, 256>>>(t, W2, outC, dis, b, n, outC, out, act);
}

static void run_scores_sort(const float* h, int n, int npad, const float* p, int k,
                            int* perm, float* score, float* pn) {
    k_pnorm<<<1, 256>>>(p, HC, pn);
    k_scores<<<(n + 7) / 8, 256>>>(h, n, HC, p, pn, score);
    k_sort_topk<<<1, 1024>>>(score, n, npad, k, perm);
}

extern "C" void kernel_launch(void* const* d_in, const int* in_sizes, int n_in,
                              void* d_out, int out_size) {
    const float* x   = (const float*)d_in[0];
    const int*   ei  = (const int*)  d_in[1];
    const float* Wd0 = (const float*)d_in[2];  const float* bd0 = (const float*)d_in[3];
    const float* Wd1 = (const float*)d_in[4];  const float* bd1 = (const float*)d_in[5];
    const float* Wd2 = (const float*)d_in[6];  const float* bd2 = (const float*)d_in[7];
    const float* Wd3 = (const float*)d_in[8];  const float* bd3 = (const float*)d_in[9];
    const float* p1  = (const float*)d_in[10];
    const float* p2  = (const float*)d_in[11];
    const float* p3  = (const float*)d_in[12];
    const float* Wu0 = (const float*)d_in[13]; const float* bu0 = (const float*)d_in[14];
    const float* Wu1 = (const float*)d_in[15]; const float* bu1 = (const float*)d_in[16];
    const float* Wu2 = (const float*)d_in[17]; const float* bu2 = (const float*)d_in[18];
    const int E = in_sizes[1] / 2;

    float *Augp, *h0, *h1, *h2, *h3, *hb, *xw, *t, *u, *dis, *sc, *pn;
    int *pm0, *pm1, *pm2;
    __nv_bfloat16 *bA0, *bA1, *bX2, *bX3, *G, *Q, *zpk;
    cudaGetSymbolAddress((void**)&Augp, g_Augp);
    cudaGetSymbolAddress((void**)&h0,  g_h0);
    cudaGetSymbolAddress((void**)&h1,  g_h1);
    cudaGetSymbolAddress((void**)&h2,  g_h2);
    cudaGetSymbolAddress((void**)&h3,  g_h3);
    cudaGetSymbolAddress((void**)&hb,  g_hb);
    cudaGetSymbolAddress((void**)&xw,  g_xw);
    cudaGetSymbolAddress((void**)&t,   g_t);
    cudaGetSymbolAddress((void**)&u,   g_u);
    cudaGetSymbolAddress((void**)&dis, g_dis);
    cudaGetSymbolAddress((void**)&sc,  g_sc);
    cudaGetSymbolAddress((void**)&pn,  g_pn);
    cudaGetSymbolAddress((void**)&pm0, g_perm0);
    cudaGetSymbolAddress((void**)&pm1, g_perm1);
    cudaGetSymbolAddress((void**)&pm2, g_perm2);
    cudaGetSymbolAddress((void**)&bA0, g_bA0);
    cudaGetSymbolAddress((void**)&bA1, g_bA1);
    cudaGetSymbolAddress((void**)&bX2, g_bX2);
    cudaGetSymbolAddress((void**)&bX3, g_bX3);
    cudaGetSymbolAddress((void**)&G,   g_G);
    cudaGetSymbolAddress((void**)&Q,   g_Q);
    cudaGetSymbolAddress((void**)&zpk, g_zpk);

    // ---- build bf16(A0+I) directly ----
    cudaMemsetAsync(bA0, 0, (size_t)N0 * N0 * sizeof(__nv_bfloat16), 0);
    k_edges_b<<<(E + 255) / 256, 256>>>(ei, E, bA0);
    k_diag1_b<<<(N0 + 255) / 256, 256>>>(bA0, N0, N0);

    // ---- down path: level 0, adjacency-first order (inC=128 << 512) ----
    k_dis_b<<<N0, 256>>>(bA0, N0, N0, dis);
    k_scale_pack<<<(N0 * 256 + 255) / 256, 256>>>(x, dis, N0, N0, INC, INC, zpk);
    cudaMemsetAsync(t, 0, (size_t)N0 * 256 * sizeof(float), 0);
    run_nn(N0, 256, N0, bA0, N0, zpk, 256, t, 256, 2, 4);
    k_sum2_scale<<<(N0 * INC + 255) / 256, 256>>>(t, 256, INC, dis, N0, INC, xw);
    run_sgemm(N0, HC, INC, xw, Wd0, bd0, h0, ACT_RELU);

    // pool0: A1 = [(A0+I)^2]_{perm0,perm0} = G@G^T (symmetric, upper tiles only)
    run_scores_sort(h0, N0, 4096, p1, KP1, pm0, sc, pn);
    k_gather_rows<<<(2048 * 4096 + 255) / 256, 256>>>(bA0, 4096, pm0, KP1, 2048, G);
    cudaMemsetAsync(Augp, 0, (size_t)2048 * 2048 * sizeof(float), 0);
    run_nt_tri(2048, 4096, G, 4096, G, 4096, Augp, 2048, 2);
    k_gatherX<<<(KP1 * HC + 255) / 256, 256>>>(h0, HC, pm0, sc, KP1, u);
    k_crop_tobf16<<<(2048 * 2048 + 255) / 256, 256>>>(Augp, 2048, KP1, 2048, bA1);
    run_gcn_exact(bA1, KP1, 2048, u, HC, Wd1, HC, bd1, h1, ACT_RELU, 4,
                  xw, t, dis, zpk);

    // pool1: A2 submatrix via G@G^T (symmetric)
    run_scores_sort(h1, KP1, 2048, p2, KP2, pm1, sc, pn);
    k_gather_rows<<<(1024 * 2048 + 255) / 256, 256>>>(bA1, 2048, pm1, KP2, 1024, G);
    cudaMemsetAsync(Augp, 0, (size_t)1024 * 1024 * sizeof(float), 0);
    run_nt_tri(1024, 2048, G, 2048, G, 2048, Augp, 1024, 8);
    k_gatherX<<<(KP2 * HC + 255) / 256, 256>>>(h1, HC, pm1, sc, KP2, u);
    k_crop_pack_X<<<(1024 * 1024 + 255) / 256, 256>>>(Augp, 1024, KP2, 1024, bX2);
    run_gcn_split(bX2, KP2, 1024, u, HC, Wd2, HC, bd2, h2, ACT_RELU, 2,
                  xw, t, dis, zpk);

    // pool2: A3 = P@P^T + P@Q^T (both symmetric, exact hi/lo split)
    run_scores_sort(h2, KP2, 1024, p3, KP3, pm2, sc, pn);
    k_gather_PQ_b<<<(512 * 2048 + 255) / 256, 256>>>(bX2, 1024, pm2, KP3, 512, G, Q);
    cudaMemsetAsync(Augp, 0, (size_t)512 * 512 * sizeof(float), 0);
    run_nt_tri(512, 2048, G, 2048, G, 2048, Augp, 512, 8);
    run_nt_tri(512, 2048, G, 2048, Q, 2048, Augp, 512, 8);
    k_gatherX<<<(KP3 * HC + 255) / 256, 256>>>(h2, HC, pm2, sc, KP3, u);
    k_crop_pack_X<<<(512 * 512 + 255) / 256, 256>>>(Augp, 512, KP3, 512, bX3);
    run_gcn_split(bX3, KP3, 512, u, HC, Wd3, HC, bd3, h3, ACT_RELU, 4,
                  xw, t, dis, zpk);

    // ---- up path ----
    cudaMemcpyAsync(u, h2, (size_t)KP2 * HC * sizeof(float), cudaMemcpyDeviceToDevice, 0);
    k_scatter_add<<<(KP3 * HC + 255) / 256, 256>>>(u, h3, pm2, KP3, HC);
    run_gcn_split(bX2, KP2, 1024, u, HC, Wu0, HC, bu0, hb, ACT_RELU, 2,
                  xw, t, dis, zpk);

    cudaMemcpyAsync(u, h1, (size_t)KP1 * HC * sizeof(float), cudaMemcpyDeviceToDevice, 0);
    k_scatter_add<<<(KP2 * HC + 255) / 256, 256>>>(u, hb, pm1, KP2, HC);
    run_gcn_exact(bA1, KP1, 2048, u, HC, Wu1, HC, bu1, hb, ACT_RELU, 4,
                  xw, t, dis, zpk);

    cudaMemcpyAsync(u, h0, (size_t)N0 * HC * sizeof(float), cudaMemcpyDeviceToDevice, 0);
    k_scatter_add<<<(KP1 * HC + 255) / 256, 256>>>(u, hb, pm0, KP1, HC);
    run_gcn_exact(bA0, N0, 4096, u, HC, Wu2, OC, bu2, (float*)d_out, ACT_SIGM, 4,
                  xw, t, dis, zpk);
}

// round 11
// speedup vs baseline: 1.5579x; 1.3796x over previous
#include <cuda_runtime.h>
#include <cuda_bf16.h>
#include <cstdint>
#include <math.h>

// ---------------- problem constants ----------------
#define N0   4096
#define INC  128
#define HC   512
#define OC   64
#define KP1  2000
#define KP2  1000
#define KP3  500

#define ACT_NONE 0
#define ACT_RELU 1
#define ACT_SIGM 2

// ---------------- scratch (device globals; allocation-free) ----------------
__device__ float g_Augp[(size_t)2048*2048];
__device__ float g_h0 [(size_t)N0*HC];
__device__ float g_h1 [(size_t)KP1*HC];
__device__ float g_h2 [(size_t)KP2*HC];
__device__ float g_h3 [(size_t)KP3*HC];
__device__ float g_hb [(size_t)KP1*HC];
__device__ float g_xw [(size_t)N0*HC];
__device__ float g_t  [(size_t)4096*1024];
__device__ float g_u  [(size_t)N0*HC];
__device__ float g_dis[N0];
__device__ float g_sc [N0];
__device__ float g_pn [1];
__device__ int   g_perm0[KP1];
__device__ int   g_perm1[KP2];
__device__ int   g_perm2[KP3];
__device__ __nv_bfloat16 g_bA0 [(size_t)4096*4096];  // bf16(A0+I)
__device__ __nv_bfloat16 g_bA1 [(size_t)2048*2048];  // bf16(A1+I)
__device__ __nv_bfloat16 g_bX2 [(size_t)1024*2048];  // (A2+I) split [hi|lo]
__device__ __nv_bfloat16 g_bX3 [(size_t)512*1024];   // (A3+I) split [hi|lo]
__device__ __nv_bfloat16 g_G  [(size_t)2048*4096];   // row-gathered operand / P
__device__ __nv_bfloat16 g_Q  [(size_t)512*2048];    // pool2 [lo|hi] operand
__device__ __nv_bfloat16 g_zpk[(size_t)4096*1024];   // packed z operand
__device__ __nv_bfloat16 g_Xpk[(size_t)4096*1536];   // packed feature operand [hi|lo|hi]
__device__ __nv_bfloat16 g_Wpk[(size_t)1536*512];    // packed weight operand [hi;hi;lo]

// ---------------- cp.async helpers ----------------
#define CPASYNC16(dst_u32, src_ptr) \
    asm volatile("cp.async.ca.shared.global [%0], [%1], 16;" :: "r"(dst_u32), "l"(src_ptr))
#define CP_COMMIT() asm volatile("cp.async.commit_group;")

// 128x128 tiles, 4-stage pipeline, dynamic smem (2 CTAs/SM)
#define NN_AS (128*40)
#define NN_BS (32*136)
#define NT_AS (128*40)
#define NT_BS (128*40)
#define NN_SMEM (4 * (NN_AS + NN_BS) * 2)   // 75776 B
#define NT_SMEM (4 * (NT_AS + NT_BS) * 2)   // 81920 B

// acc: 0 = store (+optional bias/act), 2 = atomicAdd (C pre-zeroed; split-K)
// ---------------- NN GEMM: C(MxN) = A(MxK) @ B(KxN), bf16->fp32 ----------------
__global__ void __launch_bounds__(256) hgemm_nn(int M, int N, int K,
        const __nv_bfloat16* __restrict__ A, int lda,
        const __nv_bfloat16* __restrict__ B, int ldb,
        float* __restrict__ C, int ldc, int acc,
        const float* __restrict__ bias, int act) {
    extern __shared__ __nv_bfloat16 dsm[];
    __nv_bfloat16* Asm = dsm;
    __nv_bfloat16* Bsm = dsm + 4 * NN_AS;
    const int tid  = threadIdx.x;
    const int lane = tid & 31;
    const int warp = tid >> 5;
    const int wm = (warp >> 2) * 64;
    const int wn = (warp & 3) * 32;
    const int m0 = blockIdx.y * 128;
    const int n0 = blockIdx.x * 128;
    const int Kc = K / gridDim.z;
    const int k0 = blockIdx.z * Kc;

    const int ar = tid >> 1, ac = (tid & 1) * 16;
    const int br = tid >> 3, bc = (tid & 7) * 16;

    float c[4][4][4];
#pragma unroll
    for (int mt = 0; mt < 4; mt++)
#pragma unroll
        for (int nt = 0; nt < 4; nt++)
#pragma unroll
            for (int r = 0; r < 4; r++) c[mt][nt][r] = 0.f;

    const int ntile = Kc >> 5;

#define NN_LOAD(s, kk) { \
    unsigned da = (unsigned)__cvta_generic_to_shared(Asm + (s) * NN_AS + ar * 40 + ac); \
    const __nv_bfloat16* pa = A + (size_t)(m0 + ar) * lda + (kk) + ac; \
    CPASYNC16(da, pa); CPASYNC16(da + 16, pa + 8); \
    unsigned db = (unsigned)__cvta_generic_to_shared(Bsm + (s) * NN_BS + br * 136 + bc); \
    const __nv_bfloat16* pb = B + (size_t)((kk) + br) * ldb + n0 + bc; \
    CPASYNC16(db, pb); CPASYNC16(db + 16, pb + 8); }

    for (int p = 0; p < 3; ++p) {
        if (p < ntile) NN_LOAD(p, k0 + p * 32);
        CP_COMMIT();
    }

    for (int it = 0; it < ntile; ++it) {
        asm volatile("cp.async.wait_group 2;");
        __syncthreads();
        int pf = it + 3;
        if (pf < ntile) NN_LOAD(pf & 3, k0 + pf * 32);
        CP_COMMIT();

        const int s = it & 3;
        const __nv_bfloat16* As_s = Asm + s * NN_AS;
        const __nv_bfloat16* Bs_s = Bsm + s * NN_BS;
#pragma unroll
        for (int ks = 0; ks < 32; ks += 16) {
            uint32_t af[4][4];
#pragma unroll
            for (int mt = 0; mt < 4; mt++) {
                unsigned addr = (unsigned)__cvta_generic_to_shared(
                    As_s + (wm + mt * 16 + (lane & 15)) * 40 + ks + (lane >> 4) * 8);
                asm volatile("ldmatrix.sync.aligned.m8n8.x4.shared.b16 {%0,%1,%2,%3}, [%4];"
                    : "=r"(af[mt][0]), "=r"(af[mt][1]), "=r"(af[mt][2]), "=r"(af[mt][3])
                    : "r"(addr));
            }
            uint32_t bfr[4][2];
#pragma unroll
            for (int nt = 0; nt < 4; nt++) {
                unsigned addr = (unsigned)__cvta_generic_to_shared(
                    Bs_s + (ks + (lane & 15)) * 136 + wn + nt * 8);
                asm volatile("ldmatrix.sync.aligned.m8n8.x2.trans.shared.b16 {%0,%1}, [%2];"
                    : "=r"(bfr[nt][0]), "=r"(bfr[nt][1]) : "r"(addr));
            }
#pragma unroll
            for (int mt = 0; mt < 4; mt++)
#pragma unroll
                for (int nt = 0; nt < 4; nt++)
                    asm volatile(
                        "mma.sync.aligned.m16n8k16.row.col.f32.bf16.bf16.f32 "
                        "{%0,%1,%2,%3}, {%4,%5,%6,%7}, {%8,%9}, {%0,%1,%2,%3};"
                        : "+f"(c[mt][nt][0]), "+f"(c[mt][nt][1]),
                          "+f"(c[mt][nt][2]), "+f"(c[mt][nt][3])
                        : "r"(af[mt][0]), "r"(af[mt][1]), "r"(af[mt][2]), "r"(af[mt][3]),
                          "r"(bfr[nt][0]), "r"(bfr[nt][1]));
        }
        __syncthreads();
    }

    const int r0 = lane >> 2, c0 = (lane & 3) * 2;
#pragma unroll
    for (int mt = 0; mt < 4; mt++)
#pragma unroll
        for (int nt = 0; nt < 4; nt++) {
            int row = m0 + wm + mt * 16 + r0;
            int col = n0 + wn + nt * 8 + c0;
            float* p0 = C + (size_t)row * ldc + col;
            float* p1 = C + (size_t)(row + 8) * ldc + col;
            if (acc == 2) {
                atomicAdd(p0,     c[mt][nt][0]); atomicAdd(p0 + 1, c[mt][nt][1]);
                atomicAdd(p1,     c[mt][nt][2]); atomicAdd(p1 + 1, c[mt][nt][3]);
            } else {
                float v0 = c[mt][nt][0], v1 = c[mt][nt][1];
                float v2 = c[mt][nt][2], v3 = c[mt][nt][3];
                if (bias) { v0 += bias[col]; v1 += bias[col + 1];
                            v2 += bias[col]; v3 += bias[col + 1]; }
                if (act == ACT_RELU) {
                    v0 = fmaxf(v0, 0.f); v1 = fmaxf(v1, 0.f);
                    v2 = fmaxf(v2, 0.f); v3 = fmaxf(v3, 0.f);
                }
                p0[0] = v0; p0[1] = v1;
                p1[0] = v2; p1[1] = v3;
            }
        }
}

// ---------------- NT GEMM: C(MxN) = A(MxK) @ B(NxK)^T ----------------
// tri != 0: C symmetric, M==N; compute only tiles with n-tile >= m-tile.
__global__ void __launch_bounds__(256) hgemm_nt(int M, int N, int K,
        const __nv_bfloat16* __restrict__ A, int lda,
        const __nv_bfloat16* __restrict__ B, int ldb,
        float* __restrict__ C, int ldc, int acc, int tri) {
    extern __shared__ __nv_bfloat16 dsm[];
    __nv_bfloat16* Asm = dsm;
    __nv_bfloat16* Bsm = dsm + 4 * NT_AS;
    const int tid  = threadIdx.x;
    const int lane = tid & 31;
    const int warp = tid >> 5;
    const int wm = (warp >> 2) * 64;
    const int wn = (warp & 3) * 32;

    int m0, n0;
    if (tri) {
        int bid = blockIdx.x;
        int by = (int)((sqrtf(8.f * bid + 1.f) - 1.f) * 0.5f);
        while ((by + 1) * (by + 2) / 2 <= bid) by++;
        while (by * (by + 1) / 2 > bid) by--;
        int bx = bid - by * (by + 1) / 2;
        m0 = bx * 128;
        n0 = by * 128;
    } else {
        m0 = blockIdx.y * 128;
        n0 = blockIdx.x * 128;
    }
    const int Kc = K / gridDim.z;
    const int k0 = blockIdx.z * Kc;

    const int ar = tid >> 1, ac = (tid & 1) * 16;

    float c[4][4][4];
#pragma unroll
    for (int mt = 0; mt < 4; mt++)
#pragma unroll
        for (int nt = 0; nt < 4; nt++)
#pragma unroll
            for (int r = 0; r < 4; r++) c[mt][nt][r] = 0.f;

    const int ntile = Kc >> 5;

#define NT_LOAD(s, kk) { \
    unsigned da = (unsigned)__cvta_generic_to_shared(Asm + (s) * NT_AS + ar * 40 + ac); \
    const __nv_bfloat16* pa = A + (size_t)(m0 + ar) * lda + (kk) + ac; \
    CPASYNC16(da, pa); CPASYNC16(da + 16, pa + 8); \
    unsigned db = (unsigned)__cvta_generic_to_shared(Bsm + (s) * NT_BS + ar * 40 + ac); \
    const __nv_bfloat16* pb = B + (size_t)(n0 + ar) * ldb + (kk) + ac; \
    CPASYNC16(db, pb); CPASYNC16(db + 16, pb + 8); }

    for (int p = 0; p < 3; ++p) {
        if (p < ntile) NT_LOAD(p, k0 + p * 32);
        CP_COMMIT();
    }

    for (int it = 0; it < ntile; ++it) {
        asm volatile("cp.async.wait_group 2;");
        __syncthreads();
        int pf = it + 3;
        if (pf < ntile) NT_LOAD(pf & 3, k0 + pf * 32);
        CP_COMMIT();

        const int s = it & 3;
        const __nv_bfloat16* As_s = Asm + s * NT_AS;
        const __nv_bfloat16* Bs_s = Bsm + s * NT_BS;
#pragma unroll
        for (int ks = 0; ks < 32; ks += 16) {
            uint32_t af[4][4];
#pragma unroll
            for (int mt = 0; mt < 4; mt++) {
                unsigned addr = (unsigned)__cvta_generic_to_shared(
                    As_s + (wm + mt * 16 + (lane & 15)) * 40 + ks + (lane >> 4) * 8);
                asm volatile("ldmatrix.sync.aligned.m8n8.x4.shared.b16 {%0,%1,%2,%3}, [%4];"
                    : "=r"(af[mt][0]), "=r"(af[mt][1]), "=r"(af[mt][2]), "=r"(af[mt][3])
                    : "r"(addr));
            }
            uint32_t bfr[4][2];
#pragma unroll
            for (int nt = 0; nt < 4; nt++) {
                unsigned addr = (unsigned)__cvta_generic_to_shared(
                    Bs_s + (wn + nt * 8 + (lane & 7)) * 40 + ks + ((lane >> 3) & 1) * 8);
                asm volatile("ldmatrix.sync.aligned.m8n8.x2.shared.b16 {%0,%1}, [%2];"
                    : "=r"(bfr[nt][0]), "=r"(bfr[nt][1]) : "r"(addr));
            }
#pragma unroll
            for (int mt = 0; mt < 4; mt++)
#pragma unroll
                for (int nt = 0; nt < 4; nt++)
                    asm volatile(
                        "mma.sync.aligned.m16n8k16.row.col.f32.bf16.bf16.f32 "
                        "{%0,%1,%2,%3}, {%4,%5,%6,%7}, {%8,%9}, {%0,%1,%2,%3};"
                        : "+f"(c[mt][nt][0]), "+f"(c[mt][nt][1]),
                          "+f"(c[mt][nt][2]), "+f"(c[mt][nt][3])
                        : "r"(af[mt][0]), "r"(af[mt][1]), "r"(af[mt][2]), "r"(af[mt][3]),
                          "r"(bfr[nt][0]), "r"(bfr[nt][1]));
        }
        __syncthreads();
    }

    const int r0 = lane >> 2, c0 = (lane & 3) * 2;
#pragma unroll
    for (int mt = 0; mt < 4; mt++)
#pragma unroll
        for (int nt = 0; nt < 4; nt++) {
            int row = m0 + wm + mt * 16 + r0;
            int col = n0 + wn + nt * 8 + c0;
            float* p0 = C + (size_t)row * ldc + col;
            float* p1 = C + (size_t)(row + 8) * ldc + col;
            if (acc == 2) {
                atomicAdd(p0,     c[mt][nt][0]); atomicAdd(p0 + 1, c[mt][nt][1]);
                atomicAdd(p1,     c[mt][nt][2]); atomicAdd(p1 + 1, c[mt][nt][3]);
            } else {
                p0[0] = c[mt][nt][0]; p0[1] = c[mt][nt][1];
                p1[0] = c[mt][nt][2]; p1[1] = c[mt][nt][3];
            }
        }
}

// ---------------- SGEMM (fp32 SIMT) with optional fused bias+act ----------------
__global__ void __launch_bounds__(256) sgemm(int M, int N, int K,
                                             const float* __restrict__ A,
                                             const float* __restrict__ B,
                                             const float* __restrict__ bias,
                                             float* __restrict__ C, int act) {
    __shared__ float As[8][128];
    __shared__ float Bs[8][128];
    const int tid  = threadIdx.x;
    const int tx   = tid & 15;
    const int ty   = tid >> 4;
    const int row0 = blockIdx.y * 128;
    const int col0 = blockIdx.x * 128;
    const int a_row = tid >> 1, a_col = (tid & 1) << 2;
    const int b_row = tid >> 5, b_col = (tid & 31) << 2;

    float acc[8][8];
#pragma unroll
    for (int i = 0; i < 8; i++)
#pragma unroll
        for (int j = 0; j < 8; j++) acc[i][j] = 0.f;

    for (int kk = 0; kk < K; kk += 8) {
        float4 av = make_float4(0.f, 0.f, 0.f, 0.f);
        {
            int gm = row0 + a_row, gk = kk + a_col;
            if (gm < M && gk < K)
                av = *reinterpret_cast<const float4*>(A + (size_t)gm * K + gk);
        }
        As[a_col + 0][a_row] = av.x;
        As[a_col + 1][a_row] = av.y;
        As[a_col + 2][a_row] = av.z;
        As[a_col + 3][a_row] = av.w;

        float4 bv = make_float4(0.f, 0.f, 0.f, 0.f);
        {
            int gk = kk + b_row, gn = col0 + b_col;
            if (gk < K && gn < N)
                bv = *reinterpret_cast<const float4*>(B + (size_t)gk * N + gn);
        }
        *reinterpret_cast<float4*>(&Bs[b_row][b_col]) = bv;
        __syncthreads();

#pragma unroll
        for (int k = 0; k < 8; k++) {
            float4 a0 = *reinterpret_cast<const float4*>(&As[k][ty * 8]);
            float4 a1 = *reinterpret_cast<const float4*>(&As[k][ty * 8 + 4]);
            float4 b0 = *reinterpret_cast<const float4*>(&Bs[k][tx * 8]);
            float4 b1 = *reinterpret_cast<const float4*>(&Bs[k][tx * 8 + 4]);
            float a[8] = {a0.x, a0.y, a0.z, a0.w, a1.x, a1.y, a1.z, a1.w};
            float b[8] = {b0.x, b0.y, b0.z, b0.w, b1.x, b1.y, b1.z, b1.w};
#pragma unroll
            for (int i = 0; i < 8; i++)
#pragma unroll
                for (int j = 0; j < 8; j++) acc[i][j] += a[i] * b[j];
        }
        __syncthreads();
    }

#pragma unroll
    for (int i = 0; i < 8; i++) {
        int gm = row0 + ty * 8 + i;
        if (gm >= M) continue;
        float* Cr = C + (size_t)gm * N;
#pragma unroll
        for (int j = 0; j < 8; j++) {
            int gn = col0 + tx * 8 + j;
            if (gn >= N) continue;
            float v = acc[i][j];
            if (bias) v += bias[gn];
            if (act == ACT_RELU) v = fmaxf(v, 0.f);
            else if (act == ACT_SIGM) v = 1.f / (1.f + expf(-v));
            Cr[gn] = v;
        }
    }
}

// ---------------- elementwise / graph kernels ----------------
__global__ void k_edges_b(const int* __restrict__ ei, int E, __nv_bfloat16* __restrict__ A) {
    int e = blockIdx.x * blockDim.x + threadIdx.x;
    if (e >= E) return;
    int s = ei[e], d = ei[E + e];
    __nv_bfloat16 one = __float2bfloat16(1.f);
    A[(size_t)s * N0 + d] = one;
    A[(size_t)d * N0 + s] = one;
}

__global__ void k_diag1_b(__nv_bfloat16* __restrict__ A, int n, int ld) {
    int i = blockIdx.x * blockDim.x + threadIdx.x;
    if (i < n) {
        size_t p = (size_t)i * ld + i;
        A[p] = __float2bfloat16(__bfloat162float(A[p]) + 1.f);
    }
}

__global__ void k_dis_b(const __nv_bfloat16* __restrict__ M, int ld, int w,
                        float* __restrict__ dis) {
    __shared__ float red[256];
    int row = blockIdx.x;
    const __nv_bfloat16* Mr = M + (size_t)row * ld;
    float s = 0.f;
    for (int j = threadIdx.x; j < w; j += 256) s += __bfloat162float(Mr[j]);
    red[threadIdx.x] = s;
    __syncthreads();
    for (int o = 128; o > 0; o >>= 1) {
        if (threadIdx.x < o) red[threadIdx.x] += red[threadIdx.x + o];
        __syncthreads();
    }
    if (threadIdx.x == 0) dis[row] = rsqrtf(red[0]);
}

__global__ void k_scale_pack(const float* __restrict__ xw, const float* __restrict__ dis,
                             int n, int np, int C, int Cpad,
                             __nv_bfloat16* __restrict__ zpk) {
    int i = blockIdx.x * blockDim.x + threadIdx.x;
    int W = 2 * Cpad;
    if (i >= np * W) return;
    int r = i / W, cc = i - r * W;
    int col = (cc < Cpad) ? cc : cc - Cpad;
    float v = (r < n && col < C) ? dis[r] * xw[(size_t)r * C + col] : 0.f;
    __nv_bfloat16 hi = __float2bfloat16(v);
    if (cc < Cpad) zpk[i] = hi;
    else           zpk[i] = __float2bfloat16(v - __bfloat162float(hi));
}

__global__ void k_scale_pack_stk(const float* __restrict__ xw, const float* __restrict__ dis,
                                 int n, int np, int C,
                                 __nv_bfloat16* __restrict__ Bp) {
    int i = blockIdx.x * blockDim.x + threadIdx.x;
    int W = 2 * C;
    if (i >= 2 * np * W) return;
    int r = i / W, cc = i - r * W;
    int rr = (r < np) ? r : r - np;
    int col = (cc < C) ? cc : cc - C;
    float v = (rr < n) ? dis[rr] * xw[(size_t)rr * C + col] : 0.f;
    __nv_bfloat16 hi = __float2bfloat16(v);
    __nv_bfloat16 lo = __float2bfloat16(v - __bfloat162float(hi));
    bool wantHi = ((r < np) == (cc < C));
    Bp[i] = wantHi ? hi : lo;
}

// feature pack: Xp (np x 3C) = [hi(X) | lo(X) | hi(X)]
__global__ void k_packX3(const float* __restrict__ X, int np, int C,
                         __nv_bfloat16* __restrict__ Xp) {
    int i = blockIdx.x * blockDim.x + threadIdx.x;
    int W = 3 * C;
    if (i >= np * W) return;
    int r = i / W, cc = i - r * W;
    int col = cc; if (col >= C) col -= C; if (col >= C) col -= C;
    float v = X[(size_t)r * C + col];
    __nv_bfloat16 hi = __float2bfloat16(v);
    bool isLo = (cc >= C && cc < 2 * C);
    Xp[i] = isLo ? __float2bfloat16(v - __bfloat162float(hi)) : hi;
}

// weight pack: Wp (3K x N) = [Whi ; Whi ; Wlo]
__global__ void k_packW3(const float* __restrict__ W, int K, int N,
                         __nv_bfloat16* __restrict__ Wp) {
    int i = blockIdx.x * blockDim.x + threadIdx.x;
    if (i >= 3 * K * N) return;
    int r = i / N, cc = i - r * N;
    int rr = r; if (rr >= K) rr -= K; if (rr >= K) rr -= K;
    float v = W[(size_t)rr * N + cc];
    __nv_bfloat16 hi = __float2bfloat16(v);
    Wp[i] = (r < 2 * K) ? hi : __float2bfloat16(v - __bfloat162float(hi));
}

__global__ void k_epilogue_sum2(const float* __restrict__ t, int ldt, int half,
                                const float* __restrict__ dis, const float* __restrict__ b,
                                int n, int C, float* __restrict__ out, int act) {
    int i = blockIdx.x * blockDim.x + threadIdx.x;
    if (i >= n * C) return;
    int r = i / C, cc = i - r * C;
    float v = dis[r] * (t[(size_t)r * ldt + cc] + t[(size_t)r * ldt + cc + half]) + b[cc];
    if (act == ACT_RELU) v = fmaxf(v, 0.f);
    else if (act == ACT_SIGM) v = 1.f / (1.f + expf(-v));
    out[i] = v;
}

__global__ void k_sum2_scale(const float* __restrict__ t, int ldt, int half,
                             const float* __restrict__ dis, int n, int C,
                             float* __restrict__ S) {
    int i = blockIdx.x * blockDim.x + threadIdx.x;
    if (i >= n * C) return;
    int r = i / C, cc = i - r * C;
    S[i] = dis[r] * (t[(size_t)r * ldt + cc] + t[(size_t)r * ldt + cc + half]);
}

__global__ void k_crop_tobf16(const float* __restrict__ Augp, int kpad, int k, int np,
                              __nv_bfloat16* __restrict__ bA) {
    int i = blockIdx.x * blockDim.x + threadIdx.x;
    if (i >= np * np) return;
    int r = i / np, cc = i - r * np;
    float v = 0.f;
    if (r < k && cc < k) {
        if (r == cc) v = 1.f;
        else {
            int rr = (r < cc) ? r : cc;
            int c2 = (r < cc) ? cc : r;
            v = Augp[(size_t)rr * kpad + c2];
        }
    }
    bA[i] = __float2bfloat16(v);
}

__global__ void k_crop_pack_X(const float* __restrict__ Augp, int kpad, int k, int np,
                              __nv_bfloat16* __restrict__ X) {
    int i = blockIdx.x * blockDim.x + threadIdx.x;
    if (i >= np * np) return;
    int r = i / np, cc = i - r * np;
    float v = 0.f;
    if (r < k && cc < k) {
        if (r == cc) v = 1.f;
        else {
            int rr = (r < cc) ? r : cc;
            int c2 = (r < cc) ? cc : r;
            v = Augp[(size_t)rr * kpad + c2];
        }
    }
    __nv_bfloat16 hi = __float2bfloat16(v);
    __nv_bfloat16 lo = __float2bfloat16(v - __bfloat162float(hi));
    X[(size_t)r * (2 * np) + cc]      = hi;
    X[(size_t)r * (2 * np) + np + cc] = lo;
}

__global__ void k_gather_rows(const __nv_bfloat16* __restrict__ bApI, int np,
                              const int* __restrict__ perm, int k, int kpad,
                              __nv_bfloat16* __restrict__ G) {
    int i = blockIdx.x * blockDim.x + threadIdx.x;
    if (i >= kpad * np) return;
    int r = i / np, j = i - r * np;
    G[i] = (r < k) ? bApI[(size_t)perm[r] * np + j] : __float2bfloat16(0.f);
}

__global__ void k_gather_PQ_b(const __nv_bfloat16* __restrict__ X2, int np,
                              const int* __restrict__ perm, int k, int kpad,
                              __nv_bfloat16* __restrict__ P,
                              __nv_bfloat16* __restrict__ Q) {
    int i = blockIdx.x * blockDim.x + threadIdx.x;
    int W = 2 * np;
    if (i >= kpad * W) return;
    int r = i / W, j = i - r * W;
    __nv_bfloat16 v = (r < k) ? X2[(size_t)perm[r] * W + j] : __float2bfloat16(0.f);
    P[i] = v;
    int js = (j < np) ? j + np : j - np;
    Q[(size_t)r * W + js] = v;
}

__global__ void k_pnorm(const float* __restrict__ p, int n, float* __restrict__ out) {
    __shared__ float red[256];
    float s = 0.f;
    for (int i = threadIdx.x; i < n; i += 256) s += p[i] * p[i];
    red[threadIdx.x] = s;
    __syncthreads();
    for (int o = 128; o > 0; o >>= 1) {
        if (threadIdx.x < o) red[threadIdx.x] += red[threadIdx.x + o];
        __syncthreads();
    }
    if (threadIdx.x == 0) out[0] = sqrtf(red[0]);
}

__global__ void k_scores(const float* __restrict__ h, int n, int C,
                         const float* __restrict__ p, const float* __restrict__ pn,
                         float* __restrict__ score) {
    int row = blockIdx.x * 8 + (threadIdx.x >> 5);
    int lane = threadIdx.x & 31;
    if (row >= n) return;
    const float* hr = h + (size_t)row * C;
    float s = 0.f;
    for (int cc = lane; cc < C; cc += 32) s += hr[cc] * p[cc];
    for (int o = 16; o > 0; o >>= 1) s += __shfl_xor_sync(0xffffffffu, s, o);
    if (lane == 0) score[row] = tanhf(s / pn[0]);
}

__global__ void __launch_bounds__(1024) k_sort_topk(const float* __restrict__ score,
                                                    int n, int npad, int k,
                                                    int* __restrict__ perm) {
    __shared__ float skey[4096];
    __shared__ int   sidx[4096];
    for (int i = threadIdx.x; i < npad; i += blockDim.x) {
        skey[i] = (i < n) ? score[i] : -INFINITY;
        sidx[i] = i;
    }
    __syncthreads();
    for (int kk = 2; kk <= npad; kk <<= 1) {
        for (int j = kk >> 1; j > 0; j >>= 1) {
            for (int i = threadIdx.x; i < npad; i += blockDim.x) {
                int ixj = i ^ j;
                if (ixj > i) {
                    float a = skey[i], b = skey[ixj];
                    bool sw = ((i & kk) == 0) ? (a < b) : (a > b);
                    if (sw) {
                        skey[i] = b; skey[ixj] = a;
                        int t = sidx[i]; sidx[i] = sidx[ixj]; sidx[ixj] = t;
                    }
                }
            }
            __syncthreads();
        }
    }
    for (int i = threadIdx.x; i < k; i += blockDim.x) perm[i] = sidx[i];
}

__global__ void k_gatherX(const float* __restrict__ h, int C,
                          const int* __restrict__ perm, const float* __restrict__ score,
                          int k, float* __restrict__ out) {
    int i = blockIdx.x * blockDim.x + threadIdx.x;
    if (i >= k * C) return;
    int r = i / C, cc = i - r * C;
    int pr = perm[r];
    out[i] = h[(size_t)pr * C + cc] * score[pr];
}

__global__ void k_scatter_add(float* __restrict__ u, const float* __restrict__ h,
                              const int* __restrict__ perm, int k, int C) {
    int i = blockIdx.x * blockDim.x + threadIdx.x;
    if (i >= k * C) return;
    int r = i / C, cc = i - r * C;
    u[(size_t)perm[r] * C + cc] += h[i];
}

// ---------------- host orchestration ----------------
static void run_sgemm(int M, int N, int K, const float* A, const float* B,
                      const float* bias, float* C, int act) {
    dim3 g((N + 127) / 128, (M + 127) / 128);
    sgemm<<<g, 256>>>(M, N, K, A, B, bias, C, act);
}
static void run_nn(int M, int N, int K, const __nv_bfloat16* A, int lda,
                   const __nv_bfloat16* B, int ldb, float* C, int ldc, int acc, int splitk,
                   const float* bias, int act) {
    cudaFuncSetAttribute(hgemm_nn, cudaFuncAttributeMaxDynamicSharedMemorySize, NN_SMEM);
    dim3 g(N / 128, M / 128, splitk);
    hgemm_nn<<<g, 256, NN_SMEM>>>(M, N, K, A, lda, B, ldb, C, ldc, acc, bias, act);
}
static void run_nt_tri(int M, int K, const __nv_bfloat16* A, int lda,
                       const __nv_bfloat16* B, int ldb, float* C, int ldc, int splitk) {
    cudaFuncSetAttribute(hgemm_nt, cudaFuncAttributeMaxDynamicSharedMemorySize, NT_SMEM);
    int T = M / 128;
    dim3 g(T * (T + 1) / 2, 1, splitk);
    hgemm_nt<<<g, 256, NT_SMEM>>>(M, M, K, A, lda, B, ldb, C, ldc, 2, 1);
}

// tensor-core feature GEMM: out(np x N) = X(np x C) @ W(C x N) via 3xK hi/lo split
static void run_xw_tc(const float* X, int np, int C, const float* W, int N,
                      const float* bias, int act, float* out, int splitk,
                      __nv_bfloat16* Xp, __nv_bfloat16* Wp) {
    int totX = np * 3 * C;
    k_packX3<<<(totX + 255) / 256, 256>>>(X, np, C, Xp);
    int totW = 3 * C * N;
    k_packW3<<<(totW + 255) / 256, 256>>>(W, C, N, Wp);
    if (splitk > 1) {
        cudaMemsetAsync(out, 0, (size_t)np * N * sizeof(float), 0);
        run_nn(np, N, 3 * C, Xp, 3 * C, Wp, N, out, N, 2, splitk, nullptr, ACT_NONE);
    } else {
        run_nn(np, N, 3 * C, Xp, 3 * C, Wp, N, out, N, 0, 1, bias, act);
    }
}

// exact-bf16 adjacency GCN (XW-first order); Cpad selectable
static void run_gcn_exact(const __nv_bfloat16* bApI, int n, int np,
                          const float* X, int inC, const float* W, int outC, const float* b,
                          float* out, int act, int splitk, int Cpad,
                          float* xw, float* t, float* dis, __nv_bfloat16* zpk,
                          __nv_bfloat16* Xp, __nv_bfloat16* Wp) {
    if (outC % 128 == 0)
        run_xw_tc(X, np, inC, W, outC, nullptr, ACT_NONE, xw, (np <= 512) ? 2 : 1, Xp, Wp);
    else
        run_sgemm(n, outC, inC, X, W, nullptr, xw, ACT_NONE);
    k_dis_b<<<n, 256>>>(bApI, np, np, dis);
    int W2 = 2 * Cpad;
    int tot = np * W2;
    k_scale_pack<<<(tot + 255) / 256, 256>>>(xw, dis, n, np, outC, Cpad, zpk);
    cudaMemsetAsync(t, 0, (size_t)np * W2 * sizeof(float), 0);
    run_nn(np, W2, np, bApI, np, zpk, W2, t, W2, 2, splitk, nullptr, ACT_NONE);
    int nc = n * outC;
    k_epilogue_sum2<<<(nc + 255) / 256, 256>>>(t, W2, Cpad, dis, b, n, outC, out, act);
}

// split-adjacency GCN
static void run_gcn_split(const __nv_bfloat16* X2, int n, int np,
                          const float* X, int inC, const float* W, int outC, const float* b,
                          float* out, int act, int splitk,
                          float* xw, float* t, float* dis, __nv_bfloat16* Bp,
                          __nv_bfloat16* Xp, __nv_bfloat16* Wp) {
    run_xw_tc(X, np, inC, W, outC, nullptr, ACT_NONE, xw, (np <= 512) ? 2 : 1, Xp, Wp);
    k_dis_b<<<n, 256>>>(X2, 2 * np, 2 * np, dis);
    int W2 = 2 * outC;
    int tot = 2 * np * W2;
    k_scale_pack_stk<<<(tot + 255) / 256, 256>>>(xw, dis, n, np, outC, Bp);
    cudaMemsetAsync(t, 0, (size_t)np * W2 * sizeof(float), 0);
    run_nn(np, W2, 2 * np, X2, 2 * np, Bp, W2, t, W2, 2, splitk, nullptr, ACT_NONE);
    int nc = n * outC;
    k_epilogue_sum2<<<(nc + 255) / 256, 256>>>(t, W2, outC, dis, b, n, outC, out, act);
}

static void run_scores_sort(const float* h, int n, int npad, const float* p, int k,
                            int* perm, float* score, float* pn) {
    k_pnorm<<<1, 256>>>(p, HC, pn);
    k_scores<<<(n + 7) / 8, 256>>>(h, n, HC, p, pn, score);
    k_sort_topk<<<1, 1024>>>(score, n, npad, k, perm);
}

extern "C" void kernel_launch(void* const* d_in, const int* in_sizes, int n_in,
                              void* d_out, int out_size) {
    const float* x   = (const float*)d_in[0];
    const int*   ei  = (const int*)  d_in[1];
    const float* Wd0 = (const float*)d_in[2];  const float* bd0 = (const float*)d_in[3];
    const float* Wd1 = (const float*)d_in[4];  const float* bd1 = (const float*)d_in[5];
    const float* Wd2 = (const float*)d_in[6];  const float* bd2 = (const float*)d_in[7];
    const float* Wd3 = (const float*)d_in[8];  const float* bd3 = (const float*)d_in[9];
    const float* p1  = (const float*)d_in[10];
    const float* p2  = (const float*)d_in[11];
    const float* p3  = (const float*)d_in[12];
    const float* Wu0 = (const float*)d_in[13]; const float* bu0 = (const float*)d_in[14];
    const float* Wu1 = (const float*)d_in[15]; const float* bu1 = (const float*)d_in[16];
    const float* Wu2 = (const float*)d_in[17]; const float* bu2 = (const float*)d_in[18];
    const int E = in_sizes[1] / 2;

    float *Augp, *h0, *h1, *h2, *h3, *hb, *xw, *t, *u, *dis, *sc, *pn;
    int *pm0, *pm1, *pm2;
    __nv_bfloat16 *bA0, *bA1, *bX2, *bX3, *G, *Q, *zpk, *Xp, *Wp;
    cudaGetSymbolAddress((void**)&Augp, g_Augp);
    cudaGetSymbolAddress((void**)&h0,  g_h0);
    cudaGetSymbolAddress((void**)&h1,  g_h1);
    cudaGetSymbolAddress((void**)&h2,  g_h2);
    cudaGetSymbolAddress((void**)&h3,  g_h3);
    cudaGetSymbolAddress((void**)&hb,  g_hb);
    cudaGetSymbolAddress((void**)&xw,  g_xw);
    cudaGetSymbolAddress((void**)&t,   g_t);
    cudaGetSymbolAddress((void**)&u,   g_u);
    cudaGetSymbolAddress((void**)&dis, g_dis);
    cudaGetSymbolAddress((void**)&sc,  g_sc);
    cudaGetSymbolAddress((void**)&pn,  g_pn);
    cudaGetSymbolAddress((void**)&pm0, g_perm0);
    cudaGetSymbolAddress((void**)&pm1, g_perm1);
    cudaGetSymbolAddress((void**)&pm2, g_perm2);
    cudaGetSymbolAddress((void**)&bA0, g_bA0);
    cudaGetSymbolAddress((void**)&bA1, g_bA1);
    cudaGetSymbolAddress((void**)&bX2, g_bX2);
    cudaGetSymbolAddress((void**)&bX3, g_bX3);
    cudaGetSymbolAddress((void**)&G,   g_G);
    cudaGetSymbolAddress((void**)&Q,   g_Q);
    cudaGetSymbolAddress((void**)&zpk, g_zpk);
    cudaGetSymbolAddress((void**)&Xp,  g_Xpk);
    cudaGetSymbolAddress((void**)&Wp,  g_Wpk);

    // ---- build bf16(A0+I) directly ----
    cudaMemsetAsync(bA0, 0, (size_t)N0 * N0 * sizeof(__nv_bfloat16), 0);
    k_edges_b<<<(E + 255) / 256, 256>>>(ei, E, bA0);
    k_diag1_b<<<(N0 + 255) / 256, 256>>>(bA0, N0, N0);

    // ---- down path: level 0, adjacency-first order (inC=128 << 512) ----
    k_dis_b<<<N0, 256>>>(bA0, N0, N0, dis);
    k_scale_pack<<<(N0 * 256 + 255) / 256, 256>>>(x, dis, N0, N0, INC, INC, zpk);
    cudaMemsetAsync(t, 0, (size_t)N0 * 256 * sizeof(float), 0);
    run_nn(N0, 256, N0, bA0, N0, zpk, 256, t, 256, 2, 4, nullptr, ACT_NONE);
    k_sum2_scale<<<(N0 * INC + 255) / 256, 256>>>(t, 256, INC, dis, N0, INC, xw);
    // h0 = relu(S @ Wd0 + bd0), tensor path with fused bias+relu
    run_xw_tc(xw, N0, INC, Wd0, HC, bd0, ACT_RELU, h0, 1, Xp, Wp);

    // pool0: A1 = [(A0+I)^2]_{perm0,perm0} = G@G^T (symmetric, upper tiles)
    run_scores_sort(h0, N0, 4096, p1, KP1, pm0, sc, pn);
    k_gather_rows<<<(2048 * 4096 + 255) / 256, 256>>>(bA0, 4096, pm0, KP1, 2048, G);
    cudaMemsetAsync(Augp, 0, (size_t)2048 * 2048 * sizeof(float), 0);
    run_nt_tri(2048, 4096, G, 4096, G, 4096, Augp, 2048, 2);
    k_gatherX<<<(KP1 * HC + 255) / 256, 256>>>(h0, HC, pm0, sc, KP1, u);
    k_crop_tobf16<<<(2048 * 2048 + 255) / 256, 256>>>(Augp, 2048, KP1, 2048, bA1);
    run_gcn_exact(bA1, KP1, 2048, u, HC, Wd1, HC, bd1, h1, ACT_RELU, 4, HC,
                  xw, t, dis, zpk, Xp, Wp);

    // pool1: A2 submatrix via G@G^T (symmetric)
    run_scores_sort(h1, KP1, 2048, p2, KP2, pm1, sc, pn);
    k_gather_rows<<<(1024 * 2048 + 255) / 256, 256>>>(bA1, 2048, pm1, KP2, 1024, G);
    cudaMemsetAsync(Augp, 0, (size_t)1024 * 1024 * sizeof(float), 0);
    run_nt_tri(1024, 2048, G, 2048, G, 2048, Augp, 1024, 8);
    k_gatherX<<<(KP2 * HC + 255) / 256, 256>>>(h1, HC, pm1, sc, KP2, u);
    k_crop_pack_X<<<(1024 * 1024 + 255) / 256, 256>>>(Augp, 1024, KP2, 1024, bX2);
    run_gcn_split(bX2, KP2, 1024, u, HC, Wd2, HC, bd2, h2, ACT_RELU, 2,
                  xw, t, dis, zpk, Xp, Wp);

    // pool2: A3 = P@P^T + P@Q^T (both symmetric, exact hi/lo split)
    run_scores_sort(h2, KP2, 1024, p3, KP3, pm2, sc, pn);
    k_gather_PQ_b<<<(512 * 2048 + 255) / 256, 256>>>(bX2, 1024, pm2, KP3, 512, G, Q);
    cudaMemsetAsync(Augp, 0, (size_t)512 * 512 * sizeof(float), 0);
    run_nt_tri(512, 2048, G, 2048, G, 2048, Augp, 512, 8);
    run_nt_tri(512, 2048, G, 2048, Q, 2048, Augp, 512, 8);
    k_gatherX<<<(KP3 * HC + 255) / 256, 256>>>(h2, HC, pm2, sc, KP3, u);
    k_crop_pack_X<<<(512 * 512 + 255) / 256, 256>>>(Augp, 512, KP3, 512, bX3);
    run_gcn_split(bX3, KP3, 512, u, HC, Wd3, HC, bd3, h3, ACT_RELU, 4,
                  xw, t, dis, zpk, Xp, Wp);

    // ---- up path ----
    cudaMemcpyAsync(u, h2, (size_t)KP2 * HC * sizeof(float), cudaMemcpyDeviceToDevice, 0);
    k_scatter_add<<<(KP3 * HC + 255) / 256, 256>>>(u, h3, pm2, KP3, HC);
    run_gcn_split(bX2, KP2, 1024, u, HC, Wu0, HC, bu0, hb, ACT_RELU, 2,
                  xw, t, dis, zpk, Xp, Wp);

    cudaMemcpyAsync(u, h1, (size_t)KP1 * HC * sizeof(float), cudaMemcpyDeviceToDevice, 0);
    k_scatter_add<<<(KP2 * HC + 255) / 256, 256>>>(u, hb, pm1, KP2, HC);
    run_gcn_exact(bA1, KP1, 2048, u, HC, Wu1, HC, bu1, hb, ACT_RELU, 4, HC,
                  xw, t, dis, zpk, Xp, Wp);

    cudaMemcpyAsync(u, h0, (size_t)N0 * HC * sizeof(float), cudaMemcpyDeviceToDevice, 0);
    k_scatter_add<<<(KP1 * HC + 255) / 256, 256>>>(u, hb, pm0, KP1, HC);
    // final layer: OC=64 -> Cpad=64 (W2=128), sgemm X@W (N=64), splitk=8
    run_gcn_exact(bA0, N0, 4096, u, HC, Wu2, OC, bu2, (float*)d_out, ACT_SIGM, 8, OC,
                  xw, t, dis, zpk, Xp, Wp);
}

// round 12
// speedup vs baseline: 1.7629x; 1.1316x over previous
#include <cuda_runtime.h>
#include <cuda_bf16.h>
#include <cstdint>
#include <math.h>

// ---------------- problem constants ----------------
#define N0   4096
#define INC  128
#define HC   512
#define OC   64
#define KP1  2000
#define KP2  1000
#define KP3  500
#define DEG  192     // CSR row stride (mean degree ~33; P(deg>192) ~ 0)

#define ACT_NONE 0
#define ACT_RELU 1
#define ACT_SIGM 2

// ---------------- scratch (device globals; allocation-free) ----------------
__device__ float g_Augp[(size_t)1024*1024];
__device__ float g_h0 [(size_t)N0*HC];
__device__ float g_h1 [(size_t)KP1*HC];
__device__ float g_h2 [(size_t)KP2*HC];
__device__ float g_h3 [(size_t)KP3*HC];
__device__ float g_hb [(size_t)KP1*HC];
__device__ float g_xw [(size_t)N0*HC];
__device__ float g_t  [(size_t)2048*1024];
__device__ float g_u  [(size_t)N0*HC];
__device__ float g_dis0[N0];
__device__ float g_dis1[2048];
__device__ float g_dis2[2048];
__device__ float g_dis3[1024];
__device__ float g_sc [N0];
__device__ float g_pn [1];
__device__ int   g_perm0[KP1];
__device__ int   g_perm1[KP2];
__device__ int   g_perm2[KP3];
__device__ int   g_inv[N0];
__device__ int   g_ccnt[N0];
__device__ int   g_ccol[(size_t)N0*DEG];
__device__ float g_cval[(size_t)N0*DEG];
__device__ __nv_bfloat16 g_bA0 [(size_t)4096*4096];  // bf16(A0+I)
__device__ __nv_bfloat16 g_bA1 [(size_t)2048*2048];  // bf16(A1+I)
__device__ __nv_bfloat16 g_bX2 [(size_t)1024*2048];  // (A2+I) split [hi|lo]
__device__ __nv_bfloat16 g_bX3 [(size_t)512*1024];   // (A3+I) split [hi|lo]
__device__ __nv_bfloat16 g_G  [(size_t)1024*2048];   // gathered operand / P
__device__ __nv_bfloat16 g_Q  [(size_t)512*2048];    // pool2 [lo|hi] operand
__device__ __nv_bfloat16 g_zpk[(size_t)2048*1024];   // packed z operand
__device__ __nv_bfloat16 g_Xpk[(size_t)4096*1536];   // packed feature [hi|lo|hi]
__device__ __nv_bfloat16 g_Wpk[(size_t)1536*512];    // packed weight [hi;hi;lo]

// ---------------- cp.async helpers ----------------
#define CPASYNC16(dst_u32, src_ptr) \
    asm volatile("cp.async.ca.shared.global [%0], [%1], 16;" :: "r"(dst_u32), "l"(src_ptr))
#define CP_COMMIT() asm volatile("cp.async.commit_group;")

#define NN_AS (128*40)
#define NN_BS (32*136)
#define NT_AS (128*40)
#define NT_BS (128*40)
#define NN_SMEM (4 * (NN_AS + NN_BS) * 2)
#define NT_SMEM (4 * (NT_AS + NT_BS) * 2)

// ---------------- NN GEMM: C(MxN) = A(MxK) @ B(KxN), bf16->fp32 ----------------
__global__ void __launch_bounds__(256) hgemm_nn(int M, int N, int K,
        const __nv_bfloat16* __restrict__ A, int lda,
        const __nv_bfloat16* __restrict__ B, int ldb,
        float* __restrict__ C, int ldc, int acc,
        const float* __restrict__ bias, int act) {
    extern __shared__ __nv_bfloat16 dsm[];
    __nv_bfloat16* Asm = dsm;
    __nv_bfloat16* Bsm = dsm + 4 * NN_AS;
    const int tid  = threadIdx.x;
    const int lane = tid & 31;
    const int warp = tid >> 5;
    const int wm = (warp >> 2) * 64;
    const int wn = (warp & 3) * 32;
    const int m0 = blockIdx.y * 128;
    const int n0 = blockIdx.x * 128;
    const int Kc = K / gridDim.z;
    const int k0 = blockIdx.z * Kc;

    const int ar = tid >> 1, ac = (tid & 1) * 16;
    const int br = tid >> 3, bc = (tid & 7) * 16;

    float c[4][4][4];
#pragma unroll
    for (int mt = 0; mt < 4; mt++)
#pragma unroll
        for (int nt = 0; nt < 4; nt++)
#pragma unroll
            for (int r = 0; r < 4; r++) c[mt][nt][r] = 0.f;

    const int ntile = Kc >> 5;

#define NN_LOAD(s, kk) { \
    unsigned da = (unsigned)__cvta_generic_to_shared(Asm + (s) * NN_AS + ar * 40 + ac); \
    const __nv_bfloat16* pa = A + (size_t)(m0 + ar) * lda + (kk) + ac; \
    CPASYNC16(da, pa); CPASYNC16(da + 16, pa + 8); \
    unsigned db = (unsigned)__cvta_generic_to_shared(Bsm + (s) * NN_BS + br * 136 + bc); \
    const __nv_bfloat16* pb = B + (size_t)((kk) + br) * ldb + n0 + bc; \
    CPASYNC16(db, pb); CPASYNC16(db + 16, pb + 8); }

    for (int p = 0; p < 3; ++p) {
        if (p < ntile) NN_LOAD(p, k0 + p * 32);
        CP_COMMIT();
    }

    for (int it = 0; it < ntile; ++it) {
        asm volatile("cp.async.wait_group 2;");
        __syncthreads();
        int pf = it + 3;
        if (pf < ntile) NN_LOAD(pf & 3, k0 + pf * 32);
        CP_COMMIT();

        const int s = it & 3;
        const __nv_bfloat16* As_s = Asm + s * NN_AS;
        const __nv_bfloat16* Bs_s = Bsm + s * NN_BS;
#pragma unroll
        for (int ks = 0; ks < 32; ks += 16) {
            uint32_t af[4][4];
#pragma unroll
            for (int mt = 0; mt < 4; mt++) {
                unsigned addr = (unsigned)__cvta_generic_to_shared(
                    As_s + (wm + mt * 16 + (lane & 15)) * 40 + ks + (lane >> 4) * 8);
                asm volatile("ldmatrix.sync.aligned.m8n8.x4.shared.b16 {%0,%1,%2,%3}, [%4];"
                    : "=r"(af[mt][0]), "=r"(af[mt][1]), "=r"(af[mt][2]), "=r"(af[mt][3])
                    : "r"(addr));
            }
            uint32_t bfr[4][2];
#pragma unroll
            for (int nt = 0; nt < 4; nt++) {
                unsigned addr = (unsigned)__cvta_generic_to_shared(
                    Bs_s + (ks + (lane & 15)) * 136 + wn + nt * 8);
                asm volatile("ldmatrix.sync.aligned.m8n8.x2.trans.shared.b16 {%0,%1}, [%2];"
                    : "=r"(bfr[nt][0]), "=r"(bfr[nt][1]) : "r"(addr));
            }
#pragma unroll
            for (int mt = 0; mt < 4; mt++)
#pragma unroll
                for (int nt = 0; nt < 4; nt++)
                    asm volatile(
                        "mma.sync.aligned.m16n8k16.row.col.f32.bf16.bf16.f32 "
                        "{%0,%1,%2,%3}, {%4,%5,%6,%7}, {%8,%9}, {%0,%1,%2,%3};"
                        : "+f"(c[mt][nt][0]), "+f"(c[mt][nt][1]),
                          "+f"(c[mt][nt][2]), "+f"(c[mt][nt][3])
                        : "r"(af[mt][0]), "r"(af[mt][1]), "r"(af[mt][2]), "r"(af[mt][3]),
                          "r"(bfr[nt][0]), "r"(bfr[nt][1]));
        }
        __syncthreads();
    }

    const int r0 = lane >> 2, c0 = (lane & 3) * 2;
#pragma unroll
    for (int mt = 0; mt < 4; mt++)
#pragma unroll
        for (int nt = 0; nt < 4; nt++) {
            int row = m0 + wm + mt * 16 + r0;
            int col = n0 + wn + nt * 8 + c0;
            float* p0 = C + (size_t)row * ldc + col;
            float* p1 = C + (size_t)(row + 8) * ldc + col;
            if (acc == 2) {
                atomicAdd(p0,     c[mt][nt][0]); atomicAdd(p0 + 1, c[mt][nt][1]);
                atomicAdd(p1,     c[mt][nt][2]); atomicAdd(p1 + 1, c[mt][nt][3]);
            } else {
                float v0 = c[mt][nt][0], v1 = c[mt][nt][1];
                float v2 = c[mt][nt][2], v3 = c[mt][nt][3];
                if (bias) { v0 += bias[col]; v1 += bias[col + 1];
                            v2 += bias[col]; v3 += bias[col + 1]; }
                if (act == ACT_RELU) {
                    v0 = fmaxf(v0, 0.f); v1 = fmaxf(v1, 0.f);
                    v2 = fmaxf(v2, 0.f); v3 = fmaxf(v3, 0.f);
                }
                p0[0] = v0; p0[1] = v1;
                p1[0] = v2; p1[1] = v3;
            }
        }
}

// ---------------- NT GEMM (tri-symmetric option) ----------------
__global__ void __launch_bounds__(256) hgemm_nt(int M, int N, int K,
        const __nv_bfloat16* __restrict__ A, int lda,
        const __nv_bfloat16* __restrict__ B, int ldb,
        float* __restrict__ C, int ldc, int acc, int tri) {
    extern __shared__ __nv_bfloat16 dsm[];
    __nv_bfloat16* Asm = dsm;
    __nv_bfloat16* Bsm = dsm + 4 * NT_AS;
    const int tid  = threadIdx.x;
    const int lane = tid & 31;
    const int warp = tid >> 5;
    const int wm = (warp >> 2) * 64;
    const int wn = (warp & 3) * 32;

    int m0, n0;
    if (tri) {
        int bid = blockIdx.x;
        int by = (int)((sqrtf(8.f * bid + 1.f) - 1.f) * 0.5f);
        while ((by + 1) * (by + 2) / 2 <= bid) by++;
        while (by * (by + 1) / 2 > bid) by--;
        int bx = bid - by * (by + 1) / 2;
        m0 = bx * 128;
        n0 = by * 128;
    } else {
        m0 = blockIdx.y * 128;
        n0 = blockIdx.x * 128;
    }
    const int Kc = K / gridDim.z;
    const int k0 = blockIdx.z * Kc;

    const int ar = tid >> 1, ac = (tid & 1) * 16;

    float c[4][4][4];
#pragma unroll
    for (int mt = 0; mt < 4; mt++)
#pragma unroll
        for (int nt = 0; nt < 4; nt++)
#pragma unroll
            for (int r = 0; r < 4; r++) c[mt][nt][r] = 0.f;

    const int ntile = Kc >> 5;

#define NT_LOAD(s, kk) { \
    unsigned da = (unsigned)__cvta_generic_to_shared(Asm + (s) * NT_AS + ar * 40 + ac); \
    const __nv_bfloat16* pa = A + (size_t)(m0 + ar) * lda + (kk) + ac; \
    CPASYNC16(da, pa); CPASYNC16(da + 16, pa + 8); \
    unsigned db = (unsigned)__cvta_generic_to_shared(Bsm + (s) * NT_BS + ar * 40 + ac); \
    const __nv_bfloat16* pb = B + (size_t)(n0 + ar) * ldb + (kk) + ac; \
    CPASYNC16(db, pb); CPASYNC16(db + 16, pb + 8); }

    for (int p = 0; p < 3; ++p) {
        if (p < ntile) NT_LOAD(p, k0 + p * 32);
        CP_COMMIT();
    }

    for (int it = 0; it < ntile; ++it) {
        asm volatile("cp.async.wait_group 2;");
        __syncthreads();
        int pf = it + 3;
        if (pf < ntile) NT_LOAD(pf & 3, k0 + pf * 32);
        CP_COMMIT();

        const int s = it & 3;
        const __nv_bfloat16* As_s = Asm + s * NT_AS;
        const __nv_bfloat16* Bs_s = Bsm + s * NT_BS;
#pragma unroll
        for (int ks = 0; ks < 32; ks += 16) {
            uint32_t af[4][4];
#pragma unroll
            for (int mt = 0; mt < 4; mt++) {
                unsigned addr = (unsigned)__cvta_generic_to_shared(
                    As_s + (wm + mt * 16 + (lane & 15)) * 40 + ks + (lane >> 4) * 8);
                asm volatile("ldmatrix.sync.aligned.m8n8.x4.shared.b16 {%0,%1,%2,%3}, [%4];"
                    : "=r"(af[mt][0]), "=r"(af[mt][1]), "=r"(af[mt][2]), "=r"(af[mt][3])
                    : "r"(addr));
            }
            uint32_t bfr[4][2];
#pragma unroll
            for (int nt = 0; nt < 4; nt++) {
                unsigned addr = (unsigned)__cvta_generic_to_shared(
                    Bs_s + (wn + nt * 8 + (lane & 7)) * 40 + ks + ((lane >> 3) & 1) * 8);
                asm volatile("ldmatrix.sync.aligned.m8n8.x2.shared.b16 {%0,%1}, [%2];"
                    : "=r"(bfr[nt][0]), "=r"(bfr[nt][1]) : "r"(addr));
            }
#pragma unroll
            for (int mt = 0; mt < 4; mt++)
#pragma unroll
                for (int nt = 0; nt < 4; nt++)
                    asm volatile(
                        "mma.sync.aligned.m16n8k16.row.col.f32.bf16.bf16.f32 "
                        "{%0,%1,%2,%3}, {%4,%5,%6,%7}, {%8,%9}, {%0,%1,%2,%3};"
                        : "+f"(c[mt][nt][0]), "+f"(c[mt][nt][1]),
                          "+f"(c[mt][nt][2]), "+f"(c[mt][nt][3])
                        : "r"(af[mt][0]), "r"(af[mt][1]), "r"(af[mt][2]), "r"(af[mt][3]),
                          "r"(bfr[nt][0]), "r"(bfr[nt][1]));
        }
        __syncthreads();
    }

    const int r0 = lane >> 2, c0 = (lane & 3) * 2;
#pragma unroll
    for (int mt = 0; mt < 4; mt++)
#pragma unroll
        for (int nt = 0; nt < 4; nt++) {
            int row = m0 + wm + mt * 16 + r0;
            int col = n0 + wn + nt * 8 + c0;
            float* p0 = C + (size_t)row * ldc + col;
            float* p1 = C + (size_t)(row + 8) * ldc + col;
            if (acc == 2) {
                atomicAdd(p0,     c[mt][nt][0]); atomicAdd(p0 + 1, c[mt][nt][1]);
                atomicAdd(p1,     c[mt][nt][2]); atomicAdd(p1 + 1, c[mt][nt][3]);
            } else {
                p0[0] = c[mt][nt][0]; p0[1] = c[mt][nt][1];
                p1[0] = c[mt][nt][2]; p1[1] = c[mt][nt][3];
            }
        }
}

// ---------------- SGEMM (fp32 SIMT) ----------------
__global__ void __launch_bounds__(256) sgemm(int M, int N, int K,
                                             const float* __restrict__ A,
                                             const float* __restrict__ B,
                                             const float* __restrict__ bias,
                                             float* __restrict__ C, int act) {
    __shared__ float As[8][128];
    __shared__ float Bs[8][128];
    const int tid  = threadIdx.x;
    const int tx   = tid & 15;
    const int ty   = tid >> 4;
    const int row0 = blockIdx.y * 128;
    const int col0 = blockIdx.x * 128;
    const int a_row = tid >> 1, a_col = (tid & 1) << 2;
    const int b_row = tid >> 5, b_col = (tid & 31) << 2;

    float acc[8][8];
#pragma unroll
    for (int i = 0; i < 8; i++)
#pragma unroll
        for (int j = 0; j < 8; j++) acc[i][j] = 0.f;

    for (int kk = 0; kk < K; kk += 8) {
        float4 av = make_float4(0.f, 0.f, 0.f, 0.f);
        {
            int gm = row0 + a_row, gk = kk + a_col;
            if (gm < M && gk < K)
                av = *reinterpret_cast<const float4*>(A + (size_t)gm * K + gk);
        }
        As[a_col + 0][a_row] = av.x;
        As[a_col + 1][a_row] = av.y;
        As[a_col + 2][a_row] = av.z;
        As[a_col + 3][a_row] = av.w;

        float4 bv = make_float4(0.f, 0.f, 0.f, 0.f);
        {
            int gk = kk + b_row, gn = col0 + b_col;
            if (gk < K && gn < N)
                bv = *reinterpret_cast<const float4*>(B + (size_t)gk * N + gn);
        }
        *reinterpret_cast<float4*>(&Bs[b_row][b_col]) = bv;
        __syncthreads();

#pragma unroll
        for (int k = 0; k < 8; k++) {
            float4 a0 = *reinterpret_cast<const float4*>(&As[k][ty * 8]);
            float4 a1 = *reinterpret_cast<const float4*>(&As[k][ty * 8 + 4]);
            float4 b0 = *reinterpret_cast<const float4*>(&Bs[k][tx * 8]);
            float4 b1 = *reinterpret_cast<const float4*>(&Bs[k][tx * 8 + 4]);
            float a[8] = {a0.x, a0.y, a0.z, a0.w, a1.x, a1.y, a1.z, a1.w};
            float b[8] = {b0.x, b0.y, b0.z, b0.w, b1.x, b1.y, b1.z, b1.w};
#pragma unroll
            for (int i = 0; i < 8; i++)
#pragma unroll
                for (int j = 0; j < 8; j++) acc[i][j] += a[i] * b[j];
        }
        __syncthreads();
    }

#pragma unroll
    for (int i = 0; i < 8; i++) {
        int gm = row0 + ty * 8 + i;
        if (gm >= M) continue;
        float* Cr = C + (size_t)gm * N;
#pragma unroll
        for (int j = 0; j < 8; j++) {
            int gn = col0 + tx * 8 + j;
            if (gn >= N) continue;
            float v = acc[i][j];
            if (bias) v += bias[gn];
            if (act == ACT_RELU) v = fmaxf(v, 0.f);
            else if (act == ACT_SIGM) v = 1.f / (1.f + expf(-v));
            Cr[gn] = v;
        }
    }
}

// ---------------- graph / elementwise kernels ----------------
__global__ void k_edges_b(const int* __restrict__ ei, int E, __nv_bfloat16* __restrict__ A) {
    int e = blockIdx.x * blockDim.x + threadIdx.x;
    if (e >= E) return;
    int s = ei[e], d = ei[E + e];
    __nv_bfloat16 one = __float2bfloat16(1.f);
    A[(size_t)s * N0 + d] = one;
    A[(size_t)d * N0 + s] = one;
}

__global__ void k_diag1_b(__nv_bfloat16* __restrict__ A, int n, int ld) {
    int i = blockIdx.x * blockDim.x + threadIdx.x;
    if (i < n) {
        size_t p = (size_t)i * ld + i;
        A[p] = __float2bfloat16(__bfloat162float(A[p]) + 1.f);
    }
}

// CSR build from dense bf16 matrix (one block per row)
__global__ void k_csr(const __nv_bfloat16* __restrict__ A, int n,
                      int* __restrict__ cnt, int* __restrict__ col,
                      float* __restrict__ val) {
    __shared__ int c;
    int row = blockIdx.x;
    if (threadIdx.x == 0) c = 0;
    __syncthreads();
    const __nv_bfloat16* Ar = A + (size_t)row * n;
    for (int j = threadIdx.x; j < n; j += 256) {
        float v = __bfloat162float(Ar[j]);
        if (v != 0.f) {
            int s = atomicAdd(&c, 1);
            col[(size_t)row * DEG + s] = j;
            val[(size_t)row * DEG + s] = v;
        }
    }
    __syncthreads();
    if (threadIdx.x == 0) cnt[row] = c;
}

__global__ void k_dis_b(const __nv_bfloat16* __restrict__ M, int ld, int w,
                        float* __restrict__ dis) {
    __shared__ float red[256];
    int row = blockIdx.x;
    const __nv_bfloat16* Mr = M + (size_t)row * ld;
    float s = 0.f;
    for (int j = threadIdx.x; j < w; j += 256) s += __bfloat162float(Mr[j]);
    red[threadIdx.x] = s;
    __syncthreads();
    for (int o = 128; o > 0; o >>= 1) {
        if (threadIdx.x < o) red[threadIdx.x] += red[threadIdx.x + o];
        __syncthreads();
    }
    if (threadIdx.x == 0) dis[row] = rsqrtf(red[0]);
}

// SpMM GCN: S[i][c] = dis[i] * sum_e val_ie * dis[col_ie] * X[col_ie][c]
// block = C threads (C <= 512), grid = n rows. act applied with bias (may be null).
__global__ void k_spmm(const int* __restrict__ cnt, const int* __restrict__ col,
                       const float* __restrict__ val,
                       const float* __restrict__ X, int C,
                       const float* __restrict__ dis,
                       const float* __restrict__ bias, int act,
                       float* __restrict__ S) {
    int row = blockIdx.x, c = threadIdx.x;
    if (c >= C) return;
    int m = cnt[row];
    const int* cr = col + (size_t)row * DEG;
    const float* vr = val + (size_t)row * DEG;
    float acc = 0.f;
    for (int e = 0; e < m; e++) {
        int j = cr[e];
        acc += vr[e] * dis[j] * X[(size_t)j * C + c];
    }
    float v = acc * dis[row];
    if (bias) v += bias[c];
    if (act == ACT_SIGM) v = 1.f / (1.f + expf(-v));
    S[(size_t)row * C + c] = v;
}

// SpGEMM pool0: bA1[r][:] = bf16 of [(A0+I)^2]_{perm,perm} row r, diag -> 1 (+I after zero)
__global__ void __launch_bounds__(256) k_spgemm(
        const int* __restrict__ cnt, const int* __restrict__ col,
        const float* __restrict__ val, const int* __restrict__ perm,
        const int* __restrict__ inv, int k, int np,
        __nv_bfloat16* __restrict__ bA1) {
    __shared__ float acc[2048];
    int r = blockIdx.x;
    for (int i = threadIdx.x; i < np; i += 256) acc[i] = 0.f;
    __syncthreads();
    if (r < k) {
        int row = perm[r];
        int m = cnt[row];
        const int* cr = col + (size_t)row * DEG;
        const float* vr = val + (size_t)row * DEG;
        for (int e1 = 0; e1 < m; e1++) {
            int j = cr[e1];
            float w1 = vr[e1];
            int mj = cnt[j];
            const int* cj = col + (size_t)j * DEG;
            const float* vj = val + (size_t)j * DEG;
            for (int e2 = threadIdx.x; e2 < mj; e2 += 256) {
                int cidx = inv[cj[e2]];
                if (cidx >= 0) atomicAdd(&acc[cidx], w1 * vj[e2]);
            }
        }
    }
    __syncthreads();
    __nv_bfloat16* out = bA1 + (size_t)r * np;
    for (int cidx = threadIdx.x; cidx < np; cidx += 256) {
        float v = (r < k) ? ((cidx == r) ? 1.f : acc[cidx]) : 0.f;
        out[cidx] = __float2bfloat16(v);
    }
}

__global__ void k_inv_init(int* __restrict__ inv, int n) {
    int i = blockIdx.x * blockDim.x + threadIdx.x;
    if (i < n) inv[i] = -1;
}
__global__ void k_inv_set(const int* __restrict__ perm, int k, int* __restrict__ inv) {
    int i = blockIdx.x * blockDim.x + threadIdx.x;
    if (i < k) inv[perm[i]] = i;
}

__global__ void k_scale_pack(const float* __restrict__ xw, const float* __restrict__ dis,
                             int n, int np, int C, int Cpad,
                             __nv_bfloat16* __restrict__ zpk) {
    int i = blockIdx.x * blockDim.x + threadIdx.x;
    int W = 2 * Cpad;
    if (i >= np * W) return;
    int r = i / W, cc = i - r * W;
    int colx = (cc < Cpad) ? cc : cc - Cpad;
    float v = (r < n && colx < C) ? dis[r] * xw[(size_t)r * C + colx] : 0.f;
    __nv_bfloat16 hi = __float2bfloat16(v);
    if (cc < Cpad) zpk[i] = hi;
    else           zpk[i] = __float2bfloat16(v - __bfloat162float(hi));
}

__global__ void k_scale_pack_stk(const float* __restrict__ xw, const float* __restrict__ dis,
                                 int n, int np, int C,
                                 __nv_bfloat16* __restrict__ Bp) {
    int i = blockIdx.x * blockDim.x + threadIdx.x;
    int W = 2 * C;
    if (i >= 2 * np * W) return;
    int r = i / W, cc = i - r * W;
    int rr = (r < np) ? r : r - np;
    int colx = (cc < C) ? cc : cc - C;
    float v = (rr < n) ? dis[rr] * xw[(size_t)rr * C + colx] : 0.f;
    __nv_bfloat16 hi = __float2bfloat16(v);
    __nv_bfloat16 lo = __float2bfloat16(v - __bfloat162float(hi));
    bool wantHi = ((r < np) == (cc < C));
    Bp[i] = wantHi ? hi : lo;
}

__global__ void k_packX3(const float* __restrict__ X, int np, int C,
                         __nv_bfloat16* __restrict__ Xp) {
    int i = blockIdx.x * blockDim.x + threadIdx.x;
    int W = 3 * C;
    if (i >= np * W) return;
    int r = i / W, cc = i - r * W;
    int colx = cc; if (colx >= C) colx -= C; if (colx >= C) colx -= C;
    float v = X[(size_t)r * C + colx];
    __nv_bfloat16 hi = __float2bfloat16(v);
    bool isLo = (cc >= C && cc < 2 * C);
    Xp[i] = isLo ? __float2bfloat16(v - __bfloat162float(hi)) : hi;
}

__global__ void k_packW3(const float* __restrict__ W, int K, int N,
                         __nv_bfloat16* __restrict__ Wp) {
    int i = blockIdx.x * blockDim.x + threadIdx.x;
    if (i >= 3 * K * N) return;
    int r = i / N, cc = i - r * N;
    int rr = r; if (rr >= K) rr -= K; if (rr >= K) rr -= K;
    float v = W[(size_t)rr * N + cc];
    __nv_bfloat16 hi = __float2bfloat16(v);
    Wp[i] = (r < 2 * K) ? hi : __float2bfloat16(v - __bfloat162float(hi));
}

__global__ void k_epilogue_sum2(const float* __restrict__ t, int ldt, int half,
                                const float* __restrict__ dis, const float* __restrict__ b,
                                int n, int C, float* __restrict__ out, int act) {
    int i = blockIdx.x * blockDim.x + threadIdx.x;
    if (i >= n * C) return;
    int r = i / C, cc = i - r * C;
    float v = dis[r] * (t[(size_t)r * ldt + cc] + t[(size_t)r * ldt + cc + half]) + b[cc];
    if (act == ACT_RELU) v = fmaxf(v, 0.f);
    else if (act == ACT_SIGM) v = 1.f / (1.f + expf(-v));
    out[i] = v;
}

__global__ void k_crop_pack_X(const float* __restrict__ Augp, int kpad, int k, int np,
                              __nv_bfloat16* __restrict__ X) {
    int i = blockIdx.x * blockDim.x + threadIdx.x;
    if (i >= np * np) return;
    int r = i / np, cc = i - r * np;
    float v = 0.f;
    if (r < k && cc < k) {
        if (r == cc) v = 1.f;
        else {
            int rr = (r < cc) ? r : cc;
            int c2 = (r < cc) ? cc : r;
            v = Augp[(size_t)rr * kpad + c2];
        }
    }
    __nv_bfloat16 hi = __float2bfloat16(v);
    __nv_bfloat16 lo = __float2bfloat16(v - __bfloat162float(hi));
    X[(size_t)r * (2 * np) + cc]      = hi;
    X[(size_t)r * (2 * np) + np + cc] = lo;
}

__global__ void k_gather_rows(const __nv_bfloat16* __restrict__ bApI, int np,
                              const int* __restrict__ perm, int k, int kpad,
                              __nv_bfloat16* __restrict__ G) {
    int i = blockIdx.x * blockDim.x + threadIdx.x;
    if (i >= kpad * np) return;
    int r = i / np, j = i - r * np;
    G[i] = (r < k) ? bApI[(size_t)perm[r] * np + j] : __float2bfloat16(0.f);
}

__global__ void k_gather_PQ_b(const __nv_bfloat16* __restrict__ X2, int np,
                              const int* __restrict__ perm, int k, int kpad,
                              __nv_bfloat16* __restrict__ P,
                              __nv_bfloat16* __restrict__ Q) {
    int i = blockIdx.x * blockDim.x + threadIdx.x;
    int W = 2 * np;
    if (i >= kpad * W) return;
    int r = i / W, j = i - r * W;
    __nv_bfloat16 v = (r < k) ? X2[(size_t)perm[r] * W + j] : __float2bfloat16(0.f);
    P[i] = v;
    int js = (j < np) ? j + np : j - np;
    Q[(size_t)r * W + js] = v;
}

__global__ void k_pnorm(const float* __restrict__ p, int n, float* __restrict__ out) {
    __shared__ float red[256];
    float s = 0.f;
    for (int i = threadIdx.x; i < n; i += 256) s += p[i] * p[i];
    red[threadIdx.x] = s;
    __syncthreads();
    for (int o = 128; o > 0; o >>= 1) {
        if (threadIdx.x < o) red[threadIdx.x] += red[threadIdx.x + o];
        __syncthreads();
    }
    if (threadIdx.x == 0) out[0] = sqrtf(red[0]);
}

__global__ void k_scores(const float* __restrict__ h, int n, int C,
                         const float* __restrict__ p, const float* __restrict__ pn,
                         float* __restrict__ score) {
    int row = blockIdx.x * 8 + (threadIdx.x >> 5);
    int lane = threadIdx.x & 31;
    if (row >= n) return;
    const float* hr = h + (size_t)row * C;
    float s = 0.f;
    for (int cc = lane; cc < C; cc += 32) s += hr[cc] * p[cc];
    for (int o = 16; o > 0; o >>= 1) s += __shfl_xor_sync(0xffffffffu, s, o);
    if (lane == 0) score[row] = tanhf(s / pn[0]);
}

__global__ void __launch_bounds__(1024) k_sort_topk(const float* __restrict__ score,
                                                    int n, int npad, int k,
                                                    int* __restrict__ perm) {
    __shared__ float skey[4096];
    __shared__ int   sidx[4096];
    for (int i = threadIdx.x; i < npad; i += blockDim.x) {
        skey[i] = (i < n) ? score[i] : -INFINITY;
        sidx[i] = i;
    }
    __syncthreads();
    for (int kk = 2; kk <= npad; kk <<= 1) {
        for (int j = kk >> 1; j > 0; j >>= 1) {
            for (int i = threadIdx.x; i < npad; i += blockDim.x) {
                int ixj = i ^ j;
                if (ixj > i) {
                    float a = skey[i], b = skey[ixj];
                    bool sw = ((i & kk) == 0) ? (a < b) : (a > b);
                    if (sw) {
                        skey[i] = b; skey[ixj] = a;
                        int t = sidx[i]; sidx[i] = sidx[ixj]; sidx[ixj] = t;
                    }
                }
            }
            __syncthreads();
        }
    }
    for (int i = threadIdx.x; i < k; i += blockDim.x) perm[i] = sidx[i];
}

__global__ void k_gatherX(const float* __restrict__ h, int C,
                          const int* __restrict__ perm, const float* __restrict__ score,
                          int k, float* __restrict__ out) {
    int i = blockIdx.x * blockDim.x + threadIdx.x;
    if (i >= k * C) return;
    int r = i / C, cc = i - r * C;
    int pr = perm[r];
    out[i] = h[(size_t)pr * C + cc] * score[pr];
}

__global__ void k_scatter_add(float* __restrict__ u, const float* __restrict__ h,
                              const int* __restrict__ perm, int k, int C) {
    int i = blockIdx.x * blockDim.x + threadIdx.x;
    if (i >= k * C) return;
    int r = i / C, cc = i - r * C;
    u[(size_t)perm[r] * C + cc] += h[i];
}

// ---------------- host orchestration ----------------
static void run_sgemm(int M, int N, int K, const float* A, const float* B,
                      const float* bias, float* C, int act) {
    dim3 g((N + 127) / 128, (M + 127) / 128);
    sgemm<<<g, 256>>>(M, N, K, A, B, bias, C, act);
}
static void run_nn(int M, int N, int K, const __nv_bfloat16* A, int lda,
                   const __nv_bfloat16* B, int ldb, float* C, int ldc, int acc, int splitk,
                   const float* bias, int act) {
    cudaFuncSetAttribute(hgemm_nn, cudaFuncAttributeMaxDynamicSharedMemorySize, NN_SMEM);
    dim3 g(N / 128, M / 128, splitk);
    hgemm_nn<<<g, 256, NN_SMEM>>>(M, N, K, A, lda, B, ldb, C, ldc, acc, bias, act);
}
static void run_nt_tri(int M, int K, const __nv_bfloat16* A, int lda,
                       const __nv_bfloat16* B, int ldb, float* C, int ldc, int splitk) {
    cudaFuncSetAttribute(hgemm_nt, cudaFuncAttributeMaxDynamicSharedMemorySize, NT_SMEM);
    int T = M / 128;
    dim3 g(T * (T + 1) / 2, 1, splitk);
    hgemm_nt<<<g, 256, NT_SMEM>>>(M, M, K, A, lda, B, ldb, C, ldc, 2, 1);
}

static void run_xw_tc(const float* X, int np, int C, const float* W, int N,
                      const float* bias, int act, float* out, int splitk,
                      __nv_bfloat16* Xp, __nv_bfloat16* Wp) {
    int totX = np * 3 * C;
    k_packX3<<<(totX + 255) / 256, 256>>>(X, np, C, Xp);
    int totW = 3 * C * N;
    k_packW3<<<(totW + 255) / 256, 256>>>(W, C, N, Wp);
    if (splitk > 1) {
        cudaMemsetAsync(out, 0, (size_t)np * N * sizeof(float), 0);
        run_nn(np, N, 3 * C, Xp, 3 * C, Wp, N, out, N, 2, splitk, nullptr, ACT_NONE);
    } else {
        run_nn(np, N, 3 * C, Xp, 3 * C, Wp, N, out, N, 0, 1, bias, act);
    }
}

// exact-bf16 adjacency GCN (cached dis)
static void run_gcn_exact(const __nv_bfloat16* bApI, int n, int np,
                          const float* X, int inC, const float* W, int outC, const float* b,
                          float* out, int act, int splitk,
                          float* xw, float* t, const float* dis, __nv_bfloat16* zpk,
                          __nv_bfloat16* Xp, __nv_bfloat16* Wp) {
    run_xw_tc(X, np, inC, W, outC, nullptr, ACT_NONE, xw, 1, Xp, Wp);
    int Cpad = outC;
    int W2 = 2 * Cpad;
    int tot = np * W2;
    k_scale_pack<<<(tot + 255) / 256, 256>>>(xw, dis, n, np, outC, Cpad, zpk);
    cudaMemsetAsync(t, 0, (size_t)np * W2 * sizeof(float), 0);
    run_nn(np, W2, np, bApI, np, zpk, W2, t, W2, 2, splitk, nullptr, ACT_NONE);
    int nc = n * outC;
    k_epilogue_sum2<<<(nc + 255) / 256, 256>>>(t, W2, Cpad, dis, b, n, outC, out, act);
}

static void run_gcn_split(const __nv_bfloat16* X2, int n, int np,
                          const float* X, int inC, const float* W, int outC, const float* b,
                          float* out, int act, int splitk,
                          float* xw, float* t, const float* dis, __nv_bfloat16* Bp,
                          __nv_bfloat16* Xp, __nv_bfloat16* Wp) {
    run_xw_tc(X, np, inC, W, outC, nullptr, ACT_NONE, xw, (np <= 512) ? 2 : 1, Xp, Wp);
    int W2 = 2 * outC;
    int tot = 2 * np * W2;
    k_scale_pack_stk<<<(tot + 255) / 256, 256>>>(xw, dis, n, np, outC, Bp);
    cudaMemsetAsync(t, 0, (size_t)np * W2 * sizeof(float), 0);
    run_nn(np, W2, 2 * np, X2, 2 * np, Bp, W2, t, W2, 2, splitk, nullptr, ACT_NONE);
    int nc = n * outC;
    k_epilogue_sum2<<<(nc + 255) / 256, 256>>>(t, W2, outC, dis, b, n, outC, out, act);
}

static void run_scores_sort(const float* h, int n, int npad, const float* p, int k,
                            int* perm, float* score, float* pn) {
    k_pnorm<<<1, 256>>>(p, HC, pn);
    k_scores<<<(n + 7) / 8, 256>>>(h, n, HC, p, pn, score);
    k_sort_topk<<<1, 1024>>>(score, n, npad, k, perm);
}

extern "C" void kernel_launch(void* const* d_in, const int* in_sizes, int n_in,
                              void* d_out, int out_size) {
    const float* x   = (const float*)d_in[0];
    const int*   ei  = (const int*)  d_in[1];
    const float* Wd0 = (const float*)d_in[2];  const float* bd0 = (const float*)d_in[3];
    const float* Wd1 = (const float*)d_in[4];  const float* bd1 = (const float*)d_in[5];
    const float* Wd2 = (const float*)d_in[6];  const float* bd2 = (const float*)d_in[7];
    const float* Wd3 = (const float*)d_in[8];  const float* bd3 = (const float*)d_in[9];
    const float* p1  = (const float*)d_in[10];
    const float* p2  = (const float*)d_in[11];
    const float* p3  = (const float*)d_in[12];
    const float* Wu0 = (const float*)d_in[13]; const float* bu0 = (const float*)d_in[14];
    const float* Wu1 = (const float*)d_in[15]; const float* bu1 = (const float*)d_in[16];
    const float* Wu2 = (const float*)d_in[17]; const float* bu2 = (const float*)d_in[18];
    const int E = in_sizes[1] / 2;

    float *Augp, *h0, *h1, *h2, *h3, *hb, *xw, *t, *u, *sc, *pn;
    float *dis0, *dis1, *dis2, *dis3;
    int *pm0, *pm1, *pm2, *inv, *ccnt, *ccol;
    float *cval;
    __nv_bfloat16 *bA0, *bA1, *bX2, *bX3, *G, *Q, *zpk, *Xp, *Wp;
    cudaGetSymbolAddress((void**)&Augp, g_Augp);
    cudaGetSymbolAddress((void**)&h0,  g_h0);
    cudaGetSymbolAddress((void**)&h1,  g_h1);
    cudaGetSymbolAddress((void**)&h2,  g_h2);
    cudaGetSymbolAddress((void**)&h3,  g_h3);
    cudaGetSymbolAddress((void**)&hb,  g_hb);
    cudaGetSymbolAddress((void**)&xw,  g_xw);
    cudaGetSymbolAddress((void**)&t,   g_t);
    cudaGetSymbolAddress((void**)&u,   g_u);
    cudaGetSymbolAddress((void**)&dis0, g_dis0);
    cudaGetSymbolAddress((void**)&dis1, g_dis1);
    cudaGetSymbolAddress((void**)&dis2, g_dis2);
    cudaGetSymbolAddress((void**)&dis3, g_dis3);
    cudaGetSymbolAddress((void**)&sc,  g_sc);
    cudaGetSymbolAddress((void**)&pn,  g_pn);
    cudaGetSymbolAddress((void**)&pm0, g_perm0);
    cudaGetSymbolAddress((void**)&pm1, g_perm1);
    cudaGetSymbolAddress((void**)&pm2, g_perm2);
    cudaGetSymbolAddress((void**)&inv, g_inv);
    cudaGetSymbolAddress((void**)&ccnt, g_ccnt);
    cudaGetSymbolAddress((void**)&ccol, g_ccol);
    cudaGetSymbolAddress((void**)&cval, g_cval);
    cudaGetSymbolAddress((void**)&bA0, g_bA0);
    cudaGetSymbolAddress((void**)&bA1, g_bA1);
    cudaGetSymbolAddress((void**)&bX2, g_bX2);
    cudaGetSymbolAddress((void**)&bX3, g_bX3);
    cudaGetSymbolAddress((void**)&G,   g_G);
    cudaGetSymbolAddress((void**)&Q,   g_Q);
    cudaGetSymbolAddress((void**)&zpk, g_zpk);
    cudaGetSymbolAddress((void**)&Xp,  g_Xpk);
    cudaGetSymbolAddress((void**)&Wp,  g_Wpk);

    // ---- build bf16(A0+I) + CSR + dis0 ----
    cudaMemsetAsync(bA0, 0, (size_t)N0 * N0 * sizeof(__nv_bfloat16), 0);
    k_edges_b<<<(E + 255) / 256, 256>>>(ei, E, bA0);
    k_diag1_b<<<(N0 + 255) / 256, 256>>>(bA0, N0, N0);
    k_csr<<<N0, 256>>>(bA0, N0, ccnt, ccol, cval);
    k_dis_b<<<N0, 256>>>(bA0, N0, N0, dis0);

    // ---- down level 0: sparse, exact fp32: S = D(A+I)D x; h0 = relu(S@Wd0+bd0) ----
    k_spmm<<<N0, INC>>>(ccnt, ccol, cval, x, INC, dis0, nullptr, ACT_NONE, xw);
    run_xw_tc(xw, N0, INC, Wd0, HC, bd0, ACT_RELU, h0, 1, Xp, Wp);

    // pool0: bA1 = crop([(A0+I)^2]) + I via SpGEMM (exact small ints)
    run_scores_sort(h0, N0, 4096, p1, KP1, pm0, sc, pn);
    k_inv_init<<<(N0 + 255) / 256, 256>>>(inv, N0);
    k_inv_set<<<(KP1 + 255) / 256, 256>>>(pm0, KP1, inv);
    k_spgemm<<<2048, 256>>>(ccnt, ccol, cval, pm0, inv, KP1, 2048, bA1);
    k_gatherX<<<(KP1 * HC + 255) / 256, 256>>>(h0, HC, pm0, sc, KP1, u);
    k_dis_b<<<KP1, 256>>>(bA1, 2048, 2048, dis1);
    run_gcn_exact(bA1, KP1, 2048, u, HC, Wd1, HC, bd1, h1, ACT_RELU, 4,
                  xw, t, dis1, zpk, Xp, Wp);

    // pool1: A2 submatrix via G@G^T (symmetric dense bf16, exact small ints)
    run_scores_sort(h1, KP1, 2048, p2, KP2, pm1, sc, pn);
    k_gather_rows<<<(1024 * 2048 + 255) / 256, 256>>>(bA1, 2048, pm1, KP2, 1024, G);
    cudaMemsetAsync(Augp, 0, (size_t)1024 * 1024 * sizeof(float), 0);
    run_nt_tri(1024, 2048, G, 2048, G, 2048, Augp, 1024, 8);
    k_gatherX<<<(KP2 * HC + 255) / 256, 256>>>(h1, HC, pm1, sc, KP2, u);
    k_crop_pack_X<<<(1024 * 1024 + 255) / 256, 256>>>(Augp, 1024, KP2, 1024, bX2);
    k_dis_b<<<KP2, 256>>>(bX2, 2048, 2048, dis2);
    run_gcn_split(bX2, KP2, 1024, u, HC, Wd2, HC, bd2, h2, ACT_RELU, 2,
                  xw, t, dis2, zpk, Xp, Wp);

    // pool2: A3 = P@P^T + P@Q^T (both symmetric, exact hi/lo split)
    run_scores_sort(h2, KP2, 1024, p3, KP3, pm2, sc, pn);
    k_gather_PQ_b<<<(512 * 2048 + 255) / 256, 256>>>(bX2, 1024, pm2, KP3, 512, G, Q);
    cudaMemsetAsync(Augp, 0, (size_t)512 * 512 * sizeof(float), 0);
    run_nt_tri(512, 2048, G, 2048, G, 2048, Augp, 512, 8);
    run_nt_tri(512, 2048, G, 2048, Q, 2048, Augp, 512, 8);
    k_gatherX<<<(KP3 * HC + 255) / 256, 256>>>(h2, HC, pm2, sc, KP3, u);
    k_crop_pack_X<<<(512 * 512 + 255) / 256, 256>>>(Augp, 512, KP3, 512, bX3);
    k_dis_b<<<KP3, 256>>>(bX3, 1024, 1024, dis3);
    run_gcn_split(bX3, KP3, 512, u, HC, Wd3, HC, bd3, h3, ACT_RELU, 4,
                  xw, t, dis3, zpk, Xp, Wp);

    // ---- up path ----
    cudaMemcpyAsync(u, h2, (size_t)KP2 * HC * sizeof(float), cudaMemcpyDeviceToDevice, 0);
    k_scatter_add<<<(KP3 * HC + 255) / 256, 256>>>(u, h3, pm2, KP3, HC);
    run_gcn_split(bX2, KP2, 1024, u, HC, Wu0, HC, bu0, hb, ACT_RELU, 2,
                  xw, t, dis2, zpk, Xp, Wp);

    cudaMemcpyAsync(u, h1, (size_t)KP1 * HC * sizeof(float), cudaMemcpyDeviceToDevice, 0);
    k_scatter_add<<<(KP2 * HC + 255) / 256, 256>>>(u, hb, pm1, KP2, HC);
    run_gcn_exact(bA1, KP1, 2048, u, HC, Wu1, HC, bu1, hb, ACT_RELU, 4,
                  xw, t, dis1, zpk, Xp, Wp);

    cudaMemcpyAsync(u, h0, (size_t)N0 * HC * sizeof(float), cudaMemcpyDeviceToDevice, 0);
    k_scatter_add<<<(KP1 * HC + 255) / 256, 256>>>(u, hb, pm0, KP1, HC);
    // final level-0 GCN: xw = u@Wu2 (N=64 sgemm), then sparse SpMM + sigmoid (exact)
    run_sgemm(N0, OC, HC, u, Wu2, nullptr, xw, ACT_NONE);
    k_spmm<<<N0, OC>>>(ccnt, ccol, cval, xw, OC, dis0, bu2, ACT_SIGM, (float*)d_out);
}

// round 13
// speedup vs baseline: 1.9278x; 1.0935x over previous
#include <cuda_runtime.h>
#include <cuda_bf16.h>
#include <cstdint>
#include <math.h>

// ---------------- problem constants ----------------
#define N0   4096
#define INC  128
#define HC   512
#define OC   64
#define KP1  2000
#define KP2  1000
#define KP3  500
#define DEG  192     // CSR row stride (mean degree ~33)

#define ACT_NONE 0
#define ACT_RELU 1
#define ACT_SIGM 2

// ---------------- scratch (device globals; allocation-free) ----------------
__device__ float g_Augp[(size_t)1024*1024];
__device__ float g_h0 [(size_t)N0*HC];
__device__ float g_h1 [(size_t)KP1*HC];
__device__ float g_h2 [(size_t)KP2*HC];
__device__ float g_h3 [(size_t)KP3*HC];
__device__ float g_hb [(size_t)KP1*HC];
__device__ float g_xw [(size_t)N0*HC];
__device__ float g_t  [(size_t)2048*1024];
__device__ float g_u  [(size_t)N0*HC];
__device__ float g_dis0[N0];
__device__ float g_dis1[2048];
__device__ float g_dis2[2048];
__device__ float g_dis3[1024];
__device__ float g_sc [N0];
__device__ float g_pn [1];
__device__ int   g_perm0[KP1];
__device__ int   g_perm1[KP2];
__device__ int   g_perm2[KP3];
__device__ int   g_inv[N0];
__device__ int   g_ccnt[N0];
__device__ int   g_ccol[(size_t)N0*DEG];
__device__ float g_cval[(size_t)N0*DEG];
__device__ unsigned char g_m0[(size_t)N0*N0];        // 16 MB adjacency mask
__device__ __nv_bfloat16 g_bA1 [(size_t)2048*2048];  // bf16(A1+I)
__device__ __nv_bfloat16 g_bX2 [(size_t)1024*2048];  // (A2+I) split [hi|lo]
__device__ __nv_bfloat16 g_bX3 [(size_t)512*1024];   // (A3+I) split [hi|lo]
__device__ __nv_bfloat16 g_G  [(size_t)1024*2048];   // gathered operand / P
__device__ __nv_bfloat16 g_Q  [(size_t)512*2048];    // pool2 [lo|hi] operand
__device__ __nv_bfloat16 g_zpk[(size_t)2048*1024];   // packed z operand
__device__ __nv_bfloat16 g_Xpk[(size_t)4096*1536];   // packed feature [hi|lo|hi]
__device__ __nv_bfloat16 g_Wpk[(size_t)1536*512];    // packed weight [hi;hi;lo]

// ---------------- cp.async helpers ----------------
#define CPASYNC16(dst_u32, src_ptr) \
    asm volatile("cp.async.ca.shared.global [%0], [%1], 16;" :: "r"(dst_u32), "l"(src_ptr))
#define CP_COMMIT() asm volatile("cp.async.commit_group;")

#define NN_AS (128*40)
#define NN_BS (32*136)
#define NT_AS (128*40)
#define NT_BS (128*40)
#define NN_SMEM (4 * (NN_AS + NN_BS) * 2)
#define NT_SMEM (4 * (NT_AS + NT_BS) * 2)

// ---------------- NN GEMM: C(MxN) = A(MxK) @ B(KxN), bf16->fp32 ----------------
__global__ void __launch_bounds__(256) hgemm_nn(int M, int N, int K,
        const __nv_bfloat16* __restrict__ A, int lda,
        const __nv_bfloat16* __restrict__ B, int ldb,
        float* __restrict__ C, int ldc, int acc,
        const float* __restrict__ bias, int act) {
    extern __shared__ __nv_bfloat16 dsm[];
    __nv_bfloat16* Asm = dsm;
    __nv_bfloat16* Bsm = dsm + 4 * NN_AS;
    const int tid  = threadIdx.x;
    const int lane = tid & 31;
    const int warp = tid >> 5;
    const int wm = (warp >> 2) * 64;
    const int wn = (warp & 3) * 32;
    const int m0 = blockIdx.y * 128;
    const int n0 = blockIdx.x * 128;
    const int Kc = K / gridDim.z;
    const int k0 = blockIdx.z * Kc;

    const int ar = tid >> 1, ac = (tid & 1) * 16;
    const int br = tid >> 3, bc = (tid & 7) * 16;

    float c[4][4][4];
#pragma unroll
    for (int mt = 0; mt < 4; mt++)
#pragma unroll
        for (int nt = 0; nt < 4; nt++)
#pragma unroll
            for (int r = 0; r < 4; r++) c[mt][nt][r] = 0.f;

    const int ntile = Kc >> 5;

#define NN_LOAD(s, kk) { \
    unsigned da = (unsigned)__cvta_generic_to_shared(Asm + (s) * NN_AS + ar * 40 + ac); \
    const __nv_bfloat16* pa = A + (size_t)(m0 + ar) * lda + (kk) + ac; \
    CPASYNC16(da, pa); CPASYNC16(da + 16, pa + 8); \
    unsigned db = (unsigned)__cvta_generic_to_shared(Bsm + (s) * NN_BS + br * 136 + bc); \
    const __nv_bfloat16* pb = B + (size_t)((kk) + br) * ldb + n0 + bc; \
    CPASYNC16(db, pb); CPASYNC16(db + 16, pb + 8); }

    for (int p = 0; p < 3; ++p) {
        if (p < ntile) NN_LOAD(p, k0 + p * 32);
        CP_COMMIT();
    }

    for (int it = 0; it < ntile; ++it) {
        asm volatile("cp.async.wait_group 2;");
        __syncthreads();
        int pf = it + 3;
        if (pf < ntile) NN_LOAD(pf & 3, k0 + pf * 32);
        CP_COMMIT();

        const int s = it & 3;
        const __nv_bfloat16* As_s = Asm + s * NN_AS;
        const __nv_bfloat16* Bs_s = Bsm + s * NN_BS;
#pragma unroll
        for (int ks = 0; ks < 32; ks += 16) {
            uint32_t af[4][4];
#pragma unroll
            for (int mt = 0; mt < 4; mt++) {
                unsigned addr = (unsigned)__cvta_generic_to_shared(
                    As_s + (wm + mt * 16 + (lane & 15)) * 40 + ks + (lane >> 4) * 8);
                asm volatile("ldmatrix.sync.aligned.m8n8.x4.shared.b16 {%0,%1,%2,%3}, [%4];"
                    : "=r"(af[mt][0]), "=r"(af[mt][1]), "=r"(af[mt][2]), "=r"(af[mt][3])
                    : "r"(addr));
            }
            uint32_t bfr[4][2];
#pragma unroll
            for (int nt = 0; nt < 4; nt++) {
                unsigned addr = (unsigned)__cvta_generic_to_shared(
                    Bs_s + (ks + (lane & 15)) * 136 + wn + nt * 8);
                asm volatile("ldmatrix.sync.aligned.m8n8.x2.trans.shared.b16 {%0,%1}, [%2];"
                    : "=r"(bfr[nt][0]), "=r"(bfr[nt][1]) : "r"(addr));
            }
#pragma unroll
            for (int mt = 0; mt < 4; mt++)
#pragma unroll
                for (int nt = 0; nt < 4; nt++)
                    asm volatile(
                        "mma.sync.aligned.m16n8k16.row.col.f32.bf16.bf16.f32 "
                        "{%0,%1,%2,%3}, {%4,%5,%6,%7}, {%8,%9}, {%0,%1,%2,%3};"
                        : "+f"(c[mt][nt][0]), "+f"(c[mt][nt][1]),
                          "+f"(c[mt][nt][2]), "+f"(c[mt][nt][3])
                        : "r"(af[mt][0]), "r"(af[mt][1]), "r"(af[mt][2]), "r"(af[mt][3]),
                          "r"(bfr[nt][0]), "r"(bfr[nt][1]));
        }
        __syncthreads();
    }

    const int r0 = lane >> 2, c0 = (lane & 3) * 2;
#pragma unroll
    for (int mt = 0; mt < 4; mt++)
#pragma unroll
        for (int nt = 0; nt < 4; nt++) {
            int row = m0 + wm + mt * 16 + r0;
            int col = n0 + wn + nt * 8 + c0;
            float* p0 = C + (size_t)row * ldc + col;
            float* p1 = C + (size_t)(row + 8) * ldc + col;
            if (acc == 2) {
                atomicAdd(p0,     c[mt][nt][0]); atomicAdd(p0 + 1, c[mt][nt][1]);
                atomicAdd(p1,     c[mt][nt][2]); atomicAdd(p1 + 1, c[mt][nt][3]);
            } else {
                float v0 = c[mt][nt][0], v1 = c[mt][nt][1];
                float v2 = c[mt][nt][2], v3 = c[mt][nt][3];
                if (bias) { v0 += bias[col]; v1 += bias[col + 1];
                            v2 += bias[col]; v3 += bias[col + 1]; }
                if (act == ACT_RELU) {
                    v0 = fmaxf(v0, 0.f); v1 = fmaxf(v1, 0.f);
                    v2 = fmaxf(v2, 0.f); v3 = fmaxf(v3, 0.f);
                }
                p0[0] = v0; p0[1] = v1;
                p1[0] = v2; p1[1] = v3;
            }
        }
}

// ---------------- NT GEMM (tri-symmetric option) ----------------
__global__ void __launch_bounds__(256) hgemm_nt(int M, int N, int K,
        const __nv_bfloat16* __restrict__ A, int lda,
        const __nv_bfloat16* __restrict__ B, int ldb,
        float* __restrict__ C, int ldc, int acc, int tri) {
    extern __shared__ __nv_bfloat16 dsm[];
    __nv_bfloat16* Asm = dsm;
    __nv_bfloat16* Bsm = dsm + 4 * NT_AS;
    const int tid  = threadIdx.x;
    const int lane = tid & 31;
    const int warp = tid >> 5;
    const int wm = (warp >> 2) * 64;
    const int wn = (warp & 3) * 32;

    int m0, n0;
    if (tri) {
        int bid = blockIdx.x;
        int by = (int)((sqrtf(8.f * bid + 1.f) - 1.f) * 0.5f);
        while ((by + 1) * (by + 2) / 2 <= bid) by++;
        while (by * (by + 1) / 2 > bid) by--;
        int bx = bid - by * (by + 1) / 2;
        m0 = bx * 128;
        n0 = by * 128;
    } else {
        m0 = blockIdx.y * 128;
        n0 = blockIdx.x * 128;
    }
    const int Kc = K / gridDim.z;
    const int k0 = blockIdx.z * Kc;

    const int ar = tid >> 1, ac = (tid & 1) * 16;

    float c[4][4][4];
#pragma unroll
    for (int mt = 0; mt < 4; mt++)
#pragma unroll
        for (int nt = 0; nt < 4; nt++)
#pragma unroll
            for (int r = 0; r < 4; r++) c[mt][nt][r] = 0.f;

    const int ntile = Kc >> 5;

#define NT_LOAD(s, kk) { \
    unsigned da = (unsigned)__cvta_generic_to_shared(Asm + (s) * NT_AS + ar * 40 + ac); \
    const __nv_bfloat16* pa = A + (size_t)(m0 + ar) * lda + (kk) + ac; \
    CPASYNC16(da, pa); CPASYNC16(da + 16, pa + 8); \
    unsigned db = (unsigned)__cvta_generic_to_shared(Bsm + (s) * NT_BS + ar * 40 + ac); \
    const __nv_bfloat16* pb = B + (size_t)(n0 + ar) * ldb + (kk) + ac; \
    CPASYNC16(db, pb); CPASYNC16(db + 16, pb + 8); }

    for (int p = 0; p < 3; ++p) {
        if (p < ntile) NT_LOAD(p, k0 + p * 32);
        CP_COMMIT();
    }

    for (int it = 0; it < ntile; ++it) {
        asm volatile("cp.async.wait_group 2;");
        __syncthreads();
        int pf = it + 3;
        if (pf < ntile) NT_LOAD(pf & 3, k0 + pf * 32);
        CP_COMMIT();

        const int s = it & 3;
        const __nv_bfloat16* As_s = Asm + s * NT_AS;
        const __nv_bfloat16* Bs_s = Bsm + s * NT_BS;
#pragma unroll
        for (int ks = 0; ks < 32; ks += 16) {
            uint32_t af[4][4];
#pragma unroll
            for (int mt = 0; mt < 4; mt++) {
                unsigned addr = (unsigned)__cvta_generic_to_shared(
                    As_s + (wm + mt * 16 + (lane & 15)) * 40 + ks + (lane >> 4) * 8);
                asm volatile("ldmatrix.sync.aligned.m8n8.x4.shared.b16 {%0,%1,%2,%3}, [%4];"
                    : "=r"(af[mt][0]), "=r"(af[mt][1]), "=r"(af[mt][2]), "=r"(af[mt][3])
                    : "r"(addr));
            }
            uint32_t bfr[4][2];
#pragma unroll
            for (int nt = 0; nt < 4; nt++) {
                unsigned addr = (unsigned)__cvta_generic_to_shared(
                    Bs_s + (wn + nt * 8 + (lane & 7)) * 40 + ks + ((lane >> 3) & 1) * 8);
                asm volatile("ldmatrix.sync.aligned.m8n8.x2.shared.b16 {%0,%1}, [%2];"
                    : "=r"(bfr[nt][0]), "=r"(bfr[nt][1]) : "r"(addr));
            }
#pragma unroll
            for (int mt = 0; mt < 4; mt++)
#pragma unroll
                for (int nt = 0; nt < 4; nt++)
                    asm volatile(
                        "mma.sync.aligned.m16n8k16.row.col.f32.bf16.bf16.f32 "
                        "{%0,%1,%2,%3}, {%4,%5,%6,%7}, {%8,%9}, {%0,%1,%2,%3};"
                        : "+f"(c[mt][nt][0]), "+f"(c[mt][nt][1]),
                          "+f"(c[mt][nt][2]), "+f"(c[mt][nt][3])
                        : "r"(af[mt][0]), "r"(af[mt][1]), "r"(af[mt][2]), "r"(af[mt][3]),
                          "r"(bfr[nt][0]), "r"(bfr[nt][1]));
        }
        __syncthreads();
    }

    const int r0 = lane >> 2, c0 = (lane & 3) * 2;
#pragma unroll
    for (int mt = 0; mt < 4; mt++)
#pragma unroll
        for (int nt = 0; nt < 4; nt++) {
            int row = m0 + wm + mt * 16 + r0;
            int col = n0 + wn + nt * 8 + c0;
            float* p0 = C + (size_t)row * ldc + col;
            float* p1 = C + (size_t)(row + 8) * ldc + col;
            if (acc == 2) {
                atomicAdd(p0,     c[mt][nt][0]); atomicAdd(p0 + 1, c[mt][nt][1]);
                atomicAdd(p1,     c[mt][nt][2]); atomicAdd(p1 + 1, c[mt][nt][3]);
            } else {
                p0[0] = c[mt][nt][0]; p0[1] = c[mt][nt][1];
                p1[0] = c[mt][nt][2]; p1[1] = c[mt][nt][3];
            }
        }
}

// ---------------- SGEMM (fp32 SIMT) ----------------
__global__ void __launch_bounds__(256) sgemm(int M, int N, int K,
                                             const float* __restrict__ A,
                                             const float* __restrict__ B,
                                             const float* __restrict__ bias,
                                             float* __restrict__ C, int act) {
    __shared__ float As[8][128];
    __shared__ float Bs[8][128];
    const int tid  = threadIdx.x;
    const int tx   = tid & 15;
    const int ty   = tid >> 4;
    const int row0 = blockIdx.y * 128;
    const int col0 = blockIdx.x * 128;
    const int a_row = tid >> 1, a_col = (tid & 1) << 2;
    const int b_row = tid >> 5, b_col = (tid & 31) << 2;

    float acc[8][8];
#pragma unroll
    for (int i = 0; i < 8; i++)
#pragma unroll
        for (int j = 0; j < 8; j++) acc[i][j] = 0.f;

    for (int kk = 0; kk < K; kk += 8) {
        float4 av = make_float4(0.f, 0.f, 0.f, 0.f);
        {
            int gm = row0 + a_row, gk = kk + a_col;
            if (gm < M && gk < K)
                av = *reinterpret_cast<const float4*>(A + (size_t)gm * K + gk);
        }
        As[a_col + 0][a_row] = av.x;
        As[a_col + 1][a_row] = av.y;
        As[a_col + 2][a_row] = av.z;
        As[a_col + 3][a_row] = av.w;

        float4 bv = make_float4(0.f, 0.f, 0.f, 0.f);
        {
            int gk = kk + b_row, gn = col0 + b_col;
            if (gk < K && gn < N)
                bv = *reinterpret_cast<const float4*>(B + (size_t)gk * N + gn);
        }
        *reinterpret_cast<float4*>(&Bs[b_row][b_col]) = bv;
        __syncthreads();

#pragma unroll
        for (int k = 0; k < 8; k++) {
            float4 a0 = *reinterpret_cast<const float4*>(&As[k][ty * 8]);
            float4 a1 = *reinterpret_cast<const float4*>(&As[k][ty * 8 + 4]);
            float4 b0 = *reinterpret_cast<const float4*>(&Bs[k][tx * 8]);
            float4 b1 = *reinterpret_cast<const float4*>(&Bs[k][tx * 8 + 4]);
            float a[8] = {a0.x, a0.y, a0.z, a0.w, a1.x, a1.y, a1.z, a1.w};
            float b[8] = {b0.x, b0.y, b0.z, b0.w, b1.x, b1.y, b1.z, b1.w};
#pragma unroll
            for (int i = 0; i < 8; i++)
#pragma unroll
                for (int j = 0; j < 8; j++) acc[i][j] += a[i] * b[j];
        }
        __syncthreads();
    }

#pragma unroll
    for (int i = 0; i < 8; i++) {
        int gm = row0 + ty * 8 + i;
        if (gm >= M) continue;
        float* Cr = C + (size_t)gm * N;
#pragma unroll
        for (int j = 0; j < 8; j++) {
            int gn = col0 + tx * 8 + j;
            if (gn >= N) continue;
            float v = acc[i][j];
            if (bias) v += bias[gn];
            if (act == ACT_RELU) v = fmaxf(v, 0.f);
            else if (act == ACT_SIGM) v = 1.f / (1.f + expf(-v));
            Cr[gn] = v;
        }
    }
}

// ---------------- graph / elementwise kernels ----------------
__global__ void k_edges_m(const int* __restrict__ ei, int E, unsigned char* __restrict__ M) {
    int e = blockIdx.x * blockDim.x + threadIdx.x;
    if (e >= E) return;
    int s = ei[e], d = ei[E + e];
    M[(size_t)s * N0 + d] = 1;
    M[(size_t)d * N0 + s] = 1;
}

// CSR of (A+I) from mask + dis = rsqrt(rowsum) in one pass
__global__ void k_csr_m(const unsigned char* __restrict__ M, int n,
                        int* __restrict__ cnt, int* __restrict__ col,
                        float* __restrict__ val, float* __restrict__ dis) {
    __shared__ int c;
    __shared__ float red[256];
    int row = blockIdx.x;
    if (threadIdx.x == 0) c = 0;
    __syncthreads();
    const unsigned char* Mr = M + (size_t)row * n;
    float lsum = 0.f;
    for (int j = threadIdx.x; j < n; j += 256) {
        float v = (float)Mr[j] + ((j == row) ? 1.f : 0.f);
        if (v != 0.f) {
            int s = atomicAdd(&c, 1);
            col[(size_t)row * DEG + s] = j;
            val[(size_t)row * DEG + s] = v;
            lsum += v;
        }
    }
    red[threadIdx.x] = lsum;
    __syncthreads();
    for (int o = 128; o > 0; o >>= 1) {
        if (threadIdx.x < o) red[threadIdx.x] += red[threadIdx.x + o];
        __syncthreads();
    }
    if (threadIdx.x == 0) { cnt[row] = c; dis[row] = rsqrtf(red[0]); }
}

__global__ void k_dis_b(const __nv_bfloat16* __restrict__ M, int ld, int w,
                        float* __restrict__ dis) {
    __shared__ float red[256];
    int row = blockIdx.x;
    const __nv_bfloat16* Mr = M + (size_t)row * ld;
    float s = 0.f;
    for (int j = threadIdx.x; j < w; j += 256) s += __bfloat162float(Mr[j]);
    red[threadIdx.x] = s;
    __syncthreads();
    for (int o = 128; o > 0; o >>= 1) {
        if (threadIdx.x < o) red[threadIdx.x] += red[threadIdx.x + o];
        __syncthreads();
    }
    if (threadIdx.x == 0) dis[row] = rsqrtf(red[0]);
}

// SpMM GCN: S[i][c] = dis[i] * sum_e val_ie * dis[col_ie] * X[col_ie][c]
__global__ void k_spmm(const int* __restrict__ cnt, const int* __restrict__ col,
                       const float* __restrict__ val,
                       const float* __restrict__ X, int C,
                       const float* __restrict__ dis,
                       const float* __restrict__ bias, int act,
                       float* __restrict__ S) {
    int row = blockIdx.x, c = threadIdx.x;
    if (c >= C) return;
    int m = cnt[row];
    const int* cr = col + (size_t)row * DEG;
    const float* vr = val + (size_t)row * DEG;
    float acc = 0.f;
    for (int e = 0; e < m; e++) {
        int j = cr[e];
        acc += vr[e] * dis[j] * X[(size_t)j * C + c];
    }
    float v = acc * dis[row];
    if (bias) v += bias[c];
    if (act == ACT_SIGM) v = 1.f / (1.f + expf(-v));
    S[(size_t)row * C + c] = v;
}

// SpGEMM pool0: bA1[r][:] = bf16 of [(A0+I)^2]_{perm,perm} row r, diag -> 1
__global__ void __launch_bounds__(256) k_spgemm(
        const int* __restrict__ cnt, const int* __restrict__ col,
        const float* __restrict__ val, const int* __restrict__ perm,
        const int* __restrict__ inv, int k, int np,
        __nv_bfloat16* __restrict__ bA1) {
    __shared__ float acc[2048];
    int r = blockIdx.x;
    for (int i = threadIdx.x; i < np; i += 256) acc[i] = 0.f;
    __syncthreads();
    if (r < k) {
        int row = perm[r];
        int m = cnt[row];
        const int* cr = col + (size_t)row * DEG;
        const float* vr = val + (size_t)row * DEG;
        for (int e1 = 0; e1 < m; e1++) {
            int j = cr[e1];
            float w1 = vr[e1];
            int mj = cnt[j];
            const int* cj = col + (size_t)j * DEG;
            const float* vj = val + (size_t)j * DEG;
            for (int e2 = threadIdx.x; e2 < mj; e2 += 256) {
                int cidx = inv[cj[e2]];
                if (cidx >= 0) atomicAdd(&acc[cidx], w1 * vj[e2]);
            }
        }
    }
    __syncthreads();
    __nv_bfloat16* out = bA1 + (size_t)r * np;
    for (int cidx = threadIdx.x; cidx < np; cidx += 256) {
        float v = (r < k) ? ((cidx == r) ? 1.f : acc[cidx]) : 0.f;
        out[cidx] = __float2bfloat16(v);
    }
}

__global__ void k_inv_init(int* __restrict__ inv, int n) {
    int i = blockIdx.x * blockDim.x + threadIdx.x;
    if (i < n) inv[i] = -1;
}
__global__ void k_inv_set(const int* __restrict__ perm, int k, int* __restrict__ inv) {
    int i = blockIdx.x * blockDim.x + threadIdx.x;
    if (i < k) inv[perm[i]] = i;
}

__global__ void k_scale_pack(const float* __restrict__ xw, const float* __restrict__ dis,
                             int n, int np, int C, int Cpad,
                             __nv_bfloat16* __restrict__ zpk) {
    int i = blockIdx.x * blockDim.x + threadIdx.x;
    int W = 2 * Cpad;
    if (i >= np * W) return;
    int r = i / W, cc = i - r * W;
    int colx = (cc < Cpad) ? cc : cc - Cpad;
    float v = (r < n && colx < C) ? dis[r] * xw[(size_t)r * C + colx] : 0.f;
    __nv_bfloat16 hi = __float2bfloat16(v);
    if (cc < Cpad) zpk[i] = hi;
    else           zpk[i] = __float2bfloat16(v - __bfloat162float(hi));
}

__global__ void k_scale_pack_stk(const float* __restrict__ xw, const float* __restrict__ dis,
                                 int n, int np, int C,
                                 __nv_bfloat16* __restrict__ Bp) {
    int i = blockIdx.x * blockDim.x + threadIdx.x;
    int W = 2 * C;
    if (i >= 2 * np * W) return;
    int r = i / W, cc = i - r * W;
    int rr = (r < np) ? r : r - np;
    int colx = (cc < C) ? cc : cc - C;
    float v = (rr < n) ? dis[rr] * xw[(size_t)rr * C + colx] : 0.f;
    __nv_bfloat16 hi = __float2bfloat16(v);
    __nv_bfloat16 lo = __float2bfloat16(v - __bfloat162float(hi));
    bool wantHi = ((r < np) == (cc < C));
    Bp[i] = wantHi ? hi : lo;
}

__global__ void k_packX3(const float* __restrict__ X, int np, int C,
                         __nv_bfloat16* __restrict__ Xp) {
    int i = blockIdx.x * blockDim.x + threadIdx.x;
    int W = 3 * C;
    if (i >= np * W) return;
    int r = i / W, cc = i - r * W;
    int colx = cc; if (colx >= C) colx -= C; if (colx >= C) colx -= C;
    float v = X[(size_t)r * C + colx];
    __nv_bfloat16 hi = __float2bfloat16(v);
    bool isLo = (cc >= C && cc < 2 * C);
    Xp[i] = isLo ? __float2bfloat16(v - __bfloat162float(hi)) : hi;
}

__global__ void k_packW3(const float* __restrict__ W, int K, int N,
                         __nv_bfloat16* __restrict__ Wp) {
    int i = blockIdx.x * blockDim.x + threadIdx.x;
    if (i >= 3 * K * N) return;
    int r = i / N, cc = i - r * N;
    int rr = r; if (rr >= K) rr -= K; if (rr >= K) rr -= K;
    float v = W[(size_t)rr * N + cc];
    __nv_bfloat16 hi = __float2bfloat16(v);
    Wp[i] = (r < 2 * K) ? hi : __float2bfloat16(v - __bfloat162float(hi));
}

__global__ void k_epilogue_sum2(const float* __restrict__ t, int ldt, int half,
                                const float* __restrict__ dis, const float* __restrict__ b,
                                int n, int C, float* __restrict__ out, int act) {
    int i = blockIdx.x * blockDim.x + threadIdx.x;
    if (i >= n * C) return;
    int r = i / C, cc = i - r * C;
    float v = dis[r] * (t[(size_t)r * ldt + cc] + t[(size_t)r * ldt + cc + half]) + b[cc];
    if (act == ACT_RELU) v = fmaxf(v, 0.f);
    else if (act == ACT_SIGM) v = 1.f / (1.f + expf(-v));
    out[i] = v;
}

__global__ void k_crop_pack_X(const float* __restrict__ Augp, int kpad, int k, int np,
                              __nv_bfloat16* __restrict__ X) {
    int i = blockIdx.x * blockDim.x + threadIdx.x;
    if (i >= np * np) return;
    int r = i / np, cc = i - r * np;
    float v = 0.f;
    if (r < k && cc < k) {
        if (r == cc) v = 1.f;
        else {
            int rr = (r < cc) ? r : cc;
            int c2 = (r < cc) ? cc : r;
            v = Augp[(size_t)rr * kpad + c2];
        }
    }
    __nv_bfloat16 hi = __float2bfloat16(v);
    __nv_bfloat16 lo = __float2bfloat16(v - __bfloat162float(hi));
    X[(size_t)r * (2 * np) + cc]      = hi;
    X[(size_t)r * (2 * np) + np + cc] = lo;
}

__global__ void k_gather_rows(const __nv_bfloat16* __restrict__ bApI, int np,
                              const int* __restrict__ perm, int k, int kpad,
                              __nv_bfloat16* __restrict__ G) {
    int i = blockIdx.x * blockDim.x + threadIdx.x;
    if (i >= kpad * np) return;
    int r = i / np, j = i - r * np;
    G[i] = (r < k) ? bApI[(size_t)perm[r] * np + j] : __float2bfloat16(0.f);
}

__global__ void k_gather_PQ_b(const __nv_bfloat16* __restrict__ X2, int np,
                              const int* __restrict__ perm, int k, int kpad,
                              __nv_bfloat16* __restrict__ P,
                              __nv_bfloat16* __restrict__ Q) {
    int i = blockIdx.x * blockDim.x + threadIdx.x;
    int W = 2 * np;
    if (i >= kpad * W) return;
    int r = i / W, j = i - r * W;
    __nv_bfloat16 v = (r < k) ? X2[(size_t)perm[r] * W + j] : __float2bfloat16(0.f);
    P[i] = v;
    int js = (j < np) ? j + np : j - np;
    Q[(size_t)r * W + js] = v;
}

__global__ void k_pnorm(const float* __restrict__ p, int n, float* __restrict__ out) {
    __shared__ float red[256];
    float s = 0.f;
    for (int i = threadIdx.x; i < n; i += 256) s += p[i] * p[i];
    red[threadIdx.x] = s;
    __syncthreads();
    for (int o = 128; o > 0; o >>= 1) {
        if (threadIdx.x < o) red[threadIdx.x] += red[threadIdx.x + o];
        __syncthreads();
    }
    if (threadIdx.x == 0) out[0] = sqrtf(red[0]);
}

__global__ void k_scores(const float* __restrict__ h, int n, int C,
                         const float* __restrict__ p, const float* __restrict__ pn,
                         float* __restrict__ score) {
    int row = blockIdx.x * 8 + (threadIdx.x >> 5);
    int lane = threadIdx.x & 31;
    if (row >= n) return;
    const float* hr = h + (size_t)row * C;
    float s = 0.f;
    for (int cc = lane; cc < C; cc += 32) s += hr[cc] * p[cc];
    for (int o = 16; o > 0; o >>= 1) s += __shfl_xor_sync(0xffffffffu, s, o);
    if (lane == 0) score[row] = tanhf(s / pn[0]);
}

// threshold-based top-k select: write the top-k index SET (any order)
__global__ void __launch_bounds__(1024) k_topk_sel(const float* __restrict__ score,
                                                   int n, int k, int* __restrict__ perm) {
    __shared__ float sc[4096];
    __shared__ int cnt;
    int tid = threadIdx.x;
    for (int i = tid; i < n; i += 1024) sc[i] = score[i];
    __syncthreads();
    float lo = -1.1f, hi = 1.1f;
    for (int it = 0; it < 40; ++it) {
        float mid = 0.5f * (lo + hi);
        if (tid == 0) cnt = 0;
        __syncthreads();
        int c = 0;
        for (int i = tid; i < n; i += 1024) if (sc[i] > mid) c++;
        if (c) atomicAdd(&cnt, c);
        __syncthreads();
        if (cnt >= k) lo = mid; else hi = mid;
        __syncthreads();
    }
    // elements strictly above hi are definitely in the top-k
    if (tid == 0) cnt = 0;
    __syncthreads();
    for (int i = tid; i < n; i += 1024)
        if (sc[i] > hi) { int s = atomicAdd(&cnt, 1); perm[s] = i; }
    __syncthreads();
    // fill remaining slots from the boundary band (lo, hi]
    for (int i = tid; i < n; i += 1024)
        if (sc[i] > lo && sc[i] <= hi) {
            int s = atomicAdd(&cnt, 1);
            if (s < k) perm[s] = i;
        }
}

__global__ void k_gatherX(const float* __restrict__ h, int C,
                          const int* __restrict__ perm, const float* __restrict__ score,
                          int k, float* __restrict__ out) {
    int i = blockIdx.x * blockDim.x + threadIdx.x;
    if (i >= k * C) return;
    int r = i / C, cc = i - r * C;
    int pr = perm[r];
    out[i] = h[(size_t)pr * C + cc] * score[pr];
}

__global__ void k_scatter_add(float* __restrict__ u, const float* __restrict__ h,
                              const int* __restrict__ perm, int k, int C) {
    int i = blockIdx.x * blockDim.x + threadIdx.x;
    if (i >= k * C) return;
    int r = i / C, cc = i - r * C;
    u[(size_t)perm[r] * C + cc] += h[i];
}

// ---------------- host orchestration ----------------
static void run_sgemm(int M, int N, int K, const float* A, const float* B,
                      const float* bias, float* C, int act) {
    dim3 g((N + 127) / 128, (M + 127) / 128);
    sgemm<<<g, 256>>>(M, N, K, A, B, bias, C, act);
}
static void run_nn(int M, int N, int K, const __nv_bfloat16* A, int lda,
                   const __nv_bfloat16* B, int ldb, float* C, int ldc, int acc, int splitk,
                   const float* bias, int act) {
    cudaFuncSetAttribute(hgemm_nn, cudaFuncAttributeMaxDynamicSharedMemorySize, NN_SMEM);
    dim3 g(N / 128, M / 128, splitk);
    hgemm_nn<<<g, 256, NN_SMEM>>>(M, N, K, A, lda, B, ldb, C, ldc, acc, bias, act);
}
static void run_nt_tri(int M, int K, const __nv_bfloat16* A, int lda,
                       const __nv_bfloat16* B, int ldb, float* C, int ldc, int splitk) {
    cudaFuncSetAttribute(hgemm_nt, cudaFuncAttributeMaxDynamicSharedMemorySize, NT_SMEM);
    int T = M / 128;
    dim3 g(T * (T + 1) / 2, 1, splitk);
    hgemm_nt<<<g, 256, NT_SMEM>>>(M, M, K, A, lda, B, ldb, C, ldc, 2, 1);
}

static void run_xw_tc(const float* X, int np, int C, const float* W, int N,
                      const float* bias, int act, float* out, int splitk,
                      __nv_bfloat16* Xp, __nv_bfloat16* Wp) {
    int totX = np * 3 * C;
    k_packX3<<<(totX + 255) / 256, 256>>>(X, np, C, Xp);
    int totW = 3 * C * N;
    k_packW3<<<(totW + 255) / 256, 256>>>(W, C, N, Wp);
    if (splitk > 1) {
        cudaMemsetAsync(out, 0, (size_t)np * N * sizeof(float), 0);
        run_nn(np, N, 3 * C, Xp, 3 * C, Wp, N, out, N, 2, splitk, nullptr, ACT_NONE);
    } else {
        run_nn(np, N, 3 * C, Xp, 3 * C, Wp, N, out, N, 0, 1, bias, act);
    }
}

static void run_gcn_exact(const __nv_bfloat16* bApI, int n, int np,
                          const float* X, int inC, const float* W, int outC, const float* b,
                          float* out, int act, int splitk,
                          float* xw, float* t, const float* dis, __nv_bfloat16* zpk,
                          __nv_bfloat16* Xp, __nv_bfloat16* Wp) {
    run_xw_tc(X, np, inC, W, outC, nullptr, ACT_NONE, xw, 1, Xp, Wp);
    int Cpad = outC;
    int W2 = 2 * Cpad;
    int tot = np * W2;
    k_scale_pack<<<(tot + 255) / 256, 256>>>(xw, dis, n, np, outC, Cpad, zpk);
    cudaMemsetAsync(t, 0, (size_t)np * W2 * sizeof(float), 0);
    run_nn(np, W2, np, bApI, np, zpk, W2, t, W2, 2, splitk, nullptr, ACT_NONE);
    int nc = n * outC;
    k_epilogue_sum2<<<(nc + 255) / 256, 256>>>(t, W2, Cpad, dis, b, n, outC, out, act);
}

static void run_gcn_split(const __nv_bfloat16* X2, int n, int np,
                          const float* X, int inC, const float* W, int outC, const float* b,
                          float* out, int act, int splitk,
                          float* xw, float* t, const float* dis, __nv_bfloat16* Bp,
                          __nv_bfloat16* Xp, __nv_bfloat16* Wp) {
    run_xw_tc(X, np, inC, W, outC, nullptr, ACT_NONE, xw, (np <= 512) ? 2 : 1, Xp, Wp);
    int W2 = 2 * outC;
    int tot = 2 * np * W2;
    k_scale_pack_stk<<<(tot + 255) / 256, 256>>>(xw, dis, n, np, outC, Bp);
    cudaMemsetAsync(t, 0, (size_t)np * W2 * sizeof(float), 0);
    run_nn(np, W2, 2 * np, X2, 2 * np, Bp, W2, t, W2, 2, splitk, nullptr, ACT_NONE);
    int nc = n * outC;
    k_epilogue_sum2<<<(nc + 255) / 256, 256>>>(t, W2, outC, dis, b, n, outC, out, act);
}

static void run_scores_topk(const float* h, int n, const float* p, int k,
                            int* perm, float* score, float* pn) {
    k_pnorm<<<1, 256>>>(p, HC, pn);
    k_scores<<<(n + 7) / 8, 256>>>(h, n, HC, p, pn, score);
    k_topk_sel<<<1, 1024>>>(score, n, k, perm);
}

extern "C" void kernel_launch(void* const* d_in, const int* in_sizes, int n_in,
                              void* d_out, int out_size) {
    const float* x   = (const float*)d_in[0];
    const int*   ei  = (const int*)  d_in[1];
    const float* Wd0 = (const float*)d_in[2];  const float* bd0 = (const float*)d_in[3];
    const float* Wd1 = (const float*)d_in[4];  const float* bd1 = (const float*)d_in[5];
    const float* Wd2 = (const float*)d_in[6];  const float* bd2 = (const float*)d_in[7];
    const float* Wd3 = (const float*)d_in[8];  const float* bd3 = (const float*)d_in[9];
    const float* p1  = (const float*)d_in[10];
    const float* p2  = (const float*)d_in[11];
    const float* p3  = (const float*)d_in[12];
    const float* Wu0 = (const float*)d_in[13]; const float* bu0 = (const float*)d_in[14];
    const float* Wu1 = (const float*)d_in[15]; const float* bu1 = (const float*)d_in[16];
    const float* Wu2 = (const float*)d_in[17]; const float* bu2 = (const float*)d_in[18];
    const int E = in_sizes[1] / 2;

    float *Augp, *h0, *h1, *h2, *h3, *hb, *xw, *t, *u, *sc, *pn;
    float *dis0, *dis1, *dis2, *dis3;
    int *pm0, *pm1, *pm2, *inv, *ccnt, *ccol;
    float *cval;
    unsigned char* m0;
    __nv_bfloat16 *bA1, *bX2, *bX3, *G, *Q, *zpk, *Xp, *Wp;
    cudaGetSymbolAddress((void**)&Augp, g_Augp);
    cudaGetSymbolAddress((void**)&h0,  g_h0);
    cudaGetSymbolAddress((void**)&h1,  g_h1);
    cudaGetSymbolAddress((void**)&h2,  g_h2);
    cudaGetSymbolAddress((void**)&h3,  g_h3);
    cudaGetSymbolAddress((void**)&hb,  g_hb);
    cudaGetSymbolAddress((void**)&xw,  g_xw);
    cudaGetSymbolAddress((void**)&t,   g_t);
    cudaGetSymbolAddress((void**)&u,   g_u);
    cudaGetSymbolAddress((void**)&dis0, g_dis0);
    cudaGetSymbolAddress((void**)&dis1, g_dis1);
    cudaGetSymbolAddress((void**)&dis2, g_dis2);
    cudaGetSymbolAddress((void**)&dis3, g_dis3);
    cudaGetSymbolAddress((void**)&sc,  g_sc);
    cudaGetSymbolAddress((void**)&pn,  g_pn);
    cudaGetSymbolAddress((void**)&pm0, g_perm0);
    cudaGetSymbolAddress((void**)&pm1, g_perm1);
    cudaGetSymbolAddress((void**)&pm2, g_perm2);
    cudaGetSymbolAddress((void**)&inv, g_inv);
    cudaGetSymbolAddress((void**)&ccnt, g_ccnt);
    cudaGetSymbolAddress((void**)&ccol, g_ccol);
    cudaGetSymbolAddress((void**)&cval, g_cval);
    cudaGetSymbolAddress((void**)&m0,  g_m0);
    cudaGetSymbolAddress((void**)&bA1, g_bA1);
    cudaGetSymbolAddress((void**)&bX2, g_bX2);
    cudaGetSymbolAddress((void**)&bX3, g_bX3);
    cudaGetSymbolAddress((void**)&G,   g_G);
    cudaGetSymbolAddress((void**)&Q,   g_Q);
    cudaGetSymbolAddress((void**)&zpk, g_zpk);
    cudaGetSymbolAddress((void**)&Xp,  g_Xpk);
    cudaGetSymbolAddress((void**)&Wp,  g_Wpk);

    // ---- adjacency mask -> CSR(A0+I) + dis0 (one pass, no dense bf16) ----
    cudaMemsetAsync(m0, 0, (size_t)N0 * N0, 0);
    k_edges_m<<<(E + 255) / 256, 256>>>(ei, E, m0);
    k_csr_m<<<N0, 256>>>(m0, N0, ccnt, ccol, cval, dis0);

    // ---- down level 0 (sparse, exact fp32) ----
    k_spmm<<<N0, INC>>>(ccnt, ccol, cval, x, INC, dis0, nullptr, ACT_NONE, xw);
    run_xw_tc(xw, N0, INC, Wd0, HC, bd0, ACT_RELU, h0, 1, Xp, Wp);

    // pool0: bA1 = crop([(A0+I)^2]) + I via SpGEMM
    run_scores_topk(h0, N0, p1, KP1, pm0, sc, pn);
    k_inv_init<<<(N0 + 255) / 256, 256>>>(inv, N0);
    k_inv_set<<<(KP1 + 255) / 256, 256>>>(pm0, KP1, inv);
    k_spgemm<<<2048, 256>>>(ccnt, ccol, cval, pm0, inv, KP1, 2048, bA1);
    k_gatherX<<<(KP1 * HC + 255) / 256, 256>>>(h0, HC, pm0, sc, KP1, u);
    k_dis_b<<<KP1, 256>>>(bA1, 2048, 2048, dis1);
    run_gcn_exact(bA1, KP1, 2048, u, HC, Wd1, HC, bd1, h1, ACT_RELU, 4,
                  xw, t, dis1, zpk, Xp, Wp);

    // pool1: A2 submatrix via G@G^T (symmetric bf16, exact small ints)
    run_scores_topk(h1, KP1, p2, KP2, pm1, sc, pn);
    k_gather_rows<<<(1024 * 2048 + 255) / 256, 256>>>(bA1, 2048, pm1, KP2, 1024, G);
    cudaMemsetAsync(Augp, 0, (size_t)1024 * 1024 * sizeof(float), 0);
    run_nt_tri(1024, 2048, G, 2048, G, 2048, Augp, 1024, 8);
    k_gatherX<<<(KP2 * HC + 255) / 256, 256>>>(h1, HC, pm1, sc, KP2, u);
    k_crop_pack_X<<<(1024 * 1024 + 255) / 256, 256>>>(Augp, 1024, KP2, 1024, bX2);
    k_dis_b<<<KP2, 256>>>(bX2, 2048, 2048, dis2);
    run_gcn_split(bX2, KP2, 1024, u, HC, Wd2, HC, bd2, h2, ACT_RELU, 2,
                  xw, t, dis2, zpk, Xp, Wp);

    // pool2: A3 = P@P^T + P@Q^T (both symmetric, exact hi/lo split)
    run_scores_topk(h2, KP2, p3, KP3, pm2, sc, pn);
    k_gather_PQ_b<<<(512 * 2048 + 255) / 256, 256>>>(bX2, 1024, pm2, KP3, 512, G, Q);
    cudaMemsetAsync(Augp, 0, (size_t)512 * 512 * sizeof(float), 0);
    run_nt_tri(512, 2048, G, 2048, G, 2048, Augp, 512, 8);
    run_nt_tri(512, 2048, G, 2048, Q, 2048, Augp, 512, 8);
    k_gatherX<<<(KP3 * HC + 255) / 256, 256>>>(h2, HC, pm2, sc, KP3, u);
    k_crop_pack_X<<<(512 * 512 + 255) / 256, 256>>>(Augp, 512, KP3, 512, bX3);
    k_dis_b<<<KP3, 256>>>(bX3, 1024, 1024, dis3);
    run_gcn_split(bX3, KP3, 512, u, HC, Wd3, HC, bd3, h3, ACT_RELU, 4,
                  xw, t, dis3, zpk, Xp, Wp);

    // ---- up path ----
    cudaMemcpyAsync(u, h2, (size_t)KP2 * HC * sizeof(float), cudaMemcpyDeviceToDevice, 0);
    k_scatter_add<<<(KP3 * HC + 255) / 256, 256>>>(u, h3, pm2, KP3, HC);
    run_gcn_split(bX2, KP2, 1024, u, HC, Wu0, HC, bu0, hb, ACT_RELU, 2,
                  xw, t, dis2, zpk, Xp, Wp);

    cudaMemcpyAsync(u, h1, (size_t)KP1 * HC * sizeof(float), cudaMemcpyDeviceToDevice, 0);
    k_scatter_add<<<(KP2 * HC + 255) / 256, 256>>>(u, hb, pm1, KP2, HC);
    run_gcn_exact(bA1, KP1, 2048, u, HC, Wu1, HC, bu1, hb, ACT_RELU, 4,
                  xw, t, dis1, zpk, Xp, Wp);

    cudaMemcpyAsync(u, h0, (size_t)N0 * HC * sizeof(float), cudaMemcpyDeviceToDevice, 0);
    k_scatter_add<<<(KP1 * HC + 255) / 256, 256>>>(u, hb, pm0, KP1, HC);
    // final level-0 GCN: xw = u@Wu2 (N=64 sgemm), then SpMM + sigmoid (exact)
    run_sgemm(N0, OC, HC, u, Wu2, nullptr, xw, ACT_NONE);
    k_spmm<<<N0, OC>>>(ccnt, ccol, cval, xw, OC, dis0, bu2, ACT_SIGM, (float*)d_out);
}

// round 14
// speedup vs baseline: 2.1518x; 1.1162x over previous
#include <cuda_runtime.h>
#include <cuda_bf16.h>
#include <cstdint>
#include <math.h>

// ---------------- problem constants ----------------
#define N0   4096
#define INC  128
#define HC   512
#define OC   64
#define KP1  2000
#define KP2  1000
#define KP3  500
#define DEG  192

#define ACT_NONE 0
#define ACT_RELU 1
#define ACT_SIGM 2

// ---------------- scratch (device globals; allocation-free) ----------------
__device__ float g_Augp[(size_t)1024*1024];
__device__ float g_h0 [(size_t)N0*HC];
__device__ float g_h1 [(size_t)KP1*HC];
__device__ float g_h2 [(size_t)KP2*HC];
__device__ float g_h3 [(size_t)KP3*HC];
__device__ float g_hb [(size_t)KP1*HC];
__device__ float g_xw [(size_t)N0*HC];
__device__ float g_t  [(size_t)2048*1024];
__device__ float g_u  [(size_t)N0*HC];
__device__ float g_dis0[N0];
__device__ float g_dis1[2048];
__device__ float g_dis2[2048];
__device__ float g_dis3[1024];
__device__ float g_sc [N0];
__device__ int   g_perm0[KP1];
__device__ int   g_perm1[KP2];
__device__ int   g_perm2[KP3];
__device__ int   g_inv[N0];
__device__ int   g_ccnt[N0];
__device__ int   g_ccol[(size_t)N0*DEG];
__device__ float g_cval[(size_t)N0*DEG];
__device__ unsigned char g_m0[(size_t)N0*N0];
__device__ __nv_bfloat16 g_bA1 [(size_t)2048*2048];
__device__ __nv_bfloat16 g_bX2 [(size_t)1024*2048];
__device__ __nv_bfloat16 g_bX3 [(size_t)512*1024];
__device__ __nv_bfloat16 g_G  [(size_t)1024*2048];
__device__ __nv_bfloat16 g_Q  [(size_t)512*2048];
__device__ __nv_bfloat16 g_zpk[(size_t)2048*1024];
__device__ __nv_bfloat16 g_Xpk[(size_t)4096*1536];
__device__ __nv_bfloat16 g_Wpk[(size_t)1536*512];

// ---------------- cp.async helpers ----------------
#define CPASYNC16(dst_u32, src_ptr) \
    asm volatile("cp.async.ca.shared.global [%0], [%1], 16;" :: "r"(dst_u32), "l"(src_ptr))
#define CP_COMMIT() asm volatile("cp.async.commit_group;")

#define NN_AS (128*40)
#define NN_BS (32*136)
#define NT_AS (128*40)
#define NT_BS (128*40)
#define NN_SMEM (4 * (NN_AS + NN_BS) * 2)
#define NT_SMEM (4 * (NT_AS + NT_BS) * 2)

// ---------------- NN GEMM: C(MxN) = A(MxK) @ B(KxN), bf16->fp32 ----------------
__global__ void __launch_bounds__(256) hgemm_nn(int M, int N, int K,
        const __nv_bfloat16* __restrict__ A, int lda,
        const __nv_bfloat16* __restrict__ B, int ldb,
        float* __restrict__ C, int ldc, int acc,
        const float* __restrict__ bias, int act) {
    extern __shared__ __nv_bfloat16 dsm[];
    __nv_bfloat16* Asm = dsm;
    __nv_bfloat16* Bsm = dsm + 4 * NN_AS;
    const int tid  = threadIdx.x;
    const int lane = tid & 31;
    const int warp = tid >> 5;
    const int wm = (warp >> 2) * 64;
    const int wn = (warp & 3) * 32;
    const int m0 = blockIdx.y * 128;
    const int n0 = blockIdx.x * 128;
    const int Kc = K / gridDim.z;
    const int k0 = blockIdx.z * Kc;

    const int ar = tid >> 1, ac = (tid & 1) * 16;
    const int br = tid >> 3, bc = (tid & 7) * 16;

    float c[4][4][4];
#pragma unroll
    for (int mt = 0; mt < 4; mt++)
#pragma unroll
        for (int nt = 0; nt < 4; nt++)
#pragma unroll
            for (int r = 0; r < 4; r++) c[mt][nt][r] = 0.f;

    const int ntile = Kc >> 5;

#define NN_LOAD(s, kk) { \
    unsigned da = (unsigned)__cvta_generic_to_shared(Asm + (s) * NN_AS + ar * 40 + ac); \
    const __nv_bfloat16* pa = A + (size_t)(m0 + ar) * lda + (kk) + ac; \
    CPASYNC16(da, pa); CPASYNC16(da + 16, pa + 8); \
    unsigned db = (unsigned)__cvta_generic_to_shared(Bsm + (s) * NN_BS + br * 136 + bc); \
    const __nv_bfloat16* pb = B + (size_t)((kk) + br) * ldb + n0 + bc; \
    CPASYNC16(db, pb); CPASYNC16(db + 16, pb + 8); }

    for (int p = 0; p < 3; ++p) {
        if (p < ntile) NN_LOAD(p, k0 + p * 32);
        CP_COMMIT();
    }

    for (int it = 0; it < ntile; ++it) {
        asm volatile("cp.async.wait_group 2;");
        __syncthreads();
        int pf = it + 3;
        if (pf < ntile) NN_LOAD(pf & 3, k0 + pf * 32);
        CP_COMMIT();

        const int s = it & 3;
        const __nv_bfloat16* As_s = Asm + s * NN_AS;
        const __nv_bfloat16* Bs_s = Bsm + s * NN_BS;
#pragma unroll
        for (int ks = 0; ks < 32; ks += 16) {
            uint32_t af[4][4];
#pragma unroll
            for (int mt = 0; mt < 4; mt++) {
                unsigned addr = (unsigned)__cvta_generic_to_shared(
                    As_s + (wm + mt * 16 + (lane & 15)) * 40 + ks + (lane >> 4) * 8);
                asm volatile("ldmatrix.sync.aligned.m8n8.x4.shared.b16 {%0,%1,%2,%3}, [%4];"
                    : "=r"(af[mt][0]), "=r"(af[mt][1]), "=r"(af[mt][2]), "=r"(af[mt][3])
                    : "r"(addr));
            }
            uint32_t bfr[4][2];
#pragma unroll
            for (int nt = 0; nt < 4; nt++) {
                unsigned addr = (unsigned)__cvta_generic_to_shared(
                    Bs_s + (ks + (lane & 15)) * 136 + wn + nt * 8);
                asm volatile("ldmatrix.sync.aligned.m8n8.x2.trans.shared.b16 {%0,%1}, [%2];"
                    : "=r"(bfr[nt][0]), "=r"(bfr[nt][1]) : "r"(addr));
            }
#pragma unroll
            for (int mt = 0; mt < 4; mt++)
#pragma unroll
                for (int nt = 0; nt < 4; nt++)
                    asm volatile(
                        "mma.sync.aligned.m16n8k16.row.col.f32.bf16.bf16.f32 "
                        "{%0,%1,%2,%3}, {%4,%5,%6,%7}, {%8,%9}, {%0,%1,%2,%3};"
                        : "+f"(c[mt][nt][0]), "+f"(c[mt][nt][1]),
                          "+f"(c[mt][nt][2]), "+f"(c[mt][nt][3])
                        : "r"(af[mt][0]), "r"(af[mt][1]), "r"(af[mt][2]), "r"(af[mt][3]),
                          "r"(bfr[nt][0]), "r"(bfr[nt][1]));
        }
        __syncthreads();
    }

    const int r0 = lane >> 2, c0 = (lane & 3) * 2;
#pragma unroll
    for (int mt = 0; mt < 4; mt++)
#pragma unroll
        for (int nt = 0; nt < 4; nt++) {
            int row = m0 + wm + mt * 16 + r0;
            int col = n0 + wn + nt * 8 + c0;
            float* p0 = C + (size_t)row * ldc + col;
            float* p1 = C + (size_t)(row + 8) * ldc + col;
            if (acc == 2) {
                atomicAdd(p0,     c[mt][nt][0]); atomicAdd(p0 + 1, c[mt][nt][1]);
                atomicAdd(p1,     c[mt][nt][2]); atomicAdd(p1 + 1, c[mt][nt][3]);
            } else {
                float v0 = c[mt][nt][0], v1 = c[mt][nt][1];
                float v2 = c[mt][nt][2], v3 = c[mt][nt][3];
                if (bias) { v0 += bias[col]; v1 += bias[col + 1];
                            v2 += bias[col]; v3 += bias[col + 1]; }
                if (act == ACT_RELU) {
                    v0 = fmaxf(v0, 0.f); v1 = fmaxf(v1, 0.f);
                    v2 = fmaxf(v2, 0.f); v3 = fmaxf(v3, 0.f);
                }
                p0[0] = v0; p0[1] = v1;
                p1[0] = v2; p1[1] = v3;
            }
        }
}

// ---------------- NT GEMM (tri-symmetric option) ----------------
__global__ void __launch_bounds__(256) hgemm_nt(int M, int N, int K,
        const __nv_bfloat16* __restrict__ A, int lda,
        const __nv_bfloat16* __restrict__ B, int ldb,
        float* __restrict__ C, int ldc, int acc, int tri) {
    extern __shared__ __nv_bfloat16 dsm[];
    __nv_bfloat16* Asm = dsm;
    __nv_bfloat16* Bsm = dsm + 4 * NT_AS;
    const int tid  = threadIdx.x;
    const int lane = tid & 31;
    const int warp = tid >> 5;
    const int wm = (warp >> 2) * 64;
    const int wn = (warp & 3) * 32;

    int m0, n0;
    if (tri) {
        int bid = blockIdx.x;
        int by = (int)((sqrtf(8.f * bid + 1.f) - 1.f) * 0.5f);
        while ((by + 1) * (by + 2) / 2 <= bid) by++;
        while (by * (by + 1) / 2 > bid) by--;
        int bx = bid - by * (by + 1) / 2;
        m0 = bx * 128;
        n0 = by * 128;
    } else {
        m0 = blockIdx.y * 128;
        n0 = blockIdx.x * 128;
    }
    const int Kc = K / gridDim.z;
    const int k0 = blockIdx.z * Kc;

    const int ar = tid >> 1, ac = (tid & 1) * 16;

    float c[4][4][4];
#pragma unroll
    for (int mt = 0; mt < 4; mt++)
#pragma unroll
        for (int nt = 0; nt < 4; nt++)
#pragma unroll
            for (int r = 0; r < 4; r++) c[mt][nt][r] = 0.f;

    const int ntile = Kc >> 5;

#define NT_LOAD(s, kk) { \
    unsigned da = (unsigned)__cvta_generic_to_shared(Asm + (s) * NT_AS + ar * 40 + ac); \
    const __nv_bfloat16* pa = A + (size_t)(m0 + ar) * lda + (kk) + ac; \
    CPASYNC16(da, pa); CPASYNC16(da + 16, pa + 8); \
    unsigned db = (unsigned)__cvta_generic_to_shared(Bsm + (s) * NT_BS + ar * 40 + ac); \
    const __nv_bfloat16* pb = B + (size_t)(n0 + ar) * ldb + (kk) + ac; \
    CPASYNC16(db, pb); CPASYNC16(db + 16, pb + 8); }

    for (int p = 0; p < 3; ++p) {
        if (p < ntile) NT_LOAD(p, k0 + p * 32);
        CP_COMMIT();
    }

    for (int it = 0; it < ntile; ++it) {
        asm volatile("cp.async.wait_group 2;");
        __syncthreads();
        int pf = it + 3;
        if (pf < ntile) NT_LOAD(pf & 3, k0 + pf * 32);
        CP_COMMIT();

        const int s = it & 3;
        const __nv_bfloat16* As_s = Asm + s * NT_AS;
        const __nv_bfloat16* Bs_s = Bsm + s * NT_BS;
#pragma unroll
        for (int ks = 0; ks < 32; ks += 16) {
            uint32_t af[4][4];
#pragma unroll
            for (int mt = 0; mt < 4; mt++) {
                unsigned addr = (unsigned)__cvta_generic_to_shared(
                    As_s + (wm + mt * 16 + (lane & 15)) * 40 + ks + (lane >> 4) * 8);
                asm volatile("ldmatrix.sync.aligned.m8n8.x4.shared.b16 {%0,%1,%2,%3}, [%4];"
                    : "=r"(af[mt][0]), "=r"(af[mt][1]), "=r"(af[mt][2]), "=r"(af[mt][3])
                    : "r"(addr));
            }
            uint32_t bfr[4][2];
#pragma unroll
            for (int nt = 0; nt < 4; nt++) {
                unsigned addr = (unsigned)__cvta_generic_to_shared(
                    Bs_s + (wn + nt * 8 + (lane & 7)) * 40 + ks + ((lane >> 3) & 1) * 8);
                asm volatile("ldmatrix.sync.aligned.m8n8.x2.shared.b16 {%0,%1}, [%2];"
                    : "=r"(bfr[nt][0]), "=r"(bfr[nt][1]) : "r"(addr));
            }
#pragma unroll
            for (int mt = 0; mt < 4; mt++)
#pragma unroll
                for (int nt = 0; nt < 4; nt++)
                    asm volatile(
                        "mma.sync.aligned.m16n8k16.row.col.f32.bf16.bf16.f32 "
                        "{%0,%1,%2,%3}, {%4,%5,%6,%7}, {%8,%9}, {%0,%1,%2,%3};"
                        : "+f"(c[mt][nt][0]), "+f"(c[mt][nt][1]),
                          "+f"(c[mt][nt][2]), "+f"(c[mt][nt][3])
                        : "r"(af[mt][0]), "r"(af[mt][1]), "r"(af[mt][2]), "r"(af[mt][3]),
                          "r"(bfr[nt][0]), "r"(bfr[nt][1]));
        }
        __syncthreads();
    }

    const int r0 = lane >> 2, c0 = (lane & 3) * 2;
#pragma unroll
    for (int mt = 0; mt < 4; mt++)
#pragma unroll
        for (int nt = 0; nt < 4; nt++) {
            int row = m0 + wm + mt * 16 + r0;
            int col = n0 + wn + nt * 8 + c0;
            float* p0 = C + (size_t)row * ldc + col;
            float* p1 = C + (size_t)(row + 8) * ldc + col;
            if (acc == 2) {
                atomicAdd(p0,     c[mt][nt][0]); atomicAdd(p0 + 1, c[mt][nt][1]);
                atomicAdd(p1,     c[mt][nt][2]); atomicAdd(p1 + 1, c[mt][nt][3]);
            } else {
                p0[0] = c[mt][nt][0]; p0[1] = c[mt][nt][1];
                p1[0] = c[mt][nt][2]; p1[1] = c[mt][nt][3];
            }
        }
}

// ---------------- SGEMM (fp32 SIMT) ----------------
__global__ void __launch_bounds__(256) sgemm(int M, int N, int K,
                                             const float* __restrict__ A,
                                             const float* __restrict__ B,
                                             const float* __restrict__ bias,
                                             float* __restrict__ C, int act) {
    __shared__ float As[8][128];
    __shared__ float Bs[8][128];
    const int tid  = threadIdx.x;
    const int tx   = tid & 15;
    const int ty   = tid >> 4;
    const int row0 = blockIdx.y * 128;
    const int col0 = blockIdx.x * 128;
    const int a_row = tid >> 1, a_col = (tid & 1) << 2;
    const int b_row = tid >> 5, b_col = (tid & 31) << 2;

    float acc[8][8];
#pragma unroll
    for (int i = 0; i < 8; i++)
#pragma unroll
        for (int j = 0; j < 8; j++) acc[i][j] = 0.f;

    for (int kk = 0; kk < K; kk += 8) {
        float4 av = make_float4(0.f, 0.f, 0.f, 0.f);
        {
            int gm = row0 + a_row, gk = kk + a_col;
            if (gm < M && gk < K)
                av = *reinterpret_cast<const float4*>(A + (size_t)gm * K + gk);
        }
        As[a_col + 0][a_row] = av.x;
        As[a_col + 1][a_row] = av.y;
        As[a_col + 2][a_row] = av.z;
        As[a_col + 3][a_row] = av.w;

        float4 bv = make_float4(0.f, 0.f, 0.f, 0.f);
        {
            int gk = kk + b_row, gn = col0 + b_col;
            if (gk < K && gn < N)
                bv = *reinterpret_cast<const float4*>(B + (size_t)gk * N + gn);
        }
        *reinterpret_cast<float4*>(&Bs[b_row][b_col]) = bv;
        __syncthreads();

#pragma unroll
        for (int k = 0; k < 8; k++) {
            float4 a0 = *reinterpret_cast<const float4*>(&As[k][ty * 8]);
            float4 a1 = *reinterpret_cast<const float4*>(&As[k][ty * 8 + 4]);
            float4 b0 = *reinterpret_cast<const float4*>(&Bs[k][tx * 8]);
            float4 b1 = *reinterpret_cast<const float4*>(&Bs[k][tx * 8 + 4]);
            float a[8] = {a0.x, a0.y, a0.z, a0.w, a1.x, a1.y, a1.z, a1.w};
            float b[8] = {b0.x, b0.y, b0.z, b0.w, b1.x, b1.y, b1.z, b1.w};
#pragma unroll
            for (int i = 0; i < 8; i++)
#pragma unroll
                for (int j = 0; j < 8; j++) acc[i][j] += a[i] * b[j];
        }
        __syncthreads();
    }

#pragma unroll
    for (int i = 0; i < 8; i++) {
        int gm = row0 + ty * 8 + i;
        if (gm >= M) continue;
        float* Cr = C + (size_t)gm * N;
#pragma unroll
        for (int j = 0; j < 8; j++) {
            int gn = col0 + tx * 8 + j;
            if (gn >= N) continue;
            float v = acc[i][j];
            if (bias) v += bias[gn];
            if (act == ACT_RELU) v = fmaxf(v, 0.f);
            else if (act == ACT_SIGM) v = 1.f / (1.f + expf(-v));
            Cr[gn] = v;
        }
    }
}

// ---------------- graph / elementwise kernels ----------------
__global__ void k_edges_m(const int* __restrict__ ei, int E, unsigned char* __restrict__ M) {
    int e = blockIdx.x * blockDim.x + threadIdx.x;
    if (e >= E) return;
    int s = ei[e], d = ei[E + e];
    M[(size_t)s * N0 + d] = 1;
    M[(size_t)d * N0 + s] = 1;
}

__global__ void k_csr_m(const unsigned char* __restrict__ M, int n,
                        int* __restrict__ cnt, int* __restrict__ col,
                        float* __restrict__ val, float* __restrict__ dis) {
    __shared__ int c;
    __shared__ float red[256];
    int row = blockIdx.x;
    if (threadIdx.x == 0) c = 0;
    __syncthreads();
    const unsigned char* Mr = M + (size_t)row * n;
    float lsum = 0.f;
    for (int j = threadIdx.x; j < n; j += 256) {
        float v = (float)Mr[j] + ((j == row) ? 1.f : 0.f);
        if (v != 0.f) {
            int s = atomicAdd(&c, 1);
            col[(size_t)row * DEG + s] = j;
            val[(size_t)row * DEG + s] = v;
            lsum += v;
        }
    }
    red[threadIdx.x] = lsum;
    __syncthreads();
    for (int o = 128; o > 0; o >>= 1) {
        if (threadIdx.x < o) red[threadIdx.x] += red[threadIdx.x + o];
        __syncthreads();
    }
    if (threadIdx.x == 0) { cnt[row] = c; dis[row] = rsqrtf(red[0]); }
}

__global__ void k_dis_b(const __nv_bfloat16* __restrict__ M, int ld, int w,
                        float* __restrict__ dis) {
    __shared__ float red[256];
    int row = blockIdx.x;
    const __nv_bfloat16* Mr = M + (size_t)row * ld;
    float s = 0.f;
    for (int j = threadIdx.x; j < w; j += 256) s += __bfloat162float(Mr[j]);
    red[threadIdx.x] = s;
    __syncthreads();
    for (int o = 128; o > 0; o >>= 1) {
        if (threadIdx.x < o) red[threadIdx.x] += red[threadIdx.x + o];
        __syncthreads();
    }
    if (threadIdx.x == 0) dis[row] = rsqrtf(red[0]);
}

__global__ void k_spmm(const int* __restrict__ cnt, const int* __restrict__ col,
                       const float* __restrict__ val,
                       const float* __restrict__ X, int C,
                       const float* __restrict__ dis,
                       const float* __restrict__ bias, int act,
                       float* __restrict__ S) {
    int row = blockIdx.x, c = threadIdx.x;
    if (c >= C) return;
    int m = cnt[row];
    const int* cr = col + (size_t)row * DEG;
    const float* vr = val + (size_t)row * DEG;
    float acc = 0.f;
    for (int e = 0; e < m; e++) {
        int j = cr[e];
        acc += vr[e] * dis[j] * X[(size_t)j * C + c];
    }
    float v = acc * dis[row];
    if (bias) v += bias[c];
    if (act == ACT_SIGM) v = 1.f / (1.f + expf(-v));
    S[(size_t)row * C + c] = v;
}

__global__ void __launch_bounds__(256) k_spgemm(
        const int* __restrict__ cnt, const int* __restrict__ col,
        const float* __restrict__ val, const int* __restrict__ perm,
        const int* __restrict__ inv, int k, int np,
        __nv_bfloat16* __restrict__ bA1) {
    __shared__ float acc[2048];
    int r = blockIdx.x;
    for (int i = threadIdx.x; i < np; i += 256) acc[i] = 0.f;
    __syncthreads();
    if (r < k) {
        int row = perm[r];
        int m = cnt[row];
        const int* cr = col + (size_t)row * DEG;
        const float* vr = val + (size_t)row * DEG;
        for (int e1 = 0; e1 < m; e1++) {
            int j = cr[e1];
            float w1 = vr[e1];
            int mj = cnt[j];
            const int* cj = col + (size_t)j * DEG;
            const float* vj = val + (size_t)j * DEG;
            for (int e2 = threadIdx.x; e2 < mj; e2 += 256) {
                int cidx = inv[cj[e2]];
                if (cidx >= 0) atomicAdd(&acc[cidx], w1 * vj[e2]);
            }
        }
    }
    __syncthreads();
    __nv_bfloat16* out = bA1 + (size_t)r * np;
    for (int cidx = threadIdx.x; cidx < np; cidx += 256) {
        float v = (r < k) ? ((cidx == r) ? 1.f : acc[cidx]) : 0.f;
        out[cidx] = __float2bfloat16(v);
    }
}

__global__ void k_inv_init(int* __restrict__ inv, int n) {
    int i = blockIdx.x * blockDim.x + threadIdx.x;
    if (i < n) inv[i] = -1;
}
__global__ void k_inv_set(const int* __restrict__ perm, int k, int* __restrict__ inv) {
    int i = blockIdx.x * blockDim.x + threadIdx.x;
    if (i < k) inv[perm[i]] = i;
}

__global__ void k_scale_pack(const float* __restrict__ xw, const float* __restrict__ dis,
                             int n, int np, int C, int Cpad,
                             __nv_bfloat16* __restrict__ zpk) {
    int i = blockIdx.x * blockDim.x + threadIdx.x;
    int W = 2 * Cpad;
    if (i >= np * W) return;
    int r = i / W, cc = i - r * W;
    int colx = (cc < Cpad) ? cc : cc - Cpad;
    float v = (r < n && colx < C) ? dis[r] * xw[(size_t)r * C + colx] : 0.f;
    __nv_bfloat16 hi = __float2bfloat16(v);
    if (cc < Cpad) zpk[i] = hi;
    else           zpk[i] = __float2bfloat16(v - __bfloat162float(hi));
}

__global__ void k_scale_pack_stk(const float* __restrict__ xw, const float* __restrict__ dis,
                                 int n, int np, int C,
                                 __nv_bfloat16* __restrict__ Bp) {
    int i = blockIdx.x * blockDim.x + threadIdx.x;
    int W = 2 * C;
    if (i >= 2 * np * W) return;
    int r = i / W, cc = i - r * W;
    int rr = (r < np) ? r : r - np;
    int colx = (cc < C) ? cc : cc - C;
    float v = (rr < n) ? dis[rr] * xw[(size_t)rr * C + colx] : 0.f;
    __nv_bfloat16 hi = __float2bfloat16(v);
    __nv_bfloat16 lo = __float2bfloat16(v - __bfloat162float(hi));
    bool wantHi = ((r < np) == (cc < C));
    Bp[i] = wantHi ? hi : lo;
}

__global__ void k_packX3(const float* __restrict__ X, int np, int C,
                         __nv_bfloat16* __restrict__ Xp) {
    int i = blockIdx.x * blockDim.x + threadIdx.x;
    int W = 3 * C;
    if (i >= np * W) return;
    int r = i / W, cc = i - r * W;
    int colx = cc; if (colx >= C) colx -= C; if (colx >= C) colx -= C;
    float v = X[(size_t)r * C + colx];
    __nv_bfloat16 hi = __float2bfloat16(v);
    bool isLo = (cc >= C && cc < 2 * C);
    Xp[i] = isLo ? __float2bfloat16(v - __bfloat162float(hi)) : hi;
}

__global__ void k_packW3(const float* __restrict__ W, int K, int N,
                         __nv_bfloat16* __restrict__ Wp) {
    int i = blockIdx.x * blockDim.x + threadIdx.x;
    if (i >= 3 * K * N) return;
    int r = i / N, cc = i - r * N;
    int rr = r; if (rr >= K) rr -= K; if (rr >= K) rr -= K;
    float v = W[(size_t)rr * N + cc];
    __nv_bfloat16 hi = __float2bfloat16(v);
    Wp[i] = (r < 2 * K) ? hi : __float2bfloat16(v - __bfloat162float(hi));
}

__global__ void k_epilogue_sum2(const float* __restrict__ t, int ldt, int half,
                                const float* __restrict__ dis, const float* __restrict__ b,
                                int n, int C, float* __restrict__ out, int act) {
    int i = blockIdx.x * blockDim.x + threadIdx.x;
    if (i >= n * C) return;
    int r = i / C, cc = i - r * C;
    float v = dis[r] * (t[(size_t)r * ldt + cc] + t[(size_t)r * ldt + cc + half]) + b[cc];
    if (act == ACT_RELU) v = fmaxf(v, 0.f);
    else if (act == ACT_SIGM) v = 1.f / (1.f + expf(-v));
    out[i] = v;
}

__global__ void k_crop_pack_X(const float* __restrict__ Augp, int kpad, int k, int np,
                              __nv_bfloat16* __restrict__ X) {
    int i = blockIdx.x * blockDim.x + threadIdx.x;
    if (i >= np * np) return;
    int r = i / np, cc = i - r * np;
    float v = 0.f;
    if (r < k && cc < k) {
        if (r == cc) v = 1.f;
        else {
            int rr = (r < cc) ? r : cc;
            int c2 = (r < cc) ? cc : r;
            v = Augp[(size_t)rr * kpad + c2];
        }
    }
    __nv_bfloat16 hi = __float2bfloat16(v);
    __nv_bfloat16 lo = __float2bfloat16(v - __bfloat162float(hi));
    X[(size_t)r * (2 * np) + cc]      = hi;
    X[(size_t)r * (2 * np) + np + cc] = lo;
}

__global__ void k_gather_rows(const __nv_bfloat16* __restrict__ bApI, int np,
                              const int* __restrict__ perm, int k, int kpad,
                              __nv_bfloat16* __restrict__ G) {
    int i = blockIdx.x * blockDim.x + threadIdx.x;
    if (i >= kpad * np) return;
    int r = i / np, j = i - r * np;
    G[i] = (r < k) ? bApI[(size_t)perm[r] * np + j] : __float2bfloat16(0.f);
}

__global__ void k_gather_PQ_b(const __nv_bfloat16* __restrict__ X2, int np,
                              const int* __restrict__ perm, int k, int kpad,
                              __nv_bfloat16* __restrict__ P,
                              __nv_bfloat16* __restrict__ Q) {
    int i = blockIdx.x * blockDim.x + threadIdx.x;
    int W = 2 * np;
    if (i >= kpad * W) return;
    int r = i / W, j = i - r * W;
    __nv_bfloat16 v = (r < k) ? X2[(size_t)perm[r] * W + j] : __float2bfloat16(0.f);
    P[i] = v;
    int js = (j < np) ? j + np : j - np;
    Q[(size_t)r * W + js] = v;
}

// scores with inline p-norm (each block recomputes ||p||; 512 FLOPs, free)
__global__ void k_scores(const float* __restrict__ h, int n, int C,
                         const float* __restrict__ p,
                         float* __restrict__ score) {
    __shared__ float s_pn;
    int tid = threadIdx.x;
    if (tid < 32) {
        float s = 0.f;
        for (int i = tid; i < C; i += 32) s += p[i] * p[i];
        for (int o = 16; o > 0; o >>= 1) s += __shfl_xor_sync(0xffffffffu, s, o);
        if (tid == 0) s_pn = sqrtf(s);
    }
    __syncthreads();
    int row = blockIdx.x * 8 + (tid >> 5);
    int lane = tid & 31;
    if (row >= n) return;
    const float* hr = h + (size_t)row * C;
    float s = 0.f;
    for (int cc = lane; cc < C; cc += 32) s += hr[cc] * p[cc];
    for (int o = 16; o > 0; o >>= 1) s += __shfl_xor_sync(0xffffffffu, s, o);
    if (lane == 0) score[row] = tanhf(s / s_pn);
}

__global__ void __launch_bounds__(1024) k_topk_sel(const float* __restrict__ score,
                                                   int n, int k, int* __restrict__ perm) {
    __shared__ float sc[4096];
    __shared__ int cnt;
    int tid = threadIdx.x;
    for (int i = tid; i < n; i += 1024) sc[i] = score[i];
    __syncthreads();
    float lo = -1.1f, hi = 1.1f;
    for (int it = 0; it < 40; ++it) {
        float mid = 0.5f * (lo + hi);
        if (tid == 0) cnt = 0;
        __syncthreads();
        int c = 0;
        for (int i = tid; i < n; i += 1024) if (sc[i] > mid) c++;
        if (c) atomicAdd(&cnt, c);
        __syncthreads();
        if (cnt >= k) lo = mid; else hi = mid;
        __syncthreads();
    }
    if (tid == 0) cnt = 0;
    __syncthreads();
    for (int i = tid; i < n; i += 1024)
        if (sc[i] > hi) { int s = atomicAdd(&cnt, 1); perm[s] = i; }
    __syncthreads();
    for (int i = tid; i < n; i += 1024)
        if (sc[i] > lo && sc[i] <= hi) {
            int s = atomicAdd(&cnt, 1);
            if (s < k) perm[s] = i;
        }
}

__global__ void k_gatherX(const float* __restrict__ h, int C,
                          const int* __restrict__ perm, const float* __restrict__ score,
                          int k, float* __restrict__ out) {
    int i = blockIdx.x * blockDim.x + threadIdx.x;
    if (i >= k * C) return;
    int r = i / C, cc = i - r * C;
    int pr = perm[r];
    out[i] = h[(size_t)pr * C + cc] * score[pr];
}

__global__ void k_scatter_add(float* __restrict__ u, const float* __restrict__ h,
                              const int* __restrict__ perm, int k, int C) {
    int i = blockIdx.x * blockDim.x + threadIdx.x;
    if (i >= k * C) return;
    int r = i / C, cc = i - r * C;
    u[(size_t)perm[r] * C + cc] += h[i];
}

// ---------------- host orchestration ----------------
static void run_sgemm(int M, int N, int K, const float* A, const float* B,
                      const float* bias, float* C, int act) {
    dim3 g((N + 127) / 128, (M + 127) / 128);
    sgemm<<<g, 256>>>(M, N, K, A, B, bias, C, act);
}
static void run_nn(int M, int N, int K, const __nv_bfloat16* A, int lda,
                   const __nv_bfloat16* B, int ldb, float* C, int ldc, int acc, int splitk,
                   const float* bias, int act) {
    cudaFuncSetAttribute(hgemm_nn, cudaFuncAttributeMaxDynamicSharedMemorySize, NN_SMEM);
    dim3 g(N / 128, M / 128, splitk);
    hgemm_nn<<<g, 256, NN_SMEM>>>(M, N, K, A, lda, B, ldb, C, ldc, acc, bias, act);
}
static void run_nt_tri(int M, int K, const __nv_bfloat16* A, int lda,
                       const __nv_bfloat16* B, int ldb, float* C, int ldc, int splitk) {
    cudaFuncSetAttribute(hgemm_nt, cudaFuncAttributeMaxDynamicSharedMemorySize, NT_SMEM);
    int T = M / 128;
    dim3 g(T * (T + 1) / 2, 1, splitk);
    hgemm_nt<<<g, 256, NT_SMEM>>>(M, M, K, A, lda, B, ldb, C, ldc, 2, 1);
}

// feature GEMM: splitk tuned so the grid lands at >=128 blocks
static void run_xw_tc(const float* X, int np, int C, const float* W, int N,
                      const float* bias, int act, float* out, int splitk,
                      __nv_bfloat16* Xp, __nv_bfloat16* Wp) {
    int totX = np * 3 * C;
    k_packX3<<<(totX + 255) / 256, 256>>>(X, np, C, Xp);
    int totW = 3 * C * N;
    k_packW3<<<(totW + 255) / 256, 256>>>(W, C, N, Wp);
    if (splitk > 1) {
        cudaMemsetAsync(out, 0, (size_t)np * N * sizeof(float), 0);
        run_nn(np, N, 3 * C, Xp, 3 * C, Wp, N, out, N, 2, splitk, nullptr, ACT_NONE);
    } else {
        run_nn(np, N, 3 * C, Xp, 3 * C, Wp, N, out, N, 0, 1, bias, act);
    }
}

static void run_gcn_exact(const __nv_bfloat16* bApI, int n, int np,
                          const float* X, int inC, const float* W, int outC, const float* b,
                          float* out, int act, int xwsplit, int adjsplit,
                          float* xw, float* t, const float* dis, __nv_bfloat16* zpk,
                          __nv_bfloat16* Xp, __nv_bfloat16* Wp) {
    run_xw_tc(X, np, inC, W, outC, nullptr, ACT_NONE, xw, xwsplit, Xp, Wp);
    int Cpad = outC;
    int W2 = 2 * Cpad;
    int tot = np * W2;
    k_scale_pack<<<(tot + 255) / 256, 256>>>(xw, dis, n, np, outC, Cpad, zpk);
    cudaMemsetAsync(t, 0, (size_t)np * W2 * sizeof(float), 0);
    run_nn(np, W2, np, bApI, np, zpk, W2, t, W2, 2, adjsplit, nullptr, ACT_NONE);
    int nc = n * outC;
    k_epilogue_sum2<<<(nc + 255) / 256, 256>>>(t, W2, Cpad, dis, b, n, outC, out, act);
}

static void run_gcn_split(const __nv_bfloat16* X2, int n, int np,
                          const float* X, int inC, const float* W, int outC, const float* b,
                          float* out, int act, int xwsplit, int adjsplit,
                          float* xw, float* t, const float* dis, __nv_bfloat16* Bp,
                          __nv_bfloat16* Xp, __nv_bfloat16* Wp) {
    run_xw_tc(X, np, inC, W, outC, nullptr, ACT_NONE, xw, xwsplit, Xp, Wp);
    int W2 = 2 * outC;
    int tot = 2 * np * W2;
    k_scale_pack_stk<<<(tot + 255) / 256, 256>>>(xw, dis, n, np, outC, Bp);
    cudaMemsetAsync(t, 0, (size_t)np * W2 * sizeof(float), 0);
    run_nn(np, W2, 2 * np, X2, 2 * np, Bp, W2, t, W2, 2, adjsplit, nullptr, ACT_NONE);
    int nc = n * outC;
    k_epilogue_sum2<<<(nc + 255) / 256, 256>>>(t, W2, outC, dis, b, n, outC, out, act);
}

static void run_scores_topk(const float* h, int n, const float* p, int k,
                            int* perm, float* score) {
    k_scores<<<(n + 7) / 8, 256>>>(h, n, HC, p, score);
    k_topk_sel<<<1, 1024>>>(score, n, k, perm);
}

extern "C" void kernel_launch(void* const* d_in, const int* in_sizes, int n_in,
                              void* d_out, int out_size) {
    const float* x   = (const float*)d_in[0];
    const int*   ei  = (const int*)  d_in[1];
    const float* Wd0 = (const float*)d_in[2];  const float* bd0 = (const float*)d_in[3];
    const float* Wd1 = (const float*)d_in[4];  const float* bd1 = (const float*)d_in[5];
    const float* Wd2 = (const float*)d_in[6];  const float* bd2 = (const float*)d_in[7];
    const float* Wd3 = (const float*)d_in[8];  const float* bd3 = (const float*)d_in[9];
    const float* p1  = (const float*)d_in[10];
    const float* p2  = (const float*)d_in[11];
    const float* p3  = (const float*)d_in[12];
    const float* Wu0 = (const float*)d_in[13]; const float* bu0 = (const float*)d_in[14];
    const float* Wu1 = (const float*)d_in[15]; const float* bu1 = (const float*)d_in[16];
    const float* Wu2 = (const float*)d_in[17]; const float* bu2 = (const float*)d_in[18];
    const int E = in_sizes[1] / 2;

    float *Augp, *h0, *h1, *h2, *h3, *hb, *xw, *t, *u, *sc;
    float *dis0, *dis1, *dis2, *dis3;
    int *pm0, *pm1, *pm2, *inv, *ccnt, *ccol;
    float *cval;
    unsigned char* m0;
    __nv_bfloat16 *bA1, *bX2, *bX3, *G, *Q, *zpk, *Xp, *Wp;
    cudaGetSymbolAddress((void**)&Augp, g_Augp);
    cudaGetSymbolAddress((void**)&h0,  g_h0);
    cudaGetSymbolAddress((void**)&h1,  g_h1);
    cudaGetSymbolAddress((void**)&h2,  g_h2);
    cudaGetSymbolAddress((void**)&h3,  g_h3);
    cudaGetSymbolAddress((void**)&hb,  g_hb);
    cudaGetSymbolAddress((void**)&xw,  g_xw);
    cudaGetSymbolAddress((void**)&t,   g_t);
    cudaGetSymbolAddress((void**)&u,   g_u);
    cudaGetSymbolAddress((void**)&dis0, g_dis0);
    cudaGetSymbolAddress((void**)&dis1, g_dis1);
    cudaGetSymbolAddress((void**)&dis2, g_dis2);
    cudaGetSymbolAddress((void**)&dis3, g_dis3);
    cudaGetSymbolAddress((void**)&sc,  g_sc);
    cudaGetSymbolAddress((void**)&pm0, g_perm0);
    cudaGetSymbolAddress((void**)&pm1, g_perm1);
    cudaGetSymbolAddress((void**)&pm2, g_perm2);
    cudaGetSymbolAddress((void**)&inv, g_inv);
    cudaGetSymbolAddress((void**)&ccnt, g_ccnt);
    cudaGetSymbolAddress((void**)&ccol, g_ccol);
    cudaGetSymbolAddress((void**)&cval, g_cval);
    cudaGetSymbolAddress((void**)&m0,  g_m0);
    cudaGetSymbolAddress((void**)&bA1, g_bA1);
    cudaGetSymbolAddress((void**)&bX2, g_bX2);
    cudaGetSymbolAddress((void**)&bX3, g_bX3);
    cudaGetSymbolAddress((void**)&G,   g_G);
    cudaGetSymbolAddress((void**)&Q,   g_Q);
    cudaGetSymbolAddress((void**)&zpk, g_zpk);
    cudaGetSymbolAddress((void**)&Xp,  g_Xpk);
    cudaGetSymbolAddress((void**)&Wp,  g_Wpk);

    // ---- adjacency mask -> CSR(A0+I) + dis0 ----
    cudaMemsetAsync(m0, 0, (size_t)N0 * N0, 0);
    k_edges_m<<<(E + 255) / 256, 256>>>(ei, E, m0);
    k_csr_m<<<N0, 256>>>(m0, N0, ccnt, ccol, cval, dis0);

    // ---- down level 0 (sparse, exact fp32) ----
    k_spmm<<<N0, INC>>>(ccnt, ccol, cval, x, INC, dis0, nullptr, ACT_NONE, xw);
    run_xw_tc(xw, N0, INC, Wd0, HC, bd0, ACT_RELU, h0, 1, Xp, Wp);  // 128 blocks, fused bias+relu

    // pool0: bA1 = crop([(A0+I)^2]) + I via SpGEMM
    run_scores_topk(h0, N0, p1, KP1, pm0, sc);
    k_inv_init<<<(N0 + 255) / 256, 256>>>(inv, N0);
    k_inv_set<<<(KP1 + 255) / 256, 256>>>(pm0, KP1, inv);
    k_spgemm<<<2048, 256>>>(ccnt, ccol, cval, pm0, inv, KP1, 2048, bA1);
    k_gatherX<<<(KP1 * HC + 255) / 256, 256>>>(h0, HC, pm0, sc, KP1, u);
    k_dis_b<<<KP1, 256>>>(bA1, 2048, 2048, dis1);
    run_gcn_exact(bA1, KP1, 2048, u, HC, Wd1, HC, bd1, h1, ACT_RELU, 4, 2,
                  xw, t, dis1, zpk, Xp, Wp);

    // pool1: A2 submatrix via G@G^T
    run_scores_topk(h1, KP1, p2, KP2, pm1, sc);
    k_gather_rows<<<(1024 * 2048 + 255) / 256, 256>>>(bA1, 2048, pm1, KP2, 1024, G);
    cudaMemsetAsync(Augp, 0, (size_t)1024 * 1024 * sizeof(float), 0);
    run_nt_tri(1024, 2048, G, 2048, G, 2048, Augp, 1024, 8);
    k_gatherX<<<(KP2 * HC + 255) / 256, 256>>>(h1, HC, pm1, sc, KP2, u);
    k_crop_pack_X<<<(1024 * 1024 + 255) / 256, 256>>>(Augp, 1024, KP2, 1024, bX2);
    k_dis_b<<<KP2, 256>>>(bX2, 2048, 2048, dis2);
    run_gcn_split(bX2, KP2, 1024, u, HC, Wd2, HC, bd2, h2, ACT_RELU, 8, 4,
                  xw, t, dis2, zpk, Xp, Wp);

    // pool2: A3 = P@P^T + P@Q^T
    run_scores_topk(h2, KP2, p3, KP3, pm2, sc);
    k_gather_PQ_b<<<(512 * 2048 + 255) / 256, 256>>>(bX2, 1024, pm2, KP3, 512, G, Q);
    cudaMemsetAsync(Augp, 0, (size_t)512 * 512 * sizeof(float), 0);
    run_nt_tri(512, 2048, G, 2048, G, 2048, Augp, 512, 8);
    run_nt_tri(512, 2048, G, 2048, Q, 2048, Augp, 512, 8);
    k_gatherX<<<(KP3 * HC + 255) / 256, 256>>>(h2, HC, pm2, sc, KP3, u);
    k_crop_pack_X<<<(512 * 512 + 255) / 256, 256>>>(Augp, 512, KP3, 512, bX3);
    k_dis_b<<<KP3, 256>>>(bX3, 1024, 1024, dis3);
    run_gcn_split(bX3, KP3, 512, u, HC, Wd3, HC, bd3, h3, ACT_RELU, 8, 8,
                  xw, t, dis3, zpk, Xp, Wp);

    // ---- up path ----
    cudaMemcpyAsync(u, h2, (size_t)KP2 * HC * sizeof(float), cudaMemcpyDeviceToDevice, 0);
    k_scatter_add<<<(KP3 * HC + 255) / 256, 256>>>(u, h3, pm2, KP3, HC);
    run_gcn_split(bX2, KP2, 1024, u, HC, Wu0, HC, bu0, hb, ACT_RELU, 8, 4,
                  xw, t, dis2, zpk, Xp, Wp);

    cudaMemcpyAsync(u, h1, (size_t)KP1 * HC * sizeof(float), cudaMemcpyDeviceToDevice, 0);
    k_scatter_add<<<(KP2 * HC + 255) / 256, 256>>>(u, hb, pm1, KP2, HC);
    run_gcn_exact(bA1, KP1, 2048, u, HC, Wu1, HC, bu1, hb, ACT_RELU, 4, 2,
                  xw, t, dis1, zpk, Xp, Wp);

    cudaMemcpyAsync(u, h0, (size_t)N0 * HC * sizeof(float), cudaMemcpyDeviceToDevice, 0);
    k_scatter_add<<<(KP1 * HC + 255) / 256, 256>>>(u, hb, pm0, KP1, HC);
    run_sgemm(N0, OC, HC, u, Wu2, nullptr, xw, ACT_NONE);
    k_spmm<<<N0, OC>>>(ccnt, ccol, cval, xw, OC, dis0, bu2, ACT_SIGM, (float*)d_out);
}

// round 15
// speedup vs baseline: 2.4332x; 1.1308x over previous
#include <cuda_runtime.h>
#include <cuda_bf16.h>
#include <cstdint>
#include <math.h>

// ---------------- problem constants ----------------
#define N0   4096
#define INC  128
#define HC   512
#define OC   64
#define KP1  2000
#define KP2  1000
#define KP3  500
#define DEG  192

#define ACT_NONE 0
#define ACT_RELU 1
#define ACT_SIGM 2

// packed-weight layout (all weights packed once, upfront)
#define WLEN_D0 (384*512)
#define WSEG    (1536*512)
#define WOFF_D0 0
#define WOFF_D1 (WLEN_D0)
#define WOFF_D2 (WOFF_D1 + WSEG)
#define WOFF_D3 (WOFF_D2 + WSEG)
#define WOFF_U0 (WOFF_D3 + WSEG)
#define WOFF_U1 (WOFF_U0 + WSEG)
#define WOFF_U2 (WOFF_U1 + WSEG)
#define WLEN_U2 (1536*128)
#define WTOT (WOFF_U2 + WLEN_U2)

// ---------------- scratch (device globals; allocation-free) ----------------
__device__ float g_Augp[(size_t)1024*1024];
__device__ float g_h0 [(size_t)N0*HC];
__device__ float g_h1 [(size_t)KP1*HC];
__device__ float g_h2 [(size_t)KP2*HC];
__device__ float g_h3 [(size_t)KP3*HC];
__device__ float g_hb [(size_t)KP1*HC];
__device__ float g_xw [(size_t)N0*HC];
__device__ float g_t  [(size_t)2048*1024];
__device__ float g_dis0[N0];
__device__ float g_dis1[2048];
__device__ float g_dis2[2048];
__device__ float g_dis3[1024];
__device__ float g_sc [N0];
__device__ int   g_perm0[KP1];
__device__ int   g_perm1[KP2];
__device__ int   g_perm2[KP3];
__device__ int   g_inv0[N0];
__device__ int   g_inv1[2048];
__device__ int   g_inv2[1024];
__device__ int   g_ccnt[N0];
__device__ int   g_ccol[(size_t)N0*DEG];
__device__ float g_cval[(size_t)N0*DEG];
__device__ unsigned char g_m0[(size_t)N0*N0];
__device__ __nv_bfloat16 g_bA1 [(size_t)2048*2048];
__device__ __nv_bfloat16 g_bX2 [(size_t)1024*2048];
__device__ __nv_bfloat16 g_bX3 [(size_t)512*1024];
__device__ __nv_bfloat16 g_G  [(size_t)1024*2048];
__device__ __nv_bfloat16 g_Q  [(size_t)512*2048];
__device__ __nv_bfloat16 g_zpk[(size_t)2048*1024];
__device__ __nv_bfloat16 g_Xpk[(size_t)4096*1536];
__device__ __nv_bfloat16 g_Wall[WTOT];

// ---------------- cp.async helpers ----------------
#define CPASYNC16(dst_u32, src_ptr) \
    asm volatile("cp.async.ca.shared.global [%0], [%1], 16;" :: "r"(dst_u32), "l"(src_ptr))
#define CP_COMMIT() asm volatile("cp.async.commit_group;")

#define NN_AS (128*40)
#define NN_BS (32*136)
#define NT_AS (128*40)
#define NT_BS (128*40)
#define NN_SMEM (4 * (NN_AS + NN_BS) * 2)
#define NT_SMEM (4 * (NT_AS + NT_BS) * 2)

// ---------------- NN GEMM: C(MxN) = A(MxK) @ B(KxN), bf16->fp32 ----------------
__global__ void __launch_bounds__(256) hgemm_nn(int M, int N, int K,
        const __nv_bfloat16* __restrict__ A, int lda,
        const __nv_bfloat16* __restrict__ B, int ldb,
        float* __restrict__ C, int ldc, int acc,
        const float* __restrict__ bias, int act) {
    extern __shared__ __nv_bfloat16 dsm[];
    __nv_bfloat16* Asm = dsm;
    __nv_bfloat16* Bsm = dsm + 4 * NN_AS;
    const int tid  = threadIdx.x;
    const int lane = tid & 31;
    const int warp = tid >> 5;
    const int wm = (warp >> 2) * 64;
    const int wn = (warp & 3) * 32;
    const int m0 = blockIdx.y * 128;
    const int n0 = blockIdx.x * 128;
    const int Kc = K / gridDim.z;
    const int k0 = blockIdx.z * Kc;

    const int ar = tid >> 1, ac = (tid & 1) * 16;
    const int br = tid >> 3, bc = (tid & 7) * 16;

    float c[4][4][4];
#pragma unroll
    for (int mt = 0; mt < 4; mt++)
#pragma unroll
        for (int nt = 0; nt < 4; nt++)
#pragma unroll
            for (int r = 0; r < 4; r++) c[mt][nt][r] = 0.f;

    const int ntile = Kc >> 5;

#define NN_LOAD(s, kk) { \
    unsigned da = (unsigned)__cvta_generic_to_shared(Asm + (s) * NN_AS + ar * 40 + ac); \
    const __nv_bfloat16* pa = A + (size_t)(m0 + ar) * lda + (kk) + ac; \
    CPASYNC16(da, pa); CPASYNC16(da + 16, pa + 8); \
    unsigned db = (unsigned)__cvta_generic_to_shared(Bsm + (s) * NN_BS + br * 136 + bc); \
    const __nv_bfloat16* pb = B + (size_t)((kk) + br) * ldb + n0 + bc; \
    CPASYNC16(db, pb); CPASYNC16(db + 16, pb + 8); }

    for (int p = 0; p < 3; ++p) {
        if (p < ntile) NN_LOAD(p, k0 + p * 32);
        CP_COMMIT();
    }

    for (int it = 0; it < ntile; ++it) {
        asm volatile("cp.async.wait_group 2;");
        __syncthreads();
        int pf = it + 3;
        if (pf < ntile) NN_LOAD(pf & 3, k0 + pf * 32);
        CP_COMMIT();

        const int s = it & 3;
        const __nv_bfloat16* As_s = Asm + s * NN_AS;
        const __nv_bfloat16* Bs_s = Bsm + s * NN_BS;
#pragma unroll
        for (int ks = 0; ks < 32; ks += 16) {
            uint32_t af[4][4];
#pragma unroll
            for (int mt = 0; mt < 4; mt++) {
                unsigned addr = (unsigned)__cvta_generic_to_shared(
                    As_s + (wm + mt * 16 + (lane & 15)) * 40 + ks + (lane >> 4) * 8);
                asm volatile("ldmatrix.sync.aligned.m8n8.x4.shared.b16 {%0,%1,%2,%3}, [%4];"
                    : "=r"(af[mt][0]), "=r"(af[mt][1]), "=r"(af[mt][2]), "=r"(af[mt][3])
                    : "r"(addr));
            }
            uint32_t bfr[4][2];
#pragma unroll
            for (int nt = 0; nt < 4; nt++) {
                unsigned addr = (unsigned)__cvta_generic_to_shared(
                    Bs_s + (ks + (lane & 15)) * 136 + wn + nt * 8);
                asm volatile("ldmatrix.sync.aligned.m8n8.x2.trans.shared.b16 {%0,%1}, [%2];"
                    : "=r"(bfr[nt][0]), "=r"(bfr[nt][1]) : "r"(addr));
            }
#pragma unroll
            for (int mt = 0; mt < 4; mt++)
#pragma unroll
                for (int nt = 0; nt < 4; nt++)
                    asm volatile(
                        "mma.sync.aligned.m16n8k16.row.col.f32.bf16.bf16.f32 "
                        "{%0,%1,%2,%3}, {%4,%5,%6,%7}, {%8,%9}, {%0,%1,%2,%3};"
                        : "+f"(c[mt][nt][0]), "+f"(c[mt][nt][1]),
                          "+f"(c[mt][nt][2]), "+f"(c[mt][nt][3])
                        : "r"(af[mt][0]), "r"(af[mt][1]), "r"(af[mt][2]), "r"(af[mt][3]),
                          "r"(bfr[nt][0]), "r"(bfr[nt][1]));
        }
        __syncthreads();
    }

    const int r0 = lane >> 2, c0 = (lane & 3) * 2;
#pragma unroll
    for (int mt = 0; mt < 4; mt++)
#pragma unroll
        for (int nt = 0; nt < 4; nt++) {
            int row = m0 + wm + mt * 16 + r0;
            int col = n0 + wn + nt * 8 + c0;
            float* p0 = C + (size_t)row * ldc + col;
            float* p1 = C + (size_t)(row + 8) * ldc + col;
            if (acc == 2) {
                atomicAdd(p0,     c[mt][nt][0]); atomicAdd(p0 + 1, c[mt][nt][1]);
                atomicAdd(p1,     c[mt][nt][2]); atomicAdd(p1 + 1, c[mt][nt][3]);
            } else {
                float v0 = c[mt][nt][0], v1 = c[mt][nt][1];
                float v2 = c[mt][nt][2], v3 = c[mt][nt][3];
                if (bias) { v0 += bias[col]; v1 += bias[col + 1];
                            v2 += bias[col]; v3 += bias[col + 1]; }
                if (act == ACT_RELU) {
                    v0 = fmaxf(v0, 0.f); v1 = fmaxf(v1, 0.f);
                    v2 = fmaxf(v2, 0.f); v3 = fmaxf(v3, 0.f);
                }
                p0[0] = v0; p0[1] = v1;
                p1[0] = v2; p1[1] = v3;
            }
        }
}

// ---------------- NT GEMM (tri-symmetric option) ----------------
__global__ void __launch_bounds__(256) hgemm_nt(int M, int N, int K,
        const __nv_bfloat16* __restrict__ A, int lda,
        const __nv_bfloat16* __restrict__ B, int ldb,
        float* __restrict__ C, int ldc, int acc, int tri) {
    extern __shared__ __nv_bfloat16 dsm[];
    __nv_bfloat16* Asm = dsm;
    __nv_bfloat16* Bsm = dsm + 4 * NT_AS;
    const int tid  = threadIdx.x;
    const int lane = tid & 31;
    const int warp = tid >> 5;
    const int wm = (warp >> 2) * 64;
    const int wn = (warp & 3) * 32;

    int m0, n0;
    if (tri) {
        int bid = blockIdx.x;
        int by = (int)((sqrtf(8.f * bid + 1.f) - 1.f) * 0.5f);
        while ((by + 1) * (by + 2) / 2 <= bid) by++;
        while (by * (by + 1) / 2 > bid) by--;
        int bx = bid - by * (by + 1) / 2;
        m0 = bx * 128;
        n0 = by * 128;
    } else {
        m0 = blockIdx.y * 128;
        n0 = blockIdx.x * 128;
    }
    const int Kc = K / gridDim.z;
    const int k0 = blockIdx.z * Kc;

    const int ar = tid >> 1, ac = (tid & 1) * 16;

    float c[4][4][4];
#pragma unroll
    for (int mt = 0; mt < 4; mt++)
#pragma unroll
        for (int nt = 0; nt < 4; nt++)
#pragma unroll
            for (int r = 0; r < 4; r++) c[mt][nt][r] = 0.f;

    const int ntile = Kc >> 5;

#define NT_LOAD(s, kk) { \
    unsigned da = (unsigned)__cvta_generic_to_shared(Asm + (s) * NT_AS + ar * 40 + ac); \
    const __nv_bfloat16* pa = A + (size_t)(m0 + ar) * lda + (kk) + ac; \
    CPASYNC16(da, pa); CPASYNC16(da + 16, pa + 8); \
    unsigned db = (unsigned)__cvta_generic_to_shared(Bsm + (s) * NT_BS + ar * 40 + ac); \
    const __nv_bfloat16* pb = B + (size_t)(n0 + ar) * ldb + (kk) + ac; \
    CPASYNC16(db, pb); CPASYNC16(db + 16, pb + 8); }

    for (int p = 0; p < 3; ++p) {
        if (p < ntile) NT_LOAD(p, k0 + p * 32);
        CP_COMMIT();
    }

    for (int it = 0; it < ntile; ++it) {
        asm volatile("cp.async.wait_group 2;");
        __syncthreads();
        int pf = it + 3;
        if (pf < ntile) NT_LOAD(pf & 3, k0 + pf * 32);
        CP_COMMIT();

        const int s = it & 3;
        const __nv_bfloat16* As_s = Asm + s * NT_AS;
        const __nv_bfloat16* Bs_s = Bsm + s * NT_BS;
#pragma unroll
        for (int ks = 0; ks < 32; ks += 16) {
            uint32_t af[4][4];
#pragma unroll
            for (int mt = 0; mt < 4; mt++) {
                unsigned addr = (unsigned)__cvta_generic_to_shared(
                    As_s + (wm + mt * 16 + (lane & 15)) * 40 + ks + (lane >> 4) * 8);
                asm volatile("ldmatrix.sync.aligned.m8n8.x4.shared.b16 {%0,%1,%2,%3}, [%4];"
                    : "=r"(af[mt][0]), "=r"(af[mt][1]), "=r"(af[mt][2]), "=r"(af[mt][3])
                    : "r"(addr));
            }
            uint32_t bfr[4][2];
#pragma unroll
            for (int nt = 0; nt < 4; nt++) {
                unsigned addr = (unsigned)__cvta_generic_to_shared(
                    Bs_s + (wn + nt * 8 + (lane & 7)) * 40 + ks + ((lane >> 3) & 1) * 8);
                asm volatile("ldmatrix.sync.aligned.m8n8.x2.shared.b16 {%0,%1}, [%2];"
                    : "=r"(bfr[nt][0]), "=r"(bfr[nt][1]) : "r"(addr));
            }
#pragma unroll
            for (int mt = 0; mt < 4; mt++)
#pragma unroll
                for (int nt = 0; nt < 4; nt++)
                    asm volatile(
                        "mma.sync.aligned.m16n8k16.row.col.f32.bf16.bf16.f32 "
                        "{%0,%1,%2,%3}, {%4,%5,%6,%7}, {%8,%9}, {%0,%1,%2,%3};"
                        : "+f"(c[mt][nt][0]), "+f"(c[mt][nt][1]),
                          "+f"(c[mt][nt][2]), "+f"(c[mt][nt][3])
                        : "r"(af[mt][0]), "r"(af[mt][1]), "r"(af[mt][2]), "r"(af[mt][3]),
                          "r"(bfr[nt][0]), "r"(bfr[nt][1]));
        }
        __syncthreads();
    }

    const int r0 = lane >> 2, c0 = (lane & 3) * 2;
#pragma unroll
    for (int mt = 0; mt < 4; mt++)
#pragma unroll
        for (int nt = 0; nt < 4; nt++) {
            int row = m0 + wm + mt * 16 + r0;
            int col = n0 + wn + nt * 8 + c0;
            float* p0 = C + (size_t)row * ldc + col;
            float* p1 = C + (size_t)(row + 8) * ldc + col;
            if (acc == 2) {
                atomicAdd(p0,     c[mt][nt][0]); atomicAdd(p0 + 1, c[mt][nt][1]);
                atomicAdd(p1,     c[mt][nt][2]); atomicAdd(p1 + 1, c[mt][nt][3]);
            } else {
                p0[0] = c[mt][nt][0]; p0[1] = c[mt][nt][1];
                p1[0] = c[mt][nt][2]; p1[1] = c[mt][nt][3];
            }
        }
}

// ---------------- graph / elementwise kernels ----------------
__global__ void k_edges_m(const int* __restrict__ ei, int E, unsigned char* __restrict__ M) {
    int e = blockIdx.x * blockDim.x + threadIdx.x;
    if (e >= E) return;
    int s = ei[e], d = ei[E + e];
    M[(size_t)s * N0 + d] = 1;
    M[(size_t)d * N0 + s] = 1;
}

__global__ void k_csr_m(const unsigned char* __restrict__ M, int n,
                        int* __restrict__ cnt, int* __restrict__ col,
                        float* __restrict__ val, float* __restrict__ dis) {
    __shared__ int c;
    __shared__ float red[256];
    int row = blockIdx.x;
    if (threadIdx.x == 0) c = 0;
    __syncthreads();
    const unsigned char* Mr = M + (size_t)row * n;
    float lsum = 0.f;
    for (int j = threadIdx.x; j < n; j += 256) {
        float v = (float)Mr[j] + ((j == row) ? 1.f : 0.f);
        if (v != 0.f) {
            int s = atomicAdd(&c, 1);
            col[(size_t)row * DEG + s] = j;
            val[(size_t)row * DEG + s] = v;
            lsum += v;
        }
    }
    red[threadIdx.x] = lsum;
    __syncthreads();
    for (int o = 128; o > 0; o >>= 1) {
        if (threadIdx.x < o) red[threadIdx.x] += red[threadIdx.x + o];
        __syncthreads();
    }
    if (threadIdx.x == 0) { cnt[row] = c; dis[row] = rsqrtf(red[0]); }
}

__global__ void k_dis_b(const __nv_bfloat16* __restrict__ M, int ld, int w,
                        float* __restrict__ dis) {
    __shared__ float red[256];
    int row = blockIdx.x;
    const __nv_bfloat16* Mr = M + (size_t)row * ld;
    float s = 0.f;
    for (int j = threadIdx.x; j < w; j += 256) s += __bfloat162float(Mr[j]);
    red[threadIdx.x] = s;
    __syncthreads();
    for (int o = 128; o > 0; o >>= 1) {
        if (threadIdx.x < o) red[threadIdx.x] += red[threadIdx.x + o];
        __syncthreads();
    }
    if (threadIdx.x == 0) dis[row] = rsqrtf(red[0]);
}

// SpMM GCN (X has leading dim ldx)
__global__ void k_spmm(const int* __restrict__ cnt, const int* __restrict__ col,
                       const float* __restrict__ val,
                       const float* __restrict__ X, int C, int ldx,
                       const float* __restrict__ dis,
                       const float* __restrict__ bias, int act,
                       float* __restrict__ S) {
    int row = blockIdx.x, c = threadIdx.x;
    if (c >= C) return;
    int m = cnt[row];
    const int* cr = col + (size_t)row * DEG;
    const float* vr = val + (size_t)row * DEG;
    float acc = 0.f;
    for (int e = 0; e < m; e++) {
        int j = cr[e];
        acc += vr[e] * dis[j] * X[(size_t)j * ldx + c];
    }
    float v = acc * dis[row];
    if (bias) v += bias[c];
    if (act == ACT_SIGM) v = 1.f / (1.f + expf(-v));
    S[(size_t)row * C + c] = v;
}

__global__ void __launch_bounds__(256) k_spgemm(
        const int* __restrict__ cnt, const int* __restrict__ col,
        const float* __restrict__ val, const int* __restrict__ perm,
        const int* __restrict__ inv, int k, int np,
        __nv_bfloat16* __restrict__ bA1) {
    __shared__ float acc[2048];
    int r = blockIdx.x;
    for (int i = threadIdx.x; i < np; i += 256) acc[i] = 0.f;
    __syncthreads();
    if (r < k) {
        int row = perm[r];
        int m = cnt[row];
        const int* cr = col + (size_t)row * DEG;
        const float* vr = val + (size_t)row * DEG;
        for (int e1 = 0; e1 < m; e1++) {
            int j = cr[e1];
            float w1 = vr[e1];
            int mj = cnt[j];
            const int* cj = col + (size_t)j * DEG;
            const float* vj = val + (size_t)j * DEG;
            for (int e2 = threadIdx.x; e2 < mj; e2 += 256) {
                int cidx = inv[cj[e2]];
                if (cidx >= 0) atomicAdd(&acc[cidx], w1 * vj[e2]);
            }
        }
    }
    __syncthreads();
    __nv_bfloat16* out = bA1 + (size_t)r * np;
    for (int cidx = threadIdx.x; cidx < np; cidx += 256) {
        float v = (r < k) ? ((cidx == r) ? 1.f : acc[cidx]) : 0.f;
        out[cidx] = __float2bfloat16(v);
    }
}

__global__ void k_inv_init(int* __restrict__ inv, int n) {
    int i = blockIdx.x * blockDim.x + threadIdx.x;
    if (i < n) inv[i] = -1;
}
__global__ void k_inv_set(const int* __restrict__ perm, int k, int* __restrict__ inv) {
    int i = blockIdx.x * blockDim.x + threadIdx.x;
    if (i < k) inv[perm[i]] = i;
}

__global__ void k_scale_pack(const float* __restrict__ xw, const float* __restrict__ dis,
                             int n, int np, int C, int Cpad,
                             __nv_bfloat16* __restrict__ zpk) {
    int i = blockIdx.x * blockDim.x + threadIdx.x;
    int W = 2 * Cpad;
    if (i >= np * W) return;
    int r = i / W, cc = i - r * W;
    int colx = (cc < Cpad) ? cc : cc - Cpad;
    float v = (r < n && colx < C) ? dis[r] * xw[(size_t)r * C + colx] : 0.f;
    __nv_bfloat16 hi = __float2bfloat16(v);
    if (cc < Cpad) zpk[i] = hi;
    else           zpk[i] = __float2bfloat16(v - __bfloat162float(hi));
}

__global__ void k_scale_pack_stk(const float* __restrict__ xw, const float* __restrict__ dis,
                                 int n, int np, int C,
                                 __nv_bfloat16* __restrict__ Bp) {
    int i = blockIdx.x * blockDim.x + threadIdx.x;
    int W = 2 * C;
    if (i >= 2 * np * W) return;
    int r = i / W, cc = i - r * W;
    int rr = (r < np) ? r : r - np;
    int colx = (cc < C) ? cc : cc - C;
    float v = (rr < n) ? dis[rr] * xw[(size_t)rr * C + colx] : 0.f;
    __nv_bfloat16 hi = __float2bfloat16(v);
    __nv_bfloat16 lo = __float2bfloat16(v - __bfloat162float(hi));
    bool wantHi = ((r < np) == (cc < C));
    Bp[i] = wantHi ? hi : lo;
}

// standalone feature pack (level-0 down: spmm output -> [hi|lo|hi])
__global__ void k_packX3(const float* __restrict__ X, int np, int C,
                         __nv_bfloat16* __restrict__ Xp) {
    int i = blockIdx.x * blockDim.x + threadIdx.x;
    int W = 3 * C;
    if (i >= np * W) return;
    int r = i / W, cc = i - r * W;
    int colx = cc; if (colx >= C) colx -= C; if (colx >= C) colx -= C;
    float v = X[(size_t)r * C + colx];
    __nv_bfloat16 hi = __float2bfloat16(v);
    bool isLo = (cc >= C && cc < 2 * C);
    Xp[i] = isLo ? __float2bfloat16(v - __bfloat162float(hi)) : hi;
}

// fused pool gather + pack: Xp[r] = [hi|lo|hi] of h[perm[r]]*score[perm[r]]
__global__ void k_pool_pack(const float* __restrict__ h, int C,
                            const int* __restrict__ perm, const float* __restrict__ score,
                            int k, int kpad, __nv_bfloat16* __restrict__ Xp) {
    int i = blockIdx.x * blockDim.x + threadIdx.x;
    int W = 3 * C;
    if (i >= kpad * W) return;
    int r = i / W, cc = i - r * W;
    int colx = cc; if (colx >= C) colx -= C; if (colx >= C) colx -= C;
    float v = 0.f;
    if (r < k) {
        int pr = perm[r];
        v = h[(size_t)pr * C + colx] * score[pr];
    }
    __nv_bfloat16 hi = __float2bfloat16(v);
    bool isLo = (cc >= C && cc < 2 * C);
    Xp[i] = isLo ? __float2bfloat16(v - __bfloat162float(hi)) : hi;
}

// fused unpool + pack: Xp[r] = [hi|lo|hi] of (res[r] + hs[inv[r]] if inv[r]>=0)
__global__ void k_unpool_pack(const float* __restrict__ res, const float* __restrict__ hs,
                              const int* __restrict__ inv, int n, int np, int C,
                              __nv_bfloat16* __restrict__ Xp) {
    int i = blockIdx.x * blockDim.x + threadIdx.x;
    int W = 3 * C;
    if (i >= np * W) return;
    int r = i / W, cc = i - r * W;
    int colx = cc; if (colx >= C) colx -= C; if (colx >= C) colx -= C;
    float v = 0.f;
    if (r < n) {
        v = res[(size_t)r * C + colx];
        int s = inv[r];
        if (s >= 0) v += hs[(size_t)s * C + colx];
    }
    __nv_bfloat16 hi = __float2bfloat16(v);
    bool isLo = (cc >= C && cc < 2 * C);
    Xp[i] = isLo ? __float2bfloat16(v - __bfloat162float(hi)) : hi;
}

__device__ __forceinline__ __nv_bfloat16 packw_elem(const float* W, int K, int N, int Npad, int idx) {
    int r = idx / Npad, cc = idx - r * Npad;
    int rr = r; if (rr >= K) rr -= K; if (rr >= K) rr -= K;
    float v = (cc < N) ? W[(size_t)rr * N + cc] : 0.f;
    __nv_bfloat16 hi = __float2bfloat16(v);
    return (r < 2 * K) ? hi : __float2bfloat16(v - __bfloat162float(hi));
}

// pack ALL weights once: [Whi;Whi;Wlo] per layer, Wu2 padded to 128 cols
__global__ void k_packW_all(const float* __restrict__ Wd0, const float* __restrict__ Wd1,
                            const float* __restrict__ Wd2, const float* __restrict__ Wd3,
                            const float* __restrict__ Wu0, const float* __restrict__ Wu1,
                            const float* __restrict__ Wu2, __nv_bfloat16* __restrict__ out) {
    int i = blockIdx.x * blockDim.x + threadIdx.x;
    if (i >= WTOT) return;
    if (i < WOFF_D1)      out[i] = packw_elem(Wd0, 128, 512, 512, i - WOFF_D0);
    else if (i < WOFF_D2) out[i] = packw_elem(Wd1, 512, 512, 512, i - WOFF_D1);
    else if (i < WOFF_D3) out[i] = packw_elem(Wd2, 512, 512, 512, i - WOFF_D2);
    else if (i < WOFF_U0) out[i] = packw_elem(Wd3, 512, 512, 512, i - WOFF_D3);
    else if (i < WOFF_U1) out[i] = packw_elem(Wu0, 512, 512, 512, i - WOFF_U0);
    else if (i < WOFF_U2) out[i] = packw_elem(Wu1, 512, 512, 512, i - WOFF_U1);
    else                  out[i] = packw_elem(Wu2, 512, 64, 128, i - WOFF_U2);
}

__global__ void k_epilogue_sum2(const float* __restrict__ t, int ldt, int half,
                                const float* __restrict__ dis, const float* __restrict__ b,
                                int n, int C, float* __restrict__ out, int act) {
    int i = blockIdx.x * blockDim.x + threadIdx.x;
    if (i >= n * C) return;
    int r = i / C, cc = i - r * C;
    float v = dis[r] * (t[(size_t)r * ldt + cc] + t[(size_t)r * ldt + cc + half]) + b[cc];
    if (act == ACT_RELU) v = fmaxf(v, 0.f);
    else if (act == ACT_SIGM) v = 1.f / (1.f + expf(-v));
    out[i] = v;
}

__global__ void k_crop_pack_X(const float* __restrict__ Augp, int kpad, int k, int np,
                              __nv_bfloat16* __restrict__ X) {
    int i = blockIdx.x * blockDim.x + threadIdx.x;
    if (i >= np * np) return;
    int r = i / np, cc = i - r * np;
    float v = 0.f;
    if (r < k && cc < k) {
        if (r == cc) v = 1.f;
        else {
            int rr = (r < cc) ? r : cc;
            int c2 = (r < cc) ? cc : r;
            v = Augp[(size_t)rr * kpad + c2];
        }
    }
    __nv_bfloat16 hi = __float2bfloat16(v);
    __nv_bfloat16 lo = __float2bfloat16(v - __bfloat162float(hi));
    X[(size_t)r * (2 * np) + cc]      = hi;
    X[(size_t)r * (2 * np) + np + cc] = lo;
}

__global__ void k_gather_rows(const __nv_bfloat16* __restrict__ bApI, int np,
                              const int* __restrict__ perm, int k, int kpad,
                              __nv_bfloat16* __restrict__ G) {
    int i = blockIdx.x * blockDim.x + threadIdx.x;
    if (i >= kpad * np) return;
    int r = i / np, j = i - r * np;
    G[i] = (r < k) ? bApI[(size_t)perm[r] * np + j] : __float2bfloat16(0.f);
}

__global__ void k_gather_PQ_b(const __nv_bfloat16* __restrict__ X2, int np,
                              const int* __restrict__ perm, int k, int kpad,
                              __nv_bfloat16* __restrict__ P,
                              __nv_bfloat16* __restrict__ Q) {
    int i = blockIdx.x * blockDim.x + threadIdx.x;
    int W = 2 * np;
    if (i >= kpad * W) return;
    int r = i / W, j = i - r * W;
    __nv_bfloat16 v = (r < k) ? X2[(size_t)perm[r] * W + j] : __float2bfloat16(0.f);
    P[i] = v;
    int js = (j < np) ? j + np : j - np;
    Q[(size_t)r * W + js] = v;
}

// scores with inline p-norm
__global__ void k_scores(const float* __restrict__ h, int n, int C,
                         const float* __restrict__ p,
                         float* __restrict__ score) {
    __shared__ float s_pn;
    int tid = threadIdx.x;
    if (tid < 32) {
        float s = 0.f;
        for (int i = tid; i < C; i += 32) s += p[i] * p[i];
        for (int o = 16; o > 0; o >>= 1) s += __shfl_xor_sync(0xffffffffu, s, o);
        if (tid == 0) s_pn = sqrtf(s);
    }
    __syncthreads();
    int row = blockIdx.x * 8 + (tid >> 5);
    int lane = tid & 31;
    if (row >= n) return;
    const float* hr = h + (size_t)row * C;
    float s = 0.f;
    for (int cc = lane; cc < C; cc += 32) s += hr[cc] * p[cc];
    for (int o = 16; o > 0; o >>= 1) s += __shfl_xor_sync(0xffffffffu, s, o);
    if (lane == 0) score[row] = tanhf(s / s_pn);
}

__global__ void __launch_bounds__(1024) k_topk_sel(const float* __restrict__ score,
                                                   int n, int k, int* __restrict__ perm) {
    __shared__ float sc[4096];
    __shared__ int cnt;
    int tid = threadIdx.x;
    for (int i = tid; i < n; i += 1024) sc[i] = score[i];
    __syncthreads();
    float lo = -1.1f, hi = 1.1f;
    for (int it = 0; it < 40; ++it) {
        float mid = 0.5f * (lo + hi);
        if (tid == 0) cnt = 0;
        __syncthreads();
        int c = 0;
        for (int i = tid; i < n; i += 1024) if (sc[i] > mid) c++;
        if (c) atomicAdd(&cnt, c);
        __syncthreads();
        if (cnt >= k) lo = mid; else hi = mid;
        __syncthreads();
    }
    if (tid == 0) cnt = 0;
    __syncthreads();
    for (int i = tid; i < n; i += 1024)
        if (sc[i] > hi) { int s = atomicAdd(&cnt, 1); perm[s] = i; }
    __syncthreads();
    for (int i = tid; i < n; i += 1024)
        if (sc[i] > lo && sc[i] <= hi) {
            int s = atomicAdd(&cnt, 1);
            if (s < k) perm[s] = i;
        }
}

// ---------------- host orchestration ----------------
static void run_nn(int M, int N, int K, const __nv_bfloat16* A, int lda,
                   const __nv_bfloat16* B, int ldb, float* C, int ldc, int acc, int splitk,
                   const float* bias, int act) {
    cudaFuncSetAttribute(hgemm_nn, cudaFuncAttributeMaxDynamicSharedMemorySize, NN_SMEM);
    dim3 g(N / 128, M / 128, splitk);
    hgemm_nn<<<g, 256, NN_SMEM>>>(M, N, K, A, lda, B, ldb, C, ldc, acc, bias, act);
}
static void run_nt_tri(int M, int K, const __nv_bfloat16* A, int lda,
                       const __nv_bfloat16* B, int ldb, float* C, int ldc, int splitk) {
    cudaFuncSetAttribute(hgemm_nt, cudaFuncAttributeMaxDynamicSharedMemorySize, NT_SMEM);
    int T = M / 128;
    dim3 g(T * (T + 1) / 2, 1, splitk);
    hgemm_nt<<<g, 256, NT_SMEM>>>(M, M, K, A, lda, B, ldb, C, ldc, 2, 1);
}

// feature GEMM on pre-packed operands: out = Xp @ Wp  (K = 3*inC)
static void run_xw_pre(const __nv_bfloat16* Xp, int np, int K3,
                       const __nv_bfloat16* Wp, int N,
                       const float* bias, int act, float* out, int splitk) {
    if (splitk > 1) {
        cudaMemsetAsync(out, 0, (size_t)np * N * sizeof(float), 0);
        run_nn(np, N, K3, Xp, K3, Wp, N, out, N, 2, splitk, nullptr, ACT_NONE);
    } else {
        run_nn(np, N, K3, Xp, K3, Wp, N, out, N, 0, 1, bias, act);
    }
}

// GCN with pre-packed feature operand Xp (K3 = 3*inC)
static void run_gcn_exact(const __nv_bfloat16* bApI, int n, int np,
                          const __nv_bfloat16* Xp, int K3,
                          const __nv_bfloat16* Wp, int outC, const float* b,
                          float* out, int act, int xwsplit, int adjsplit,
                          float* xw, float* t, const float* dis, __nv_bfloat16* zpk) {
    run_xw_pre(Xp, np, K3, Wp, outC, nullptr, ACT_NONE, xw, xwsplit);
    int Cpad = outC;
    int W2 = 2 * Cpad;
    int tot = np * W2;
    k_scale_pack<<<(tot + 255) / 256, 256>>>(xw, dis, n, np, outC, Cpad, zpk);
    cudaMemsetAsync(t, 0, (size_t)np * W2 * sizeof(float), 0);
    run_nn(np, W2, np, bApI, np, zpk, W2, t, W2, 2, adjsplit, nullptr, ACT_NONE);
    int nc = n * outC;
    k_epilogue_sum2<<<(nc + 255) / 256, 256>>>(t, W2, Cpad, dis, b, n, outC, out, act);
}

static void run_gcn_split(const __nv_bfloat16* X2, int n, int np,
                          const __nv_bfloat16* Xp, int K3,
                          const __nv_bfloat16* Wp, int outC, const float* b,
                          float* out, int act, int xwsplit, int adjsplit,
                          float* xw, float* t, const float* dis, __nv_bfloat16* Bp) {
    run_xw_pre(Xp, np, K3, Wp, outC, nullptr, ACT_NONE, xw, xwsplit);
    int W2 = 2 * outC;
    int tot = 2 * np * W2;
    k_scale_pack_stk<<<(tot + 255) / 256, 256>>>(xw, dis, n, np, outC, Bp);
    cudaMemsetAsync(t, 0, (size_t)np * W2 * sizeof(float), 0);
    run_nn(np, W2, 2 * np, X2, 2 * np, Bp, W2, t, W2, 2, adjsplit, nullptr, ACT_NONE);
    int nc = n * outC;
    k_epilogue_sum2<<<(nc + 255) / 256, 256>>>(t, W2, outC, dis, b, n, outC, out, act);
}

static void run_scores_topk(const float* h, int n, const float* p, int k,
                            int* perm, float* score) {
    k_scores<<<(n + 7) / 8, 256>>>(h, n, HC, p, score);
    k_topk_sel<<<1, 1024>>>(score, n, k, perm);
}

extern "C" void kernel_launch(void* const* d_in, const int* in_sizes, int n_in,
                              void* d_out, int out_size) {
    const float* x   = (const float*)d_in[0];
    const int*   ei  = (const int*)  d_in[1];
    const float* Wd0 = (const float*)d_in[2];  const float* bd0 = (const float*)d_in[3];
    const float* Wd1 = (const float*)d_in[4];  const float* bd1 = (const float*)d_in[5];
    const float* Wd2 = (const float*)d_in[6];  const float* bd2 = (const float*)d_in[7];
    const float* Wd3 = (const float*)d_in[8];  const float* bd3 = (const float*)d_in[9];
    const float* p1  = (const float*)d_in[10];
    const float* p2  = (const float*)d_in[11];
    const float* p3  = (const float*)d_in[12];
    const float* Wu0 = (const float*)d_in[13]; const float* bu0 = (const float*)d_in[14];
    const float* Wu1 = (const float*)d_in[15]; const float* bu1 = (const float*)d_in[16];
    const float* Wu2 = (const float*)d_in[17]; const float* bu2 = (const float*)d_in[18];
    const int E = in_sizes[1] / 2;

    float *Augp, *h0, *h1, *h2, *h3, *hb, *xw, *t, *sc;
    float *dis0, *dis1, *dis2, *dis3;
    int *pm0, *pm1, *pm2, *inv0, *inv1, *inv2, *ccnt, *ccol;
    float *cval;
    unsigned char* m0;
    __nv_bfloat16 *bA1, *bX2, *bX3, *G, *Q, *zpk, *Xp, *Wall;
    cudaGetSymbolAddress((void**)&Augp, g_Augp);
    cudaGetSymbolAddress((void**)&h0,  g_h0);
    cudaGetSymbolAddress((void**)&h1,  g_h1);
    cudaGetSymbolAddress((void**)&h2,  g_h2);
    cudaGetSymbolAddress((void**)&h3,  g_h3);
    cudaGetSymbolAddress((void**)&hb,  g_hb);
    cudaGetSymbolAddress((void**)&xw,  g_xw);
    cudaGetSymbolAddress((void**)&t,   g_t);
    cudaGetSymbolAddress((void**)&dis0, g_dis0);
    cudaGetSymbolAddress((void**)&dis1, g_dis1);
    cudaGetSymbolAddress((void**)&dis2, g_dis2);
    cudaGetSymbolAddress((void**)&dis3, g_dis3);
    cudaGetSymbolAddress((void**)&sc,  g_sc);
    cudaGetSymbolAddress((void**)&pm0, g_perm0);
    cudaGetSymbolAddress((void**)&pm1, g_perm1);
    cudaGetSymbolAddress((void**)&pm2, g_perm2);
    cudaGetSymbolAddress((void**)&inv0, g_inv0);
    cudaGetSymbolAddress((void**)&inv1, g_inv1);
    cudaGetSymbolAddress((void**)&inv2, g_inv2);
    cudaGetSymbolAddress((void**)&ccnt, g_ccnt);
    cudaGetSymbolAddress((void**)&ccol, g_ccol);
    cudaGetSymbolAddress((void**)&cval, g_cval);
    cudaGetSymbolAddress((void**)&m0,  g_m0);
    cudaGetSymbolAddress((void**)&bA1, g_bA1);
    cudaGetSymbolAddress((void**)&bX2, g_bX2);
    cudaGetSymbolAddress((void**)&bX3, g_bX3);
    cudaGetSymbolAddress((void**)&G,   g_G);
    cudaGetSymbolAddress((void**)&Q,   g_Q);
    cudaGetSymbolAddress((void**)&zpk, g_zpk);
    cudaGetSymbolAddress((void**)&Xp,  g_Xpk);
    cudaGetSymbolAddress((void**)&Wall, g_Wall);

    // ---- upfront: pack all weights; adjacency mask -> CSR + dis0 ----
    k_packW_all<<<(WTOT + 255) / 256, 256>>>(Wd0, Wd1, Wd2, Wd3, Wu0, Wu1, Wu2, Wall);
    cudaMemsetAsync(m0, 0, (size_t)N0 * N0, 0);
    k_edges_m<<<(E + 255) / 256, 256>>>(ei, E, m0);
    k_csr_m<<<N0, 256>>>(m0, N0, ccnt, ccol, cval, dis0);

    // ---- down level 0 (sparse, exact fp32) ----
    k_spmm<<<N0, INC>>>(ccnt, ccol, cval, x, INC, INC, dis0, nullptr, ACT_NONE, xw);
    k_packX3<<<(N0 * 384 + 255) / 256, 256>>>(xw, N0, INC, Xp);
    run_xw_pre(Xp, N0, 384, Wall + WOFF_D0, HC, bd0, ACT_RELU, h0, 1);

    // pool0: bA1 = crop([(A0+I)^2]) + I via SpGEMM; features via fused pool-pack
    run_scores_topk(h0, N0, p1, KP1, pm0, sc);
    k_inv_init<<<(N0 + 255) / 256, 256>>>(inv0, N0);
    k_inv_set<<<(KP1 + 255) / 256, 256>>>(pm0, KP1, inv0);
    k_spgemm<<<2048, 256>>>(ccnt, ccol, cval, pm0, inv0, KP1, 2048, bA1);
    k_pool_pack<<<(2048 * 1536 + 255) / 256, 256>>>(h0, HC, pm0, sc, KP1, 2048, Xp);
    k_dis_b<<<KP1, 256>>>(bA1, 2048, 2048, dis1);
    run_gcn_exact(bA1, KP1, 2048, Xp, 1536, Wall + WOFF_D1, HC, bd1, h1, ACT_RELU, 4, 2,
                  xw, t, dis1, zpk);

    // pool1: A2 submatrix via G@G^T
    run_scores_topk(h1, KP1, p2, KP2, pm1, sc);
    k_inv_init<<<(2048 + 255) / 256, 256>>>(inv1, 2048);
    k_inv_set<<<(KP2 + 255) / 256, 256>>>(pm1, KP2, inv1);
    k_gather_rows<<<(1024 * 2048 + 255) / 256, 256>>>(bA1, 2048, pm1, KP2, 1024, G);
    cudaMemsetAsync(Augp, 0, (size_t)1024 * 1024 * sizeof(float), 0);
    run_nt_tri(1024, 2048, G, 2048, G, 2048, Augp, 1024, 8);
    k_pool_pack<<<(1024 * 1536 + 255) / 256, 256>>>(h1, HC, pm1, sc, KP2, 1024, Xp);
    k_crop_pack_X<<<(1024 * 1024 + 255) / 256, 256>>>(Augp, 1024, KP2, 1024, bX2);
    k_dis_b<<<KP2, 256>>>(bX2, 2048, 2048, dis2);
    run_gcn_split(bX2, KP2, 1024, Xp, 1536, Wall + WOFF_D2, HC, bd2, h2, ACT_RELU, 8, 4,
                  xw, t, dis2, zpk);

    // pool2: A3 = P@P^T + P@Q^T
    run_scores_topk(h2, KP2, p3, KP3, pm2, sc);
    k_inv_init<<<(1024 + 255) / 256, 256>>>(inv2, 1024);
    k_inv_set<<<(KP3 + 255) / 256, 256>>>(pm2, KP3, inv2);
    k_gather_PQ_b<<<(512 * 2048 + 255) / 256, 256>>>(bX2, 1024, pm2, KP3, 512, G, Q);
    cudaMemsetAsync(Augp, 0, (size_t)512 * 512 * sizeof(float), 0);
    run_nt_tri(512, 2048, G, 2048, G, 2048, Augp, 512, 8);
    run_nt_tri(512, 2048, G, 2048, Q, 2048, Augp, 512, 8);
    k_pool_pack<<<(512 * 1536 + 255) / 256, 256>>>(h2, HC, pm2, sc, KP3, 512, Xp);
    k_crop_pack_X<<<(512 * 512 + 255) / 256, 256>>>(Augp, 512, KP3, 512, bX3);
    k_dis_b<<<KP3, 256>>>(bX3, 1024, 1024, dis3);
    run_gcn_split(bX3, KP3, 512, Xp, 1536, Wall + WOFF_D3, HC, bd3, h3, ACT_RELU, 8, 8,
                  xw, t, dis3, zpk);

    // ---- up path (fused unpool + pack) ----
    k_unpool_pack<<<(1024 * 1536 + 255) / 256, 256>>>(h2, h3, inv2, KP2, 1024, HC, Xp);
    run_gcn_split(bX2, KP2, 1024, Xp, 1536, Wall + WOFF_U0, HC, bu0, hb, ACT_RELU, 8, 4,
                  xw, t, dis2, zpk);

    k_unpool_pack<<<(2048 * 1536 + 255) / 256, 256>>>(h1, hb, inv1, KP1, 2048, HC, Xp);
    run_gcn_exact(bA1, KP1, 2048, Xp, 1536, Wall + WOFF_U1, HC, bu1, hb, ACT_RELU, 4, 2,
                  xw, t, dis1, zpk);

    k_unpool_pack<<<(4096 * 1536 + 255) / 256, 256>>>(h0, hb, inv0, N0, 4096, HC, Xp);
    cudaMemsetAsync(xw, 0, (size_t)N0 * 128 * sizeof(float), 0);
    run_nn(N0, 128, 1536, Xp, 1536, Wall + WOFF_U2, 128, xw, 128, 2, 8, nullptr, ACT_NONE);
    k_spmm<<<N0, OC>>>(ccnt, ccol, cval, xw, OC, 128, dis0, bu2, ACT_SIGM, (float*)d_out);
}

// round 16
// speedup vs baseline: 2.5927x; 1.0655x over previous
#include <cuda_runtime.h>
#include <cuda_bf16.h>
#include <cstdint>
#include <math.h>

// ---------------- problem constants ----------------
#define N0   4096
#define INC  128
#define HC   512
#define OC   64
#define KP1  2000
#define KP2  1000
#define KP3  500
#define DEG  192

#define ACT_NONE 0
#define ACT_RELU 1
#define ACT_SIGM 2

// packed-weight layout
#define WLEN_D0 (384*512)
#define WSEG    (1536*512)
#define WOFF_D0 0
#define WOFF_D1 (WLEN_D0)
#define WOFF_D2 (WOFF_D1 + WSEG)
#define WOFF_D3 (WOFF_D2 + WSEG)
#define WOFF_U0 (WOFF_D3 + WSEG)
#define WOFF_U1 (WOFF_U0 + WSEG)
#define WOFF_U2 (WOFF_U1 + WSEG)
#define WLEN_U2 (1536*128)
#define WTOT (WOFF_U2 + WLEN_U2)

// ---------------- scratch ----------------
__device__ float g_Augp[(size_t)1024*1024];
__device__ float g_h0 [(size_t)N0*HC];
__device__ float g_h1 [(size_t)KP1*HC];
__device__ float g_h2 [(size_t)KP2*HC];
__device__ float g_h3 [(size_t)KP3*HC];
__device__ float g_hb [(size_t)KP1*HC];
__device__ float g_xw [(size_t)N0*HC];
__device__ float g_t  [(size_t)2048*1024];
__device__ float g_dis0[N0];
__device__ float g_dis1[2048];
__device__ float g_dis2[2048];
__device__ float g_dis3[1024];
__device__ float g_sc [N0];
__device__ int   g_perm0[KP1];
__device__ int   g_perm1[KP2];
__device__ int   g_perm2[KP3];
__device__ int   g_inv0[N0];
__device__ int   g_inv1[2048];
__device__ int   g_inv2[1024];
__device__ int   g_ccnt[N0];
__device__ int   g_ccol[(size_t)N0*DEG];
__device__ float g_cval[(size_t)N0*DEG];
__device__ unsigned char g_m0[(size_t)N0*N0];
__device__ __nv_bfloat16 g_bA1 [(size_t)2048*2048];
__device__ __nv_bfloat16 g_bX2 [(size_t)1024*2048];
__device__ __nv_bfloat16 g_bX3 [(size_t)512*1024];
__device__ __nv_bfloat16 g_G  [(size_t)1024*2048];
__device__ __nv_bfloat16 g_Q  [(size_t)512*2048];
__device__ __nv_bfloat16 g_zpk[(size_t)2048*1024];
__device__ __nv_bfloat16 g_Xpk[(size_t)4096*1536];
__device__ __nv_bfloat16 g_Wall[WTOT];

// ---------------- cp.async helpers ----------------
#define CPASYNC16(dst_u32, src_ptr) \
    asm volatile("cp.async.ca.shared.global [%0], [%1], 16;" :: "r"(dst_u32), "l"(src_ptr))
#define CP_COMMIT() asm volatile("cp.async.commit_group;")

#define NN_AS (128*40)
#define NN_BS (32*136)
#define NT_AS (128*40)
#define NT_BS (128*40)
#define NN_SMEM (4 * (NN_AS + NN_BS) * 2)
#define NT_SMEM (4 * (NT_AS + NT_BS) * 2)

// ---------------- NN GEMM ----------------
__global__ void __launch_bounds__(256) hgemm_nn(int M, int N, int K,
        const __nv_bfloat16* __restrict__ A, int lda,
        const __nv_bfloat16* __restrict__ B, int ldb,
        float* __restrict__ C, int ldc, int acc,
        const float* __restrict__ bias, int act) {
    extern __shared__ __nv_bfloat16 dsm[];
    __nv_bfloat16* Asm = dsm;
    __nv_bfloat16* Bsm = dsm + 4 * NN_AS;
    const int tid  = threadIdx.x;
    const int lane = tid & 31;
    const int warp = tid >> 5;
    const int wm = (warp >> 2) * 64;
    const int wn = (warp & 3) * 32;
    const int m0 = blockIdx.y * 128;
    const int n0 = blockIdx.x * 128;
    const int Kc = K / gridDim.z;
    const int k0 = blockIdx.z * Kc;

    const int ar = tid >> 1, ac = (tid & 1) * 16;
    const int br = tid >> 3, bc = (tid & 7) * 16;

    float c[4][4][4];
#pragma unroll
    for (int mt = 0; mt < 4; mt++)
#pragma unroll
        for (int nt = 0; nt < 4; nt++)
#pragma unroll
            for (int r = 0; r < 4; r++) c[mt][nt][r] = 0.f;

    const int ntile = Kc >> 5;

#define NN_LOAD(s, kk) { \
    unsigned da = (unsigned)__cvta_generic_to_shared(Asm + (s) * NN_AS + ar * 40 + ac); \
    const __nv_bfloat16* pa = A + (size_t)(m0 + ar) * lda + (kk) + ac; \
    CPASYNC16(da, pa); CPASYNC16(da + 16, pa + 8); \
    unsigned db = (unsigned)__cvta_generic_to_shared(Bsm + (s) * NN_BS + br * 136 + bc); \
    const __nv_bfloat16* pb = B + (size_t)((kk) + br) * ldb + n0 + bc; \
    CPASYNC16(db, pb); CPASYNC16(db + 16, pb + 8); }

    for (int p = 0; p < 3; ++p) {
        if (p < ntile) NN_LOAD(p, k0 + p * 32);
        CP_COMMIT();
    }

    for (int it = 0; it < ntile; ++it) {
        asm volatile("cp.async.wait_group 2;");
        __syncthreads();
        int pf = it + 3;
        if (pf < ntile) NN_LOAD(pf & 3, k0 + pf * 32);
        CP_COMMIT();

        const int s = it & 3;
        const __nv_bfloat16* As_s = Asm + s * NN_AS;
        const __nv_bfloat16* Bs_s = Bsm + s * NN_BS;
#pragma unroll
        for (int ks = 0; ks < 32; ks += 16) {
            uint32_t af[4][4];
#pragma unroll
            for (int mt = 0; mt < 4; mt++) {
                unsigned addr = (unsigned)__cvta_generic_to_shared(
                    As_s + (wm + mt * 16 + (lane & 15)) * 40 + ks + (lane >> 4) * 8);
                asm volatile("ldmatrix.sync.aligned.m8n8.x4.shared.b16 {%0,%1,%2,%3}, [%4];"
                    : "=r"(af[mt][0]), "=r"(af[mt][1]), "=r"(af[mt][2]), "=r"(af[mt][3])
                    : "r"(addr));
            }
            uint32_t bfr[4][2];
#pragma unroll
            for (int nt = 0; nt < 4; nt++) {
                unsigned addr = (unsigned)__cvta_generic_to_shared(
                    Bs_s + (ks + (lane & 15)) * 136 + wn + nt * 8);
                asm volatile("ldmatrix.sync.aligned.m8n8.x2.trans.shared.b16 {%0,%1}, [%2];"
                    : "=r"(bfr[nt][0]), "=r"(bfr[nt][1]) : "r"(addr));
            }
#pragma unroll
            for (int mt = 0; mt < 4; mt++)
#pragma unroll
                for (int nt = 0; nt < 4; nt++)
                    asm volatile(
                        "mma.sync.aligned.m16n8k16.row.col.f32.bf16.bf16.f32 "
                        "{%0,%1,%2,%3}, {%4,%5,%6,%7}, {%8,%9}, {%0,%1,%2,%3};"
                        : "+f"(c[mt][nt][0]), "+f"(c[mt][nt][1]),
                          "+f"(c[mt][nt][2]), "+f"(c[mt][nt][3])
                        : "r"(af[mt][0]), "r"(af[mt][1]), "r"(af[mt][2]), "r"(af[mt][3]),
                          "r"(bfr[nt][0]), "r"(bfr[nt][1]));
        }
        __syncthreads();
    }

    const int r0 = lane >> 2, c0 = (lane & 3) * 2;
#pragma unroll
    for (int mt = 0; mt < 4; mt++)
#pragma unroll
        for (int nt = 0; nt < 4; nt++) {
            int row = m0 + wm + mt * 16 + r0;
            int col = n0 + wn + nt * 8 + c0;
            float* p0 = C + (size_t)row * ldc + col;
            float* p1 = C + (size_t)(row + 8) * ldc + col;
            if (acc == 2) {
                atomicAdd(p0,     c[mt][nt][0]); atomicAdd(p0 + 1, c[mt][nt][1]);
                atomicAdd(p1,     c[mt][nt][2]); atomicAdd(p1 + 1, c[mt][nt][3]);
            } else {
                float v0 = c[mt][nt][0], v1 = c[mt][nt][1];
                float v2 = c[mt][nt][2], v3 = c[mt][nt][3];
                if (bias) { v0 += bias[col]; v1 += bias[col + 1];
                            v2 += bias[col]; v3 += bias[col + 1]; }
                if (act == ACT_RELU) {
                    v0 = fmaxf(v0, 0.f); v1 = fmaxf(v1, 0.f);
                    v2 = fmaxf(v2, 0.f); v3 = fmaxf(v3, 0.f);
                }
                p0[0] = v0; p0[1] = v1;
                p1[0] = v2; p1[1] = v3;
            }
        }
}

// ---------------- NT GEMM (tri-symmetric option) ----------------
__global__ void __launch_bounds__(256) hgemm_nt(int M, int N, int K,
        const __nv_bfloat16* __restrict__ A, int lda,
        const __nv_bfloat16* __restrict__ B, int ldb,
        float* __restrict__ C, int ldc, int acc, int tri) {
    extern __shared__ __nv_bfloat16 dsm[];
    __nv_bfloat16* Asm = dsm;
    __nv_bfloat16* Bsm = dsm + 4 * NT_AS;
    const int tid  = threadIdx.x;
    const int lane = tid & 31;
    const int warp = tid >> 5;
    const int wm = (warp >> 2) * 64;
    const int wn = (warp & 3) * 32;

    int m0, n0;
    if (tri) {
        int bid = blockIdx.x;
        int by = (int)((sqrtf(8.f * bid + 1.f) - 1.f) * 0.5f);
        while ((by + 1) * (by + 2) / 2 <= bid) by++;
        while (by * (by + 1) / 2 > bid) by--;
        int bx = bid - by * (by + 1) / 2;
        m0 = bx * 128;
        n0 = by * 128;
    } else {
        m0 = blockIdx.y * 128;
        n0 = blockIdx.x * 128;
    }
    const int Kc = K / gridDim.z;
    const int k0 = blockIdx.z * Kc;

    const int ar = tid >> 1, ac = (tid & 1) * 16;

    float c[4][4][4];
#pragma unroll
    for (int mt = 0; mt < 4; mt++)
#pragma unroll
        for (int nt = 0; nt < 4; nt++)
#pragma unroll
            for (int r = 0; r < 4; r++) c[mt][nt][r] = 0.f;

    const int ntile = Kc >> 5;

#define NT_LOAD(s, kk) { \
    unsigned da = (unsigned)__cvta_generic_to_shared(Asm + (s) * NT_AS + ar * 40 + ac); \
    const __nv_bfloat16* pa = A + (size_t)(m0 + ar) * lda + (kk) + ac; \
    CPASYNC16(da, pa); CPASYNC16(da + 16, pa + 8); \
    unsigned db = (unsigned)__cvta_generic_to_shared(Bsm + (s) * NT_BS + ar * 40 + ac); \
    const __nv_bfloat16* pb = B + (size_t)(n0 + ar) * ldb + (kk) + ac; \
    CPASYNC16(db, pb); CPASYNC16(db + 16, pb + 8); }

    for (int p = 0; p < 3; ++p) {
        if (p < ntile) NT_LOAD(p, k0 + p * 32);
        CP_COMMIT();
    }

    for (int it = 0; it < ntile; ++it) {
        asm volatile("cp.async.wait_group 2;");
        __syncthreads();
        int pf = it + 3;
        if (pf < ntile) NT_LOAD(pf & 3, k0 + pf * 32);
        CP_COMMIT();

        const int s = it & 3;
        const __nv_bfloat16* As_s = Asm + s * NT_AS;
        const __nv_bfloat16* Bs_s = Bsm + s * NT_BS;
#pragma unroll
        for (int ks = 0; ks < 32; ks += 16) {
            uint32_t af[4][4];
#pragma unroll
            for (int mt = 0; mt < 4; mt++) {
                unsigned addr = (unsigned)__cvta_generic_to_shared(
                    As_s + (wm + mt * 16 + (lane & 15)) * 40 + ks + (lane >> 4) * 8);
                asm volatile("ldmatrix.sync.aligned.m8n8.x4.shared.b16 {%0,%1,%2,%3}, [%4];"
                    : "=r"(af[mt][0]), "=r"(af[mt][1]), "=r"(af[mt][2]), "=r"(af[mt][3])
                    : "r"(addr));
            }
            uint32_t bfr[4][2];
#pragma unroll
            for (int nt = 0; nt < 4; nt++) {
                unsigned addr = (unsigned)__cvta_generic_to_shared(
                    Bs_s + (wn + nt * 8 + (lane & 7)) * 40 + ks + ((lane >> 3) & 1) * 8);
                asm volatile("ldmatrix.sync.aligned.m8n8.x2.shared.b16 {%0,%1}, [%2];"
                    : "=r"(bfr[nt][0]), "=r"(bfr[nt][1]) : "r"(addr));
            }
#pragma unroll
            for (int mt = 0; mt < 4; mt++)
#pragma unroll
                for (int nt = 0; nt < 4; nt++)
                    asm volatile(
                        "mma.sync.aligned.m16n8k16.row.col.f32.bf16.bf16.f32 "
                        "{%0,%1,%2,%3}, {%4,%5,%6,%7}, {%8,%9}, {%0,%1,%2,%3};"
                        : "+f"(c[mt][nt][0]), "+f"(c[mt][nt][1]),
                          "+f"(c[mt][nt][2]), "+f"(c[mt][nt][3])
                        : "r"(af[mt][0]), "r"(af[mt][1]), "r"(af[mt][2]), "r"(af[mt][3]),
                          "r"(bfr[nt][0]), "r"(bfr[nt][1]));
        }
        __syncthreads();
    }

    const int r0 = lane >> 2, c0 = (lane & 3) * 2;
#pragma unroll
    for (int mt = 0; mt < 4; mt++)
#pragma unroll
        for (int nt = 0; nt < 4; nt++) {
            int row = m0 + wm + mt * 16 + r0;
            int col = n0 + wn + nt * 8 + c0;
            float* p0 = C + (size_t)row * ldc + col;
            float* p1 = C + (size_t)(row + 8) * ldc + col;
            if (acc == 2) {
                atomicAdd(p0,     c[mt][nt][0]); atomicAdd(p0 + 1, c[mt][nt][1]);
                atomicAdd(p1,     c[mt][nt][2]); atomicAdd(p1 + 1, c[mt][nt][3]);
            } else {
                p0[0] = c[mt][nt][0]; p0[1] = c[mt][nt][1];
                p1[0] = c[mt][nt][2]; p1[1] = c[mt][nt][3];
            }
        }
}

// ---------------- graph / elementwise kernels ----------------
__global__ void k_edges_m(const int* __restrict__ ei, int E, unsigned char* __restrict__ M) {
    int e = blockIdx.x * blockDim.x + threadIdx.x;
    if (e >= E) return;
    int s = ei[e], d = ei[E + e];
    M[(size_t)s * N0 + d] = 1;
    M[(size_t)d * N0 + s] = 1;
}

__global__ void k_csr_m(const unsigned char* __restrict__ M, int n,
                        int* __restrict__ cnt, int* __restrict__ col,
                        float* __restrict__ val, float* __restrict__ dis) {
    __shared__ int c;
    __shared__ float red[256];
    int row = blockIdx.x;
    if (threadIdx.x == 0) c = 0;
    __syncthreads();
    const unsigned char* Mr = M + (size_t)row * n;
    float lsum = 0.f;
    for (int j = threadIdx.x; j < n; j += 256) {
        float v = (float)Mr[j] + ((j == row) ? 1.f : 0.f);
        if (v != 0.f) {
            int s = atomicAdd(&c, 1);
            col[(size_t)row * DEG + s] = j;
            val[(size_t)row * DEG + s] = v;
            lsum += v;
        }
    }
    red[threadIdx.x] = lsum;
    __syncthreads();
    for (int o = 128; o > 0; o >>= 1) {
        if (threadIdx.x < o) red[threadIdx.x] += red[threadIdx.x + o];
        __syncthreads();
    }
    if (threadIdx.x == 0) { cnt[row] = c; dis[row] = rsqrtf(red[0]); }
}

__global__ void k_dis_b(const __nv_bfloat16* __restrict__ M, int ld, int w,
                        float* __restrict__ dis) {
    __shared__ float red[256];
    int row = blockIdx.x;
    const __nv_bfloat16* Mr = M + (size_t)row * ld;
    float s = 0.f;
    for (int j = threadIdx.x; j < w; j += 256) s += __bfloat162float(Mr[j]);
    red[threadIdx.x] = s;
    __syncthreads();
    for (int o = 128; o > 0; o >>= 1) {
        if (threadIdx.x < o) red[threadIdx.x] += red[threadIdx.x + o];
        __syncthreads();
    }
    if (threadIdx.x == 0) dis[row] = rsqrtf(red[0]);
}

// SpMM GCN, 4-way edge-unrolled for MLP (X has leading dim ldx)
__global__ void k_spmm(const int* __restrict__ cnt, const int* __restrict__ col,
                       const float* __restrict__ val,
                       const float* __restrict__ X, int C, int ldx,
                       const float* __restrict__ dis,
                       const float* __restrict__ bias, int act,
                       float* __restrict__ S) {
    int row = blockIdx.x, c = threadIdx.x;
    if (c >= C) return;
    int m = cnt[row];
    const int* cr = col + (size_t)row * DEG;
    const float* vr = val + (size_t)row * DEG;
    float a0 = 0.f, a1 = 0.f, a2 = 0.f, a3 = 0.f;
    int e = 0;
    for (; e + 3 < m; e += 4) {
        int j0 = cr[e], j1 = cr[e + 1], j2 = cr[e + 2], j3 = cr[e + 3];
        float w0 = vr[e] * dis[j0], w1 = vr[e + 1] * dis[j1];
        float w2 = vr[e + 2] * dis[j2], w3 = vr[e + 3] * dis[j3];
        a0 += w0 * X[(size_t)j0 * ldx + c];
        a1 += w1 * X[(size_t)j1 * ldx + c];
        a2 += w2 * X[(size_t)j2 * ldx + c];
        a3 += w3 * X[(size_t)j3 * ldx + c];
    }
    for (; e < m; e++) {
        int j = cr[e];
        a0 += vr[e] * dis[j] * X[(size_t)j * ldx + c];
    }
    float v = ((a0 + a1) + (a2 + a3)) * dis[row];
    if (bias) v += bias[c];
    if (act == ACT_SIGM) v = 1.f / (1.f + expf(-v));
    S[(size_t)row * C + c] = v;
}

// SpGEMM pool0: warp-per-outer-edge parallelization (8 warps)
__global__ void __launch_bounds__(256) k_spgemm(
        const int* __restrict__ cnt, const int* __restrict__ col,
        const float* __restrict__ val, const int* __restrict__ perm,
        const int* __restrict__ inv, int k, int np,
        __nv_bfloat16* __restrict__ bA1) {
    __shared__ float acc[2048];
    int r = blockIdx.x;
    for (int i = threadIdx.x; i < np; i += 256) acc[i] = 0.f;
    __syncthreads();
    if (r < k) {
        int row = perm[r];
        int m = cnt[row];
        const int* cr = col + (size_t)row * DEG;
        const float* vr = val + (size_t)row * DEG;
        int warp = threadIdx.x >> 5, lane = threadIdx.x & 31;
        for (int e1 = warp; e1 < m; e1 += 8) {
            int j = cr[e1];
            float w1 = vr[e1];
            int mj = cnt[j];
            const int* cj = col + (size_t)j * DEG;
            const float* vj = val + (size_t)j * DEG;
            for (int e2 = lane; e2 < mj; e2 += 32) {
                int cidx = inv[cj[e2]];
                if (cidx >= 0) atomicAdd(&acc[cidx], w1 * vj[e2]);
            }
        }
    }
    __syncthreads();
    __nv_bfloat16* out = bA1 + (size_t)r * np;
    for (int cidx = threadIdx.x; cidx < np; cidx += 256) {
        float v = (r < k) ? ((cidx == r) ? 1.f : acc[cidx]) : 0.f;
        out[cidx] = __float2bfloat16(v);
    }
}

__global__ void k_scale_pack(const float* __restrict__ xw, const float* __restrict__ dis,
                             int n, int np, int C, int Cpad,
                             __nv_bfloat16* __restrict__ zpk) {
    int i = blockIdx.x * blockDim.x + threadIdx.x;
    int W = 2 * Cpad;
    if (i >= np * W) return;
    int r = i / W, cc = i - r * W;
    int colx = (cc < Cpad) ? cc : cc - Cpad;
    float v = (r < n && colx < C) ? dis[r] * xw[(size_t)r * C + colx] : 0.f;
    __nv_bfloat16 hi = __float2bfloat16(v);
    if (cc < Cpad) zpk[i] = hi;
    else           zpk[i] = __float2bfloat16(v - __bfloat162float(hi));
}

__global__ void k_scale_pack_stk(const float* __restrict__ xw, const float* __restrict__ dis,
                                 int n, int np, int C,
                                 __nv_bfloat16* __restrict__ Bp) {
    int i = blockIdx.x * blockDim.x + threadIdx.x;
    int W = 2 * C;
    if (i >= 2 * np * W) return;
    int r = i / W, cc = i - r * W;
    int rr = (r < np) ? r : r - np;
    int colx = (cc < C) ? cc : cc - C;
    float v = (rr < n) ? dis[rr] * xw[(size_t)rr * C + colx] : 0.f;
    __nv_bfloat16 hi = __float2bfloat16(v);
    __nv_bfloat16 lo = __float2bfloat16(v - __bfloat162float(hi));
    bool wantHi = ((r < np) == (cc < C));
    Bp[i] = wantHi ? hi : lo;
}

__global__ void k_packX3(const float* __restrict__ X, int np, int C,
                         __nv_bfloat16* __restrict__ Xp) {
    int i = blockIdx.x * blockDim.x + threadIdx.x;
    int W = 3 * C;
    if (i >= np * W) return;
    int r = i / W, cc = i - r * W;
    int colx = cc; if (colx >= C) colx -= C; if (colx >= C) colx -= C;
    float v = X[(size_t)r * C + colx];
    __nv_bfloat16 hi = __float2bfloat16(v);
    bool isLo = (cc >= C && cc < 2 * C);
    Xp[i] = isLo ? __float2bfloat16(v - __bfloat162float(hi)) : hi;
}

__global__ void k_pool_pack(const float* __restrict__ h, int C,
                            const int* __restrict__ perm, const float* __restrict__ score,
                            int k, int kpad, __nv_bfloat16* __restrict__ Xp) {
    int i = blockIdx.x * blockDim.x + threadIdx.x;
    int W = 3 * C;
    if (i >= kpad * W) return;
    int r = i / W, cc = i - r * W;
    int colx = cc; if (colx >= C) colx -= C; if (colx >= C) colx -= C;
    float v = 0.f;
    if (r < k) {
        int pr = perm[r];
        v = h[(size_t)pr * C + colx] * score[pr];
    }
    __nv_bfloat16 hi = __float2bfloat16(v);
    bool isLo = (cc >= C && cc < 2 * C);
    Xp[i] = isLo ? __float2bfloat16(v - __bfloat162float(hi)) : hi;
}

__global__ void k_unpool_pack(const float* __restrict__ res, const float* __restrict__ hs,
                              const int* __restrict__ inv, int n, int np, int C,
                              __nv_bfloat16* __restrict__ Xp) {
    int i = blockIdx.x * blockDim.x + threadIdx.x;
    int W = 3 * C;
    if (i >= np * W) return;
    int r = i / W, cc = i - r * W;
    int colx = cc; if (colx >= C) colx -= C; if (colx >= C) colx -= C;
    float v = 0.f;
    if (r < n) {
        v = res[(size_t)r * C + colx];
        int s = inv[r];
        if (s >= 0) v += hs[(size_t)s * C + colx];
    }
    __nv_bfloat16 hi = __float2bfloat16(v);
    bool isLo = (cc >= C && cc < 2 * C);
    Xp[i] = isLo ? __float2bfloat16(v - __bfloat162float(hi)) : hi;
}

__device__ __forceinline__ __nv_bfloat16 packw_elem(const float* W, int K, int N, int Npad, int idx) {
    int r = idx / Npad, cc = idx - r * Npad;
    int rr = r; if (rr >= K) rr -= K; if (rr >= K) rr -= K;
    float v = (cc < N) ? W[(size_t)rr * N + cc] : 0.f;
    __nv_bfloat16 hi = __float2bfloat16(v);
    return (r < 2 * K) ? hi : __float2bfloat16(v - __bfloat162float(hi));
}

__global__ void k_packW_all(const float* __restrict__ Wd0, const float* __restrict__ Wd1,
                            const float* __restrict__ Wd2, const float* __restrict__ Wd3,
                            const float* __restrict__ Wu0, const float* __restrict__ Wu1,
                            const float* __restrict__ Wu2, __nv_bfloat16* __restrict__ out) {
    int i = blockIdx.x * blockDim.x + threadIdx.x;
    if (i >= WTOT) return;
    if (i < WOFF_D1)      out[i] = packw_elem(Wd0, 128, 512, 512, i - WOFF_D0);
    else if (i < WOFF_D2) out[i] = packw_elem(Wd1, 512, 512, 512, i - WOFF_D1);
    else if (i < WOFF_D3) out[i] = packw_elem(Wd2, 512, 512, 512, i - WOFF_D2);
    else if (i < WOFF_U0) out[i] = packw_elem(Wd3, 512, 512, 512, i - WOFF_D3);
    else if (i < WOFF_U1) out[i] = packw_elem(Wu0, 512, 512, 512, i - WOFF_U0);
    else if (i < WOFF_U2) out[i] = packw_elem(Wu1, 512, 512, 512, i - WOFF_U1);
    else                  out[i] = packw_elem(Wu2, 512, 64, 128, i - WOFF_U2);
}

__global__ void k_epilogue_sum2(const float* __restrict__ t, int ldt, int half,
                                const float* __restrict__ dis, const float* __restrict__ b,
                                int n, int C, float* __restrict__ out, int act) {
    int i = blockIdx.x * blockDim.x + threadIdx.x;
    if (i >= n * C) return;
    int r = i / C, cc = i - r * C;
    float v = dis[r] * (t[(size_t)r * ldt + cc] + t[(size_t)r * ldt + cc + half]) + b[cc];
    if (act == ACT_RELU) v = fmaxf(v, 0.f);
    else if (act == ACT_SIGM) v = 1.f / (1.f + expf(-v));
    out[i] = v;
}

__global__ void k_crop_pack_X(const float* __restrict__ Augp, int kpad, int k, int np,
                              __nv_bfloat16* __restrict__ X) {
    int i = blockIdx.x * blockDim.x + threadIdx.x;
    if (i >= np * np) return;
    int r = i / np, cc = i - r * np;
    float v = 0.f;
    if (r < k && cc < k) {
        if (r == cc) v = 1.f;
        else {
            int rr = (r < cc) ? r : cc;
            int c2 = (r < cc) ? cc : r;
            v = Augp[(size_t)rr * kpad + c2];
        }
    }
    __nv_bfloat16 hi = __float2bfloat16(v);
    __nv_bfloat16 lo = __float2bfloat16(v - __bfloat162float(hi));
    X[(size_t)r * (2 * np) + cc]      = hi;
    X[(size_t)r * (2 * np) + np + cc] = lo;
}

__global__ void k_gather_rows(const __nv_bfloat16* __restrict__ bApI, int np,
                              const int* __restrict__ perm, int k, int kpad,
                              __nv_bfloat16* __restrict__ G) {
    int i = blockIdx.x * blockDim.x + threadIdx.x;
    if (i >= kpad * np) return;
    int r = i / np, j = i - r * np;
    G[i] = (r < k) ? bApI[(size_t)perm[r] * np + j] : __float2bfloat16(0.f);
}

__global__ void k_gather_PQ_b(const __nv_bfloat16* __restrict__ X2, int np,
                              const int* __restrict__ perm, int k, int kpad,
                              __nv_bfloat16* __restrict__ P,
                              __nv_bfloat16* __restrict__ Q) {
    int i = blockIdx.x * blockDim.x + threadIdx.x;
    int W = 2 * np;
    if (i >= kpad * W) return;
    int r = i / W, j = i - r * W;
    __nv_bfloat16 v = (r < k) ? X2[(size_t)perm[r] * W + j] : __float2bfloat16(0.f);
    P[i] = v;
    int js = (j < np) ? j + np : j - np;
    Q[(size_t)r * W + js] = v;
}

// scores with inline p-norm
__global__ void k_scores(const float* __restrict__ h, int n, int C,
                         const float* __restrict__ p,
                         float* __restrict__ score) {
    __shared__ float s_pn;
    int tid = threadIdx.x;
    if (tid < 32) {
        float s = 0.f;
        for (int i = tid; i < C; i += 32) s += p[i] * p[i];
        for (int o = 16; o > 0; o >>= 1) s += __shfl_xor_sync(0xffffffffu, s, o);
        if (tid == 0) s_pn = sqrtf(s);
    }
    __syncthreads();
    int row = blockIdx.x * 8 + (tid >> 5);
    int lane = tid & 31;
    if (row >= n) return;
    const float* hr = h + (size_t)row * C;
    float s = 0.f;
    for (int cc = lane; cc < C; cc += 32) s += hr[cc] * p[cc];
    for (int o = 16; o > 0; o >>= 1) s += __shfl_xor_sync(0xffffffffu, s, o);
    if (lane == 0) score[row] = tanhf(s / s_pn);
}

// top-k select with fused inv construction; warp-aggregated counting
__global__ void __launch_bounds__(1024) k_topk_sel(const float* __restrict__ score,
                                                   int n, int k, int* __restrict__ perm,
                                                   int* __restrict__ inv) {
    __shared__ float sc[4096];
    __shared__ int cnt;
    int tid = threadIdx.x;
    for (int i = tid; i < n; i += 1024) { sc[i] = score[i]; inv[i] = -1; }
    __syncthreads();
    float lo = -1.1f, hi = 1.1f;
    for (int it = 0; it < 40; ++it) {
        float mid = 0.5f * (lo + hi);
        if (tid == 0) cnt = 0;
        __syncthreads();
        int c = 0;
        for (int i = tid; i < n; i += 1024) if (sc[i] > mid) c++;
        for (int o = 16; o > 0; o >>= 1) c += __shfl_xor_sync(0xffffffffu, c, o);
        if ((tid & 31) == 0 && c) atomicAdd(&cnt, c);
        __syncthreads();
        if (cnt >= k) lo = mid; else hi = mid;
        __syncthreads();
    }
    if (tid == 0) cnt = 0;
    __syncthreads();
    for (int i = tid; i < n; i += 1024)
        if (sc[i] > hi) { int s = atomicAdd(&cnt, 1); perm[s] = i; inv[i] = s; }
    __syncthreads();
    for (int i = tid; i < n; i += 1024)
        if (sc[i] > lo && sc[i] <= hi) {
            int s = atomicAdd(&cnt, 1);
            if (s < k) { perm[s] = i; inv[i] = s; }
        }
}

// ---------------- host orchestration ----------------
static void run_nn(int M, int N, int K, const __nv_bfloat16* A, int lda,
                   const __nv_bfloat16* B, int ldb, float* C, int ldc, int acc, int splitk,
                   const float* bias, int act) {
    cudaFuncSetAttribute(hgemm_nn, cudaFuncAttributeMaxDynamicSharedMemorySize, NN_SMEM);
    dim3 g(N / 128, M / 128, splitk);
    hgemm_nn<<<g, 256, NN_SMEM>>>(M, N, K, A, lda, B, ldb, C, ldc, acc, bias, act);
}
static void run_nt_tri(int M, int K, const __nv_bfloat16* A, int lda,
                       const __nv_bfloat16* B, int ldb, float* C, int ldc, int splitk) {
    cudaFuncSetAttribute(hgemm_nt, cudaFuncAttributeMaxDynamicSharedMemorySize, NT_SMEM);
    int T = M / 128;
    dim3 g(T * (T + 1) / 2, 1, splitk);
    hgemm_nt<<<g, 256, NT_SMEM>>>(M, M, K, A, lda, B, ldb, C, ldc, 2, 1);
}

static void run_xw_pre(const __nv_bfloat16* Xp, int np, int K3,
                       const __nv_bfloat16* Wp, int N,
                       const float* bias, int act, float* out, int splitk) {
    if (splitk > 1) {
        cudaMemsetAsync(out, 0, (size_t)np * N * sizeof(float), 0);
        run_nn(np, N, K3, Xp, K3, Wp, N, out, N, 2, splitk, nullptr, ACT_NONE);
    } else {
        run_nn(np, N, K3, Xp, K3, Wp, N, out, N, 0, 1, bias, act);
    }
}

static void run_gcn_exact(const __nv_bfloat16* bApI, int n, int np,
                          const __nv_bfloat16* Xp, int K3,
                          const __nv_bfloat16* Wp, int outC, const float* b,
                          float* out, int act, int xwsplit, int adjsplit,
                          float* xw, float* t, const float* dis, __nv_bfloat16* zpk) {
    run_xw_pre(Xp, np, K3, Wp, outC, nullptr, ACT_NONE, xw, xwsplit);
    int Cpad = outC;
    int W2 = 2 * Cpad;
    int tot = np * W2;
    k_scale_pack<<<(tot + 255) / 256, 256>>>(xw, dis, n, np, outC, Cpad, zpk);
    cudaMemsetAsync(t, 0, (size_t)np * W2 * sizeof(float), 0);
    run_nn(np, W2, np, bApI, np, zpk, W2, t, W2, 2, adjsplit, nullptr, ACT_NONE);
    int nc = n * outC;
    k_epilogue_sum2<<<(nc + 255) / 256, 256>>>(t, W2, Cpad, dis, b, n, outC, out, act);
}

static void run_gcn_split(const __nv_bfloat16* X2, int n, int np,
                          const __nv_bfloat16* Xp, int K3,
                          const __nv_bfloat16* Wp, int outC, const float* b,
                          float* out, int act, int xwsplit, int adjsplit,
                          float* xw, float* t, const float* dis, __nv_bfloat16* Bp) {
    run_xw_pre(Xp, np, K3, Wp, outC, nullptr, ACT_NONE, xw, xwsplit);
    int W2 = 2 * outC;
    int tot = 2 * np * W2;
    k_scale_pack_stk<<<(tot + 255) / 256, 256>>>(xw, dis, n, np, outC, Bp);
    cudaMemsetAsync(t, 0, (size_t)np * W2 * sizeof(float), 0);
    run_nn(np, W2, 2 * np, X2, 2 * np, Bp, W2, t, W2, 2, adjsplit, nullptr, ACT_NONE);
    int nc = n * outC;
    k_epilogue_sum2<<<(nc + 255) / 256, 256>>>(t, W2, outC, dis, b, n, outC, out, act);
}

static void run_scores_topk(const float* h, int n, const float* p, int k,
                            int* perm, int* inv, float* score) {
    k_scores<<<(n + 7) / 8, 256>>>(h, n, HC, p, score);
    k_topk_sel<<<1, 1024>>>(score, n, k, perm, inv);
}

extern "C" void kernel_launch(void* const* d_in, const int* in_sizes, int n_in,
                              void* d_out, int out_size) {
    const float* x   = (const float*)d_in[0];
    const int*   ei  = (const int*)  d_in[1];
    const float* Wd0 = (const float*)d_in[2];  const float* bd0 = (const float*)d_in[3];
    const float* Wd1 = (const float*)d_in[4];  const float* bd1 = (const float*)d_in[5];
    const float* Wd2 = (const float*)d_in[6];  const float* bd2 = (const float*)d_in[7];
    const float* Wd3 = (const float*)d_in[8];  const float* bd3 = (const float*)d_in[9];
    const float* p1  = (const float*)d_in[10];
    const float* p2  = (const float*)d_in[11];
    const float* p3  = (const float*)d_in[12];
    const float* Wu0 = (const float*)d_in[13]; const float* bu0 = (const float*)d_in[14];
    const float* Wu1 = (const float*)d_in[15]; const float* bu1 = (const float*)d_in[16];
    const float* Wu2 = (const float*)d_in[17]; const float* bu2 = (const float*)d_in[18];
    const int E = in_sizes[1] / 2;

    float *Augp, *h0, *h1, *h2, *h3, *hb, *xw, *t, *sc;
    float *dis0, *dis1, *dis2, *dis3;
    int *pm0, *pm1, *pm2, *inv0, *inv1, *inv2, *ccnt, *ccol;
    float *cval;
    unsigned char* m0;
    __nv_bfloat16 *bA1, *bX2, *bX3, *G, *Q, *zpk, *Xp, *Wall;
    cudaGetSymbolAddress((void**)&Augp, g_Augp);
    cudaGetSymbolAddress((void**)&h0,  g_h0);
    cudaGetSymbolAddress((void**)&h1,  g_h1);
    cudaGetSymbolAddress((void**)&h2,  g_h2);
    cudaGetSymbolAddress((void**)&h3,  g_h3);
    cudaGetSymbolAddress((void**)&hb,  g_hb);
    cudaGetSymbolAddress((void**)&xw,  g_xw);
    cudaGetSymbolAddress((void**)&t,   g_t);
    cudaGetSymbolAddress((void**)&dis0, g_dis0);
    cudaGetSymbolAddress((void**)&dis1, g_dis1);
    cudaGetSymbolAddress((void**)&dis2, g_dis2);
    cudaGetSymbolAddress((void**)&dis3, g_dis3);
    cudaGetSymbolAddress((void**)&sc,  g_sc);
    cudaGetSymbolAddress((void**)&pm0, g_perm0);
    cudaGetSymbolAddress((void**)&pm1, g_perm1);
    cudaGetSymbolAddress((void**)&pm2, g_perm2);
    cudaGetSymbolAddress((void**)&inv0, g_inv0);
    cudaGetSymbolAddress((void**)&inv1, g_inv1);
    cudaGetSymbolAddress((void**)&inv2, g_inv2);
    cudaGetSymbolAddress((void**)&ccnt, g_ccnt);
    cudaGetSymbolAddress((void**)&ccol, g_ccol);
    cudaGetSymbolAddress((void**)&cval, g_cval);
    cudaGetSymbolAddress((void**)&m0,  g_m0);
    cudaGetSymbolAddress((void**)&bA1, g_bA1);
    cudaGetSymbolAddress((void**)&bX2, g_bX2);
    cudaGetSymbolAddress((void**)&bX3, g_bX3);
    cudaGetSymbolAddress((void**)&G,   g_G);
    cudaGetSymbolAddress((void**)&Q,   g_Q);
    cudaGetSymbolAddress((void**)&zpk, g_zpk);
    cudaGetSymbolAddress((void**)&Xp,  g_Xpk);
    cudaGetSymbolAddress((void**)&Wall, g_Wall);

    // ---- upfront: pack all weights; adjacency mask -> CSR + dis0 ----
    k_packW_all<<<(WTOT + 255) / 256, 256>>>(Wd0, Wd1, Wd2, Wd3, Wu0, Wu1, Wu2, Wall);
    cudaMemsetAsync(m0, 0, (size_t)N0 * N0, 0);
    k_edges_m<<<(E + 255) / 256, 256>>>(ei, E, m0);
    k_csr_m<<<N0, 256>>>(m0, N0, ccnt, ccol, cval, dis0);

    // ---- down level 0 (sparse, exact fp32) ----
    k_spmm<<<N0, INC>>>(ccnt, ccol, cval, x, INC, INC, dis0, nullptr, ACT_NONE, xw);
    k_packX3<<<(N0 * 384 + 255) / 256, 256>>>(xw, N0, INC, Xp);
    run_xw_pre(Xp, N0, 384, Wall + WOFF_D0, HC, bd0, ACT_RELU, h0, 1);

    // pool0: bA1 = crop([(A0+I)^2]) + I via SpGEMM (warp-parallel)
    run_scores_topk(h0, N0, p1, KP1, pm0, inv0, sc);
    k_spgemm<<<2048, 256>>>(ccnt, ccol, cval, pm0, inv0, KP1, 2048, bA1);
    k_pool_pack<<<(2048 * 1536 + 255) / 256, 256>>>(h0, HC, pm0, sc, KP1, 2048, Xp);
    k_dis_b<<<KP1, 256>>>(bA1, 2048, 2048, dis1);
    run_gcn_exact(bA1, KP1, 2048, Xp, 1536, Wall + WOFF_D1, HC, bd1, h1, ACT_RELU, 4, 2,
                  xw, t, dis1, zpk);

    // pool1: A2 submatrix via G@G^T
    run_scores_topk(h1, KP1, p2, KP2, pm1, inv1, sc);
    k_gather_rows<<<(1024 * 2048 + 255) / 256, 256>>>(bA1, 2048, pm1, KP2, 1024, G);
    cudaMemsetAsync(Augp, 0, (size_t)1024 * 1024 * sizeof(float), 0);
    run_nt_tri(1024, 2048, G, 2048, G, 2048, Augp, 1024, 8);
    k_pool_pack<<<(1024 * 1536 + 255) / 256, 256>>>(h1, HC, pm1, sc, KP2, 1024, Xp);
    k_crop_pack_X<<<(1024 * 1024 + 255) / 256, 256>>>(Augp, 1024, KP2, 1024, bX2);
    k_dis_b<<<KP2, 256>>>(bX2, 2048, 2048, dis2);
    run_gcn_split(bX2, KP2, 1024, Xp, 1536, Wall + WOFF_D2, HC, bd2, h2, ACT_RELU, 8, 4,
                  xw, t, dis2, zpk);

    // pool2: A3 = P@P^T + P@Q^T
    run_scores_topk(h2, KP2, p3, KP3, pm2, inv2, sc);
    k_gather_PQ_b<<<(512 * 2048 + 255) / 256, 256>>>(bX2, 1024, pm2, KP3, 512, G, Q);
    cudaMemsetAsync(Augp, 0, (size_t)512 * 512 * sizeof(float), 0);
    run_nt_tri(512, 2048, G, 2048, G, 2048, Augp, 512, 8);
    run_nt_tri(512, 2048, G, 2048, Q, 2048, Augp, 512, 8);
    k_pool_pack<<<(512 * 1536 + 255) / 256, 256>>>(h2, HC, pm2, sc, KP3, 512, Xp);
    k_crop_pack_X<<<(512 * 512 + 255) / 256, 256>>>(Augp, 512, KP3, 512, bX3);
    k_dis_b<<<KP3, 256>>>(bX3, 1024, 1024, dis3);
    run_gcn_split(bX3, KP3, 512, Xp, 1536, Wall + WOFF_D3, HC, bd3, h3, ACT_RELU, 8, 8,
                  xw, t, dis3, zpk);

    // ---- up path (fused unpool + pack) ----
    k_unpool_pack<<<(1024 * 1536 + 255) / 256, 256>>>(h2, h3, inv2, KP2, 1024, HC, Xp);
    run_gcn_split(bX2, KP2, 1024, Xp, 1536, Wall + WOFF_U0, HC, bu0, hb, ACT_RELU, 8, 4,
                  xw, t, dis2, zpk);

    k_unpool_pack<<<(2048 * 1536 + 255) / 256, 256>>>(h1, hb, inv1, KP1, 2048, HC, Xp);
    run_gcn_exact(bA1, KP1, 2048, Xp, 1536, Wall + WOFF_U1, HC, bu1, hb, ACT_RELU, 4, 2,
                  xw, t, dis1, zpk);

    k_unpool_pack<<<(4096 * 1536 + 255) / 256, 256>>>(h0, hb, inv0, N0, 4096, HC, Xp);
    cudaMemsetAsync(xw, 0, (size_t)N0 * 128 * sizeof(float), 0);
    run_nn(N0, 128, 1536, Xp, 1536, Wall + WOFF_U2, 128, xw, 128, 2, 8, nullptr, ACT_NONE);
    k_spmm<<<N0, OC>>>(ccnt, ccol, cval, xw, OC, 128, dis0, bu2, ACT_SIGM, (float*)d_out);
}